// round 9
// baseline (speedup 1.0000x reference)
#include <cuda_runtime.h>
#include <cuda_bf16.h>
#include <cstdint>

#define S_LEN   2048
#define DMODEL  1024
#define NHEADS  16
#define HDIM    64
#define BATCH   4
#define BHCNT   (BATCH * NHEADS)                   // 64
#define MROWS   (BATCH * S_LEN)                    // 8192
#define HS_ELEMS (BATCH * NHEADS * S_LEN * HDIM)   // 8388608
#define AELEMS  (MROWS * DMODEL)                   // 8388608
#define WELEMS  (DMODEL * DMODEL)                  // 1048576

// ---- scratch (all bf16 hi/lo pairs) ----
__device__ __nv_bfloat16 g_Ahi[3][AELEMS];
__device__ __nv_bfloat16 g_Alo[3][AELEMS];
__device__ __nv_bfloat16 g_Whi[4][WELEMS];   // transposed [N][K]
__device__ __nv_bfloat16 g_Wlo[4][WELEMS];
__device__ __nv_bfloat16 g_Qhi[HS_ELEMS], g_Qlo[HS_ELEMS];   // head-split, pre-scaled 1/8
__device__ __nv_bfloat16 g_Khi[HS_ELEMS], g_Klo[HS_ELEMS];
__device__ __nv_bfloat16 g_Vhi[HS_ELEMS], g_Vlo[HS_ELEMS];
__device__ __nv_bfloat16 g_Ohi[AELEMS],  g_Olo[AELEMS];      // row-major [8192][1024]

// ============================================================================
// helpers (baseline PTX only)
// ============================================================================
__device__ __forceinline__ uint32_t smem_u32(const void* p) {
    uint32_t a;
    asm("{ .reg .u64 t; cvta.to.shared.u64 t, %1; cvt.u32.u64 %0, t; }"
        : "=r"(a) : "l"(p));
    return a;
}
__device__ __forceinline__ void cp_async16(uint32_t dst, const void* src) {
    asm volatile("cp.async.cg.shared.global [%0], [%1], 16;"
                 :: "r"(dst), "l"(src));
}
__device__ __forceinline__ void cp_commit() {
    asm volatile("cp.async.commit_group;");
}
template <int N>
__device__ __forceinline__ void cp_wait() {
    asm volatile("cp.async.wait_group %0;" :: "n"(N));
}
__device__ __forceinline__ void ldsm_x4(uint32_t* r, uint32_t addr) {
    asm volatile("ldmatrix.sync.aligned.m8n8.x4.shared.b16 {%0,%1,%2,%3}, [%4];"
                 : "=r"(r[0]), "=r"(r[1]), "=r"(r[2]), "=r"(r[3]) : "r"(addr));
}
__device__ __forceinline__ void ldsm_x4t(uint32_t* r, uint32_t addr) {
    asm volatile("ldmatrix.sync.aligned.m8n8.x4.trans.shared.b16 {%0,%1,%2,%3}, [%4];"
                 : "=r"(r[0]), "=r"(r[1]), "=r"(r[2]), "=r"(r[3]) : "r"(addr));
}
__device__ __forceinline__ void mma16816(float* d, const uint32_t* a,
                                         const uint32_t* b) {
    asm volatile("mma.sync.aligned.m16n8k16.row.col.f32.bf16.bf16.f32 "
                 "{%0,%1,%2,%3}, {%4,%5,%6,%7}, {%8,%9}, {%0,%1,%2,%3};"
                 : "+f"(d[0]), "+f"(d[1]), "+f"(d[2]), "+f"(d[3])
                 : "r"(a[0]), "r"(a[1]), "r"(a[2]), "r"(a[3]),
                   "r"(b[0]), "r"(b[1]));
}
__device__ __forceinline__ void split2(float a, float b,
                                       uint32_t& hi, uint32_t& lo) {
    __nv_bfloat16 ha = __float2bfloat16(a), hb = __float2bfloat16(b);
    __nv_bfloat16 la = __float2bfloat16(a - __bfloat162float(ha));
    __nv_bfloat16 lb = __float2bfloat16(b - __bfloat162float(hb));
    hi = (uint32_t)*(uint16_t*)&ha | ((uint32_t)*(uint16_t*)&hb << 16);
    lo = (uint32_t)*(uint16_t*)&la | ((uint32_t)*(uint16_t*)&lb << 16);
}

// ============================================================================
// GEMM mainloop: tile 128(M)x128(N), BK=32, 8 warps (4Mx2N), split-bf16 3-term.
// 2-stage cp.async pipeline, one __syncthreads per K-chunk. 256 threads.
// AI = 48 MAC/B of L2 traffic (was 32 at 64x128) -> lifts LTS ceiling to HMMA peak.
// ============================================================================
#define ROWB       80
#define MAT_BYTES  (128 * ROWB)              // 10240 per array
#define STG_BYTES  (4 * MAT_BYTES)           // 40960 per stage
#define GSMEM      (2 * STG_BYTES)           // 81920

__device__ __forceinline__ void gemm_core(
    const __nv_bfloat16* __restrict__ Ahi, const __nv_bfloat16* __restrict__ Alo,
    const __nv_bfloat16* __restrict__ Bhi, const __nv_bfloat16* __restrict__ Blo,
    uint32_t sb, int tid, int bc, int br, float acc[2][8][4])
{
    const int lane   = tid & 31;
    const int wid    = tid >> 5;          // 0..7
    const int warp_m = wid >> 1;          // 0..3
    const int warp_n = wid & 1;           // 0..1

    auto issue = [&](int kc, int stage) {
        #pragma unroll
        for (int t = 0; t < 8; t++) {
            const int c   = tid + t * 256;     // 0..2047
            const int mat = c >> 9;            // 0:Ahi 1:Alo 2:Bhi 3:Blo
            const int rem = c & 511;
            const int row = rem >> 2;
            const int seg = rem & 3;
            const long gcol = (long)kc * 32 + seg * 8;
            const __nv_bfloat16* g;
            if (mat == 0)      g = Ahi + (long)(br * 128 + row) * DMODEL + gcol;
            else if (mat == 1) g = Alo + (long)(br * 128 + row) * DMODEL + gcol;
            else if (mat == 2) g = Bhi + (long)(bc * 128 + row) * DMODEL + gcol;
            else               g = Blo + (long)(bc * 128 + row) * DMODEL + gcol;
            cp_async16(sb + stage * STG_BYTES + mat * MAT_BYTES
                       + row * ROWB + seg * 16, g);
        }
        cp_commit();
    };

    issue(0, 0);

    const int NKC = DMODEL / 32;         // 32
    for (int kc = 0; kc < NKC; kc++) {
        cp_wait<0>();                    // stage kc resident
        __syncthreads();                 // visible; other stage free
        if (kc + 1 < NKC) issue(kc + 1, (kc + 1) & 1);

        const uint32_t base = sb + (kc & 1) * STG_BYTES;

        #pragma unroll
        for (int kk = 0; kk < 2; kk++) {
            uint32_t ahi[2][4], alo[2][4];
            {
                const uint32_t arow = warp_m * 32 + (lane & 15);
                const uint32_t acol = kk * 16 + (lane >> 4) * 8;
                const uint32_t off  = arow * ROWB + acol * 2;
                ldsm_x4(ahi[0], base + off);
                ldsm_x4(ahi[1], base + off + 16 * ROWB);
                ldsm_x4(alo[0], base + MAT_BYTES + off);
                ldsm_x4(alo[1], base + MAT_BYTES + off + 16 * ROWB);
            }
            // B loaded per-q to keep live regs under the 128-reg cap
            const uint32_t brow = warp_n * 64 + (lane & 7) + ((lane & 16) >> 1);
            const uint32_t bcol = kk * 16 + ((lane >> 3) & 1) * 8;
            const uint32_t boff = brow * ROWB + bcol * 2;
            #pragma unroll
            for (int q = 0; q < 4; q++) {
                uint32_t bhi[4], blo[4];
                ldsm_x4(bhi, base + 2 * MAT_BYTES + boff + q * 16 * ROWB);
                ldsm_x4(blo, base + 3 * MAT_BYTES + boff + q * 16 * ROWB);
                // term-major within q (acc reuse distance 4)
                #pragma unroll
                for (int mt = 0; mt < 2; mt++)
                    #pragma unroll
                    for (int n2 = 0; n2 < 2; n2++)
                        mma16816(acc[mt][2 * q + n2], ahi[mt], &bhi[n2 * 2]);
                #pragma unroll
                for (int mt = 0; mt < 2; mt++)
                    #pragma unroll
                    for (int n2 = 0; n2 < 2; n2++)
                        mma16816(acc[mt][2 * q + n2], ahi[mt], &blo[n2 * 2]);
                #pragma unroll
                for (int mt = 0; mt < 2; mt++)
                    #pragma unroll
                    for (int n2 = 0; n2 < 2; n2++)
                        mma16816(acc[mt][2 * q + n2], alo[mt], &bhi[n2 * 2]);
            }
        }
    }
}

// ============================================================================
// Batched QKV projection GEMM: grid (8, 64, 3), 256 threads, 2 CTAs/SM.
// ============================================================================
__global__ void __launch_bounds__(256, 2)
gemm_qkv(__nv_bfloat16* __restrict__ Qhi, __nv_bfloat16* __restrict__ Qlo,
         __nv_bfloat16* __restrict__ Khi, __nv_bfloat16* __restrict__ Klo,
         __nv_bfloat16* __restrict__ Vhi, __nv_bfloat16* __restrict__ Vlo)
{
    extern __shared__ char smem[];
    const uint32_t sb = smem_u32(smem);
    const int tid = threadIdx.x;
    const int bc = blockIdx.x, br = blockIdx.y, z = blockIdx.z;

    __nv_bfloat16 *Chi, *Clo;
    float scale;
    if (z == 0)      { Chi = Qhi; Clo = Qlo; scale = 0.125f; }
    else if (z == 1) { Chi = Khi; Clo = Klo; scale = 1.0f; }
    else             { Chi = Vhi; Clo = Vlo; scale = 1.0f; }

    float acc[2][8][4];
    #pragma unroll
    for (int mt = 0; mt < 2; mt++)
        #pragma unroll
        for (int nt = 0; nt < 8; nt++)
            #pragma unroll
            for (int i = 0; i < 4; i++) acc[mt][nt][i] = 0.0f;

    gemm_core(g_Ahi[z], g_Alo[z], g_Whi[z], g_Wlo[z], sb, tid, bc, br, acc);

    const int lane = tid & 31, wid = tid >> 5;
    const int warp_m = wid >> 1, warp_n = wid & 1;
    #pragma unroll
    for (int mt = 0; mt < 2; mt++) {
        #pragma unroll
        for (int nt = 0; nt < 8; nt++) {
            const int row0 = br * 128 + warp_m * 32 + mt * 16 + (lane >> 2);
            const int col  = bc * 128 + warp_n * 64 + nt * 8 + (lane & 3) * 2;
            const int h = col >> 6, dd = col & 63;
            #pragma unroll
            for (int half = 0; half < 2; half++) {
                const int r = row0 + half * 8;
                const int b = r >> 11, s = r & 2047;
                const long off = ((((long)b * NHEADS + h) * S_LEN + s) * HDIM) + dd;
                uint32_t hi, lo;
                split2(acc[mt][nt][half * 2] * scale,
                       acc[mt][nt][half * 2 + 1] * scale, hi, lo);
                *(uint32_t*)(Chi + off) = hi;
                *(uint32_t*)(Clo + off) = lo;
            }
        }
    }
}

// ============================================================================
// Output projection GEMM: fp32 row-major result. grid (8, 64), 256 threads.
// ============================================================================
__global__ void __launch_bounds__(256, 2)
gemm_out(const __nv_bfloat16* __restrict__ Ahi, const __nv_bfloat16* __restrict__ Alo,
         const __nv_bfloat16* __restrict__ Bhi, const __nv_bfloat16* __restrict__ Blo,
         float* __restrict__ Cf)
{
    extern __shared__ char smem[];
    const uint32_t sb = smem_u32(smem);
    const int tid = threadIdx.x;
    const int bc = blockIdx.x, br = blockIdx.y;

    float acc[2][8][4];
    #pragma unroll
    for (int mt = 0; mt < 2; mt++)
        #pragma unroll
        for (int nt = 0; nt < 8; nt++)
            #pragma unroll
            for (int i = 0; i < 4; i++) acc[mt][nt][i] = 0.0f;

    gemm_core(Ahi, Alo, Bhi, Blo, sb, tid, bc, br, acc);

    const int lane = tid & 31, wid = tid >> 5;
    const int warp_m = wid >> 1, warp_n = wid & 1;
    #pragma unroll
    for (int mt = 0; mt < 2; mt++) {
        #pragma unroll
        for (int nt = 0; nt < 8; nt++) {
            const int row0 = br * 128 + warp_m * 32 + mt * 16 + (lane >> 2);
            const int col  = bc * 128 + warp_n * 64 + nt * 8 + (lane & 3) * 2;
            float2 v01; v01.x = acc[mt][nt][0]; v01.y = acc[mt][nt][1];
            float2 v23; v23.x = acc[mt][nt][2]; v23.y = acc[mt][nt][3];
            *(float2*)&Cf[(long)row0 * DMODEL + col] = v01;
            *(float2*)&Cf[(long)(row0 + 8) * DMODEL + col] = v23;
        }
    }
}

// ============================================================================
// Tensor-core causal flash attention (unchanged from R8).
// 128 threads (4 warps x m16 = 64 q-rows). K ring 2-stage + V ring 2-stage;
// Q staged through V-stage-1 then overwritten. 73.7KB -> 3 CTAs/SM.
// ============================================================================
#define AROWB    144
#define ARR      (64 * AROWB)            // 9216   one array (64 rows)
#define KSTG     (2 * ARR)               // 18432  one K stage (hi+lo)
#define VOFF     (2 * KSTG)              // 36864  V ring base
#define ASMEM    (VOFF + 2 * KSTG)       // 73728

__global__ void __launch_bounds__(128, 3)
attn_mma(const __nv_bfloat16* __restrict__ Qhi, const __nv_bfloat16* __restrict__ Qlo,
         const __nv_bfloat16* __restrict__ Khi, const __nv_bfloat16* __restrict__ Klo,
         const __nv_bfloat16* __restrict__ Vhi, const __nv_bfloat16* __restrict__ Vlo,
         __nv_bfloat16* __restrict__ Ohi, __nv_bfloat16* __restrict__ Olo)
{
    extern __shared__ char smem[];
    const uint32_t sb = smem_u32(smem);
    const int tid = threadIdx.x, wid = tid >> 5, lane = tid & 31;
    const int qblk = (int)gridDim.x - 1 - (int)blockIdx.x;   // longest first
    const int q0 = qblk * 64;
    const int bh = blockIdx.y;
    const long base = (long)bh * S_LEN * HDIM;
    const int ntiles = qblk + 1;

    auto ld2arr = [&](const __nv_bfloat16* hi, const __nv_bfloat16* lo,
                      long grow0, uint32_t smem_base) {
        #pragma unroll
        for (int t = 0; t < 8; t++) {
            const int c = tid + t * 128;            // 0..1023
            const int arr = c >> 9, rem = c & 511;
            const int row = rem >> 3, seg = rem & 7;
            const __nv_bfloat16* src = (arr ? lo : hi)
                                     + base + (grow0 + row) * HDIM + seg * 8;
            cp_async16(smem_base + arr * ARR + row * AROWB + seg * 16, src);
        }
        cp_commit();
    };

    // ---- prologue ----
    ld2arr(Qhi, Qlo, (long)q0, sb + VOFF + KSTG);           // GQ -> V stage 1
    ld2arr(Khi, Klo, 0L, sb);                               // K(0) -> K stage 0
    cp_wait<1>();                                           // GQ done
    __syncthreads();

    uint32_t qhF[4][4], qlF[4][4];
    {
        const uint32_t arow = wid * 16 + (lane & 15);
        #pragma unroll
        for (int kt = 0; kt < 4; kt++) {
            const uint32_t off = arow * AROWB + (kt * 16 + (lane >> 4) * 8) * 2;
            ldsm_x4(qhF[kt], sb + VOFF + KSTG + off);
            ldsm_x4(qlF[kt], sb + VOFF + KSTG + ARR + off);
        }
    }
    __syncthreads();                                        // Q reads done
    ld2arr(Vhi, Vlo, 0L, sb + VOFF);                        // GV_{-1}: V(0)
    {
        const int tk = (1 < ntiles) ? 1 : 0;
        ld2arr(Khi, Klo, (long)tk * 64, sb + KSTG);         // GK_{-1}: K(1)
    }

    float m_s[2] = {-1e30f, -1e30f};
    float l_s[2] = {0.0f, 0.0f};
    float acc_o[8][4];
    #pragma unroll
    for (int nt = 0; nt < 8; nt++)
        #pragma unroll
        for (int i = 0; i < 4; i++) acc_o[nt][i] = 0.0f;

    const int wrow_lo = q0 + wid * 16;

    for (int t = 0; t < ntiles; t++) {
        cp_wait<2>();                 // K(t) resident
        __syncthreads();              // sync1: K(t) visible; V stage (t+1)&1 free
        {
            const int tv = (t + 1 < ntiles) ? t + 1 : ntiles - 1;
            ld2arr(Vhi, Vlo, (long)tv * 64, sb + VOFF + ((t + 1) & 1) * KSTG);
        }

        const uint32_t kbase = sb + (t & 1) * KSTG;
        const uint32_t vbase = sb + VOFF + (t & 1) * KSTG;
        const bool act = (t * 64 <= wrow_lo + 15);

        float acc_s[8][4];
        float tmax[2] = {-1e30f, -1e30f};
        bool act2 = false;

        if (act) {
            #pragma unroll
            for (int nt = 0; nt < 8; nt++)
                #pragma unroll
                for (int i = 0; i < 4; i++) acc_s[nt][i] = 0.0f;

            #pragma unroll
            for (int kt = 0; kt < 4; kt++) {
                uint32_t kh[4][4], kl[4][4];
                const uint32_t brow = (lane & 7) + ((lane & 16) >> 1);
                const uint32_t bcol = kt * 16 + ((lane >> 3) & 1) * 8;
                #pragma unroll
                for (int g = 0; g < 4; g++) {
                    const uint32_t off = (g * 16 + brow) * AROWB + bcol * 2;
                    ldsm_x4(kh[g], kbase + off);
                    ldsm_x4(kl[g], kbase + ARR + off);
                }
                #pragma unroll
                for (int nt = 0; nt < 8; nt++)
                    mma16816(acc_s[nt], qhF[kt], &kh[nt >> 1][(nt & 1) * 2]);
                #pragma unroll
                for (int nt = 0; nt < 8; nt++)
                    mma16816(acc_s[nt], qhF[kt], &kl[nt >> 1][(nt & 1) * 2]);
                #pragma unroll
                for (int nt = 0; nt < 8; nt++)
                    mma16816(acc_s[nt], qlF[kt], &kh[nt >> 1][(nt & 1) * 2]);
            }

            const int r0 = q0 + wid * 16 + (lane >> 2);
            if (t * 64 + 63 > wrow_lo) {
                #pragma unroll
                for (int nt = 0; nt < 8; nt++)
                    #pragma unroll
                    for (int i = 0; i < 4; i++) {
                        const int row = r0 + (i >> 1) * 8;
                        const int col = t * 64 + nt * 8 + 2 * (lane & 3) + (i & 1);
                        if (col > row) acc_s[nt][i] = -1e30f;
                    }
            }

            #pragma unroll
            for (int nt = 0; nt < 8; nt++)
                #pragma unroll
                for (int i = 0; i < 4; i++)
                    tmax[i >> 1] = fmaxf(tmax[i >> 1], acc_s[nt][i]);
            #pragma unroll
            for (int h = 0; h < 2; h++) {
                tmax[h] = fmaxf(tmax[h], __shfl_xor_sync(0xffffffffu, tmax[h], 1));
                tmax[h] = fmaxf(tmax[h], __shfl_xor_sync(0xffffffffu, tmax[h], 2));
            }
            float d = fmaxf(tmax[0] - m_s[0], tmax[1] - m_s[1]);
            d = fmaxf(d, __shfl_xor_sync(0xffffffffu, d, 4));
            d = fmaxf(d, __shfl_xor_sync(0xffffffffu, d, 8));
            d = fmaxf(d, __shfl_xor_sync(0xffffffffu, d, 16));
            act2 = (d >= -44.0f);
        }

        cp_wait<2>();                 // V(t) resident
        __syncthreads();              // sync2: V(t) visible; K stage t&1 reads done
        {
            const int tk = (t + 2 < ntiles) ? t + 2 : ntiles - 1;
            ld2arr(Khi, Klo, (long)tk * 64, sb + (t & 1) * KSTG);
        }

        if (act && act2) {
            float nm[2], corr[2];
            #pragma unroll
            for (int h = 0; h < 2; h++) {
                nm[h]   = fmaxf(m_s[h], tmax[h]);
                corr[h] = __expf(m_s[h] - nm[h]);
                m_s[h]  = nm[h];
            }
            float psum[2] = {0.0f, 0.0f};
            #pragma unroll
            for (int nt = 0; nt < 8; nt++)
                #pragma unroll
                for (int i = 0; i < 4; i++) {
                    const float p = __expf(acc_s[nt][i] - nm[i >> 1]);
                    acc_s[nt][i] = p;
                    psum[i >> 1] += p;
                }
            #pragma unroll
            for (int h = 0; h < 2; h++) {
                psum[h] += __shfl_xor_sync(0xffffffffu, psum[h], 1);
                psum[h] += __shfl_xor_sync(0xffffffffu, psum[h], 2);
                l_s[h] = l_s[h] * corr[h] + psum[h];
            }
            #pragma unroll
            for (int nt = 0; nt < 8; nt++)
                #pragma unroll
                for (int i = 0; i < 4; i++) acc_o[nt][i] *= corr[i >> 1];

            uint32_t ph[4][4], pl[4][4];
            #pragma unroll
            for (int kt = 0; kt < 4; kt++) {
                split2(acc_s[2 * kt][0],     acc_s[2 * kt][1],     ph[kt][0], pl[kt][0]);
                split2(acc_s[2 * kt][2],     acc_s[2 * kt][3],     ph[kt][1], pl[kt][1]);
                split2(acc_s[2 * kt + 1][0], acc_s[2 * kt + 1][1], ph[kt][2], pl[kt][2]);
                split2(acc_s[2 * kt + 1][2], acc_s[2 * kt + 1][3], ph[kt][3], pl[kt][3]);
            }

            #pragma unroll
            for (int kt = 0; kt < 4; kt++) {
                uint32_t vh[4][4], vl[4][4];
                const uint32_t vrow = kt * 16 + (lane & 15);
                const uint32_t vcol = (lane >> 4) * 8;
                #pragma unroll
                for (int g = 0; g < 4; g++) {
                    const uint32_t off = vrow * AROWB + (g * 16 + vcol) * 2;
                    ldsm_x4t(vh[g], vbase + off);
                    ldsm_x4t(vl[g], vbase + ARR + off);
                }
                #pragma unroll
                for (int nt = 0; nt < 8; nt++)
                    mma16816(acc_o[nt], ph[kt], &vh[nt >> 1][(nt & 1) * 2]);
                #pragma unroll
                for (int nt = 0; nt < 8; nt++)
                    mma16816(acc_o[nt], pl[kt], &vh[nt >> 1][(nt & 1) * 2]);
                #pragma unroll
                for (int nt = 0; nt < 8; nt++)
                    mma16816(acc_o[nt], ph[kt], &vl[nt >> 1][(nt & 1) * 2]);
            }
        }
    }

    // ---- epilogue ----
    const float inv0 = 1.0f / l_s[0];
    const float inv1 = 1.0f / l_s[1];
    const int b  = bh >> 4;
    const int hh = bh & 15;
    const int r0 = q0 + wid * 16 + (lane >> 2);
    #pragma unroll
    for (int nt = 0; nt < 8; nt++) {
        const int col = hh * 64 + nt * 8 + 2 * (lane & 3);
        {
            const long idx = ((long)(b * S_LEN + r0)) * DMODEL + col;
            uint32_t hi, lo;
            split2(acc_o[nt][0] * inv0, acc_o[nt][1] * inv0, hi, lo);
            *(uint32_t*)(Ohi + idx) = hi;
            *(uint32_t*)(Olo + idx) = lo;
        }
        {
            const long idx = ((long)(b * S_LEN + r0 + 8)) * DMODEL + col;
            uint32_t hi, lo;
            split2(acc_o[nt][2] * inv1, acc_o[nt][3] * inv1, hi, lo);
            *(uint32_t*)(Ohi + idx) = hi;
            *(uint32_t*)(Olo + idx) = lo;
        }
    }
}

// ============================================================================
// conversion kernels (fused)
// ============================================================================
__global__ void __launch_bounds__(256)
conv_qkv(const float* __restrict__ q, const float* __restrict__ k,
         const float* __restrict__ v)
{
    const int z = blockIdx.y;
    const float* X = (z == 0) ? q : (z == 1) ? k : v;
    const int i = blockIdx.x * 256 + threadIdx.x;   // over float2
    const float2 x = ((const float2*)X)[i];
    uint32_t h, l;
    split2(x.x, x.y, h, l);
    ((uint32_t*)g_Ahi[z])[i] = h;
    ((uint32_t*)g_Alo[z])[i] = l;
}

__global__ void __launch_bounds__(256)
conv_w(const float* __restrict__ W0, const float* __restrict__ W1,
       const float* __restrict__ W2, const float* __restrict__ W3)
{
    __shared__ float t[32][33];
    const int z = blockIdx.z;
    const float* W = (z == 0) ? W0 : (z == 1) ? W1 : (z == 2) ? W2 : W3;
    const int tx = threadIdx.x, ty = threadIdx.y;     // (32, 8)
    const int n0 = blockIdx.x * 32, k0 = blockIdx.y * 32;
    #pragma unroll
    for (int r = 0; r < 4; r++) {
        const int k = ty + r * 8;
        t[k][tx] = W[(long)(k0 + k) * DMODEL + n0 + tx];
    }
    __syncthreads();
    #pragma unroll
    for (int r = 0; r < 4; r++) {
        const int nl = ty + r * 8;
        const float x = t[tx][nl];
        const __nv_bfloat16 h = __float2bfloat16(x);
        const long o = (long)(n0 + nl) * DMODEL + k0 + tx;
        g_Whi[z][o] = h;
        g_Wlo[z][o] = __float2bfloat16(x - __bfloat162float(h));
    }
}

// ============================================================================
extern "C" void kernel_launch(void* const* d_in, const int* in_sizes, int n_in,
                              void* d_out, int out_size)
{
    const float* q = (const float*)d_in[0];
    const float* k = (const float*)d_in[1];
    const float* v = (const float*)d_in[2];
    float* out = (float*)d_out;

    __nv_bfloat16 *whi, *wlo;
    __nv_bfloat16 *qhi, *qlo, *khi, *klo, *vhi, *vlo, *ohi, *olo;
    cudaGetSymbolAddress((void**)&whi, g_Whi);
    cudaGetSymbolAddress((void**)&wlo, g_Wlo);
    cudaGetSymbolAddress((void**)&qhi, g_Qhi);
    cudaGetSymbolAddress((void**)&qlo, g_Qlo);
    cudaGetSymbolAddress((void**)&khi, g_Khi);
    cudaGetSymbolAddress((void**)&klo, g_Klo);
    cudaGetSymbolAddress((void**)&vhi, g_Vhi);
    cudaGetSymbolAddress((void**)&vlo, g_Vlo);
    cudaGetSymbolAddress((void**)&ohi, g_Ohi);
    cudaGetSymbolAddress((void**)&olo, g_Olo);

    cudaFuncSetAttribute((const void*)gemm_qkv,
                         cudaFuncAttributeMaxDynamicSharedMemorySize, GSMEM);
    cudaFuncSetAttribute((const void*)gemm_out,
                         cudaFuncAttributeMaxDynamicSharedMemorySize, GSMEM);
    cudaFuncSetAttribute((const void*)attn_mma,
                         cudaFuncAttributeMaxDynamicSharedMemorySize, ASMEM);

    conv_w<<<dim3(32, 32, 4), dim3(32, 8)>>>(
        (const float*)d_in[3], (const float*)d_in[4],
        (const float*)d_in[5], (const float*)d_in[6]);

    conv_qkv<<<dim3(AELEMS / 2 / 256, 3), 256>>>(q, k, v);

    gemm_qkv<<<dim3(8, 64, 3), 256, GSMEM>>>(qhi, qlo, khi, klo, vhi, vlo);

    attn_mma<<<dim3(S_LEN / 64, BHCNT), 128, ASMEM>>>(qhi, qlo, khi, klo,
                                                      vhi, vlo, ohi, olo);

    gemm_out<<<dim3(8, 64), 256, GSMEM>>>(ohi, olo,
        whi + 3 * (long)WELEMS, wlo + 3 * (long)WELEMS, out);
}

// round 10
// speedup vs baseline: 1.1249x; 1.1249x over previous
#include <cuda_runtime.h>
#include <cuda_bf16.h>
#include <cstdint>

#define S_LEN   2048
#define DMODEL  1024
#define NHEADS  16
#define HDIM    64
#define BATCH   4
#define BHCNT   (BATCH * NHEADS)                   // 64
#define MROWS   (BATCH * S_LEN)                    // 8192
#define HS_ELEMS (BATCH * NHEADS * S_LEN * HDIM)   // 8388608
#define AELEMS  (MROWS * DMODEL)                   // 8388608
#define WELEMS  (DMODEL * DMODEL)                  // 1048576

// ---- scratch (all bf16 hi/lo pairs) ----
__device__ __nv_bfloat16 g_Ahi[3][AELEMS];
__device__ __nv_bfloat16 g_Alo[3][AELEMS];
__device__ __nv_bfloat16 g_Whi[4][WELEMS];   // transposed [N][K]
__device__ __nv_bfloat16 g_Wlo[4][WELEMS];
__device__ __nv_bfloat16 g_Qhi[HS_ELEMS], g_Qlo[HS_ELEMS];   // head-split, pre-scaled 1/8
__device__ __nv_bfloat16 g_Khi[HS_ELEMS], g_Klo[HS_ELEMS];
__device__ __nv_bfloat16 g_Vhi[HS_ELEMS], g_Vlo[HS_ELEMS];
__device__ __nv_bfloat16 g_Ohi[AELEMS],  g_Olo[AELEMS];      // row-major [8192][1024]

// ============================================================================
// helpers (baseline PTX only)
// ============================================================================
__device__ __forceinline__ uint32_t smem_u32(const void* p) {
    uint32_t a;
    asm("{ .reg .u64 t; cvta.to.shared.u64 t, %1; cvt.u32.u64 %0, t; }"
        : "=r"(a) : "l"(p));
    return a;
}
__device__ __forceinline__ void cp_async16(uint32_t dst, const void* src) {
    asm volatile("cp.async.cg.shared.global [%0], [%1], 16;"
                 :: "r"(dst), "l"(src));
}
__device__ __forceinline__ void cp_commit() {
    asm volatile("cp.async.commit_group;");
}
template <int N>
__device__ __forceinline__ void cp_wait() {
    asm volatile("cp.async.wait_group %0;" :: "n"(N));
}
__device__ __forceinline__ void ldsm_x4(uint32_t* r, uint32_t addr) {
    asm volatile("ldmatrix.sync.aligned.m8n8.x4.shared.b16 {%0,%1,%2,%3}, [%4];"
                 : "=r"(r[0]), "=r"(r[1]), "=r"(r[2]), "=r"(r[3]) : "r"(addr));
}
__device__ __forceinline__ void ldsm_x4t(uint32_t* r, uint32_t addr) {
    asm volatile("ldmatrix.sync.aligned.m8n8.x4.trans.shared.b16 {%0,%1,%2,%3}, [%4];"
                 : "=r"(r[0]), "=r"(r[1]), "=r"(r[2]), "=r"(r[3]) : "r"(addr));
}
__device__ __forceinline__ void mma16816(float* d, const uint32_t* a,
                                         const uint32_t* b) {
    asm volatile("mma.sync.aligned.m16n8k16.row.col.f32.bf16.bf16.f32 "
                 "{%0,%1,%2,%3}, {%4,%5,%6,%7}, {%8,%9}, {%0,%1,%2,%3};"
                 : "+f"(d[0]), "+f"(d[1]), "+f"(d[2]), "+f"(d[3])
                 : "r"(a[0]), "r"(a[1]), "r"(a[2]), "r"(a[3]),
                   "r"(b[0]), "r"(b[1]));
}
// packed split: hi = bf16x2(a,b) (a in low half), lo = bf16x2 of residuals
__device__ __forceinline__ void split2(float a, float b,
                                       uint32_t& hi, uint32_t& lo) {
    uint32_t h;
    asm("cvt.rn.bf16x2.f32 %0, %1, %2;" : "=r"(h) : "f"(b), "f"(a));
    const float fa = __uint_as_float(h << 16);
    const float fb = __uint_as_float(h & 0xFFFF0000u);
    const float la = a - fa, lb = b - fb;
    uint32_t l;
    asm("cvt.rn.bf16x2.f32 %0, %1, %2;" : "=r"(l) : "f"(lb), "f"(la));
    hi = h; lo = l;
}

// ============================================================================
// GEMM mainloop: tile 64(M)x128(N), BK=32, 4 warps (2Mx2N), split-bf16 3-term.
// 2-stage cp.async pipeline, one __syncthreads per K-chunk. 128 threads.
// SMEM: unpadded 64B rows with XOR swizzle (seg ^ (row&3)) -> 48KB/CTA
//       -> 4 CTAs/SM (16 warps).
// ============================================================================
#define GA_BYTES   (64 * 64)                 // 4096  (one A array)
#define GB_BYTES   (128 * 64)                // 8192  (one B array)
#define STG_BYTES  (2 * GA_BYTES + 2 * GB_BYTES)  // 24576
#define GSMEM      (2 * STG_BYTES)           // 49152

__device__ __forceinline__ uint32_t swz64(uint32_t row, uint32_t seg) {
    return row * 64 + ((seg ^ (row & 3)) * 16);
}

__device__ __forceinline__ void gemm_core(
    const __nv_bfloat16* __restrict__ Ahi, const __nv_bfloat16* __restrict__ Alo,
    const __nv_bfloat16* __restrict__ Bhi, const __nv_bfloat16* __restrict__ Blo,
    uint32_t sb, int tid, int bc, int br, float acc[2][8][4])
{
    const int lane   = tid & 31;
    const int wid    = tid >> 5;          // 0..3
    const int warp_m = wid >> 1;
    const int warp_n = wid & 1;

    auto issue = [&](int kc, int stage) {
        #pragma unroll
        for (int t = 0; t < 12; t++) {
            const int c = tid + t * 128;   // 0..1535
            uint32_t dst;
            const __nv_bfloat16* g;
            if (c < 512) {
                const int arr = c >> 8, rem = c & 255;
                const int row = rem >> 2, seg = rem & 3;
                g = (arr ? Alo : Ahi) + (long)(br * 64 + row) * DMODEL
                  + kc * 32 + seg * 8;
                dst = sb + stage * STG_BYTES + arr * GA_BYTES + swz64(row, seg);
            } else {
                const int cb = c - 512;
                const int arr = cb >> 9, rem = cb & 511;
                const int row = rem >> 2, seg = rem & 3;
                g = (arr ? Blo : Bhi) + (long)(bc * 128 + row) * DMODEL
                  + kc * 32 + seg * 8;
                dst = sb + stage * STG_BYTES + 2 * GA_BYTES + arr * GB_BYTES
                    + swz64(row, seg);
            }
            cp_async16(dst, g);
        }
        cp_commit();
    };

    issue(0, 0);

    const int NKC = DMODEL / 32;         // 32
    for (int kc = 0; kc < NKC; kc++) {
        cp_wait<0>();                    // stage kc resident
        __syncthreads();                 // visible; other stage free
        if (kc + 1 < NKC) issue(kc + 1, (kc + 1) & 1);

        const uint32_t base = sb + (kc & 1) * STG_BYTES;

        #pragma unroll
        for (int kk = 0; kk < 2; kk++) {
            uint32_t ahi[2][4], alo[2][4];
            {
                const uint32_t ar0  = warp_m * 32 + (lane & 15);
                const uint32_t aseg = kk * 2 + (lane >> 4);
                ldsm_x4(ahi[0], base + swz64(ar0, aseg));
                ldsm_x4(ahi[1], base + swz64(ar0 + 16, aseg));
                ldsm_x4(alo[0], base + GA_BYTES + swz64(ar0, aseg));
                ldsm_x4(alo[1], base + GA_BYTES + swz64(ar0 + 16, aseg));
            }
            const uint32_t br0  = warp_n * 64 + (lane & 7) + ((lane & 16) >> 1);
            const uint32_t bseg = kk * 2 + ((lane >> 3) & 1);
            #pragma unroll
            for (int q = 0; q < 4; q++) {
                uint32_t bhi[4], blo[4];
                const uint32_t brow = br0 + q * 16;
                ldsm_x4(bhi, base + 2 * GA_BYTES + swz64(brow, bseg));
                ldsm_x4(blo, base + 2 * GA_BYTES + GB_BYTES + swz64(brow, bseg));
                #pragma unroll
                for (int mt = 0; mt < 2; mt++)
                    #pragma unroll
                    for (int n2 = 0; n2 < 2; n2++)
                        mma16816(acc[mt][2 * q + n2], ahi[mt], &bhi[n2 * 2]);
                #pragma unroll
                for (int mt = 0; mt < 2; mt++)
                    #pragma unroll
                    for (int n2 = 0; n2 < 2; n2++)
                        mma16816(acc[mt][2 * q + n2], ahi[mt], &blo[n2 * 2]);
                #pragma unroll
                for (int mt = 0; mt < 2; mt++)
                    #pragma unroll
                    for (int n2 = 0; n2 < 2; n2++)
                        mma16816(acc[mt][2 * q + n2], alo[mt], &bhi[n2 * 2]);
            }
        }
    }
}

// ============================================================================
// Batched QKV projection GEMM: grid (8, 128, 3), 128 threads, 4 CTAs/SM.
// ============================================================================
__global__ void __launch_bounds__(128, 4)
gemm_qkv(__nv_bfloat16* __restrict__ Qhi, __nv_bfloat16* __restrict__ Qlo,
         __nv_bfloat16* __restrict__ Khi, __nv_bfloat16* __restrict__ Klo,
         __nv_bfloat16* __restrict__ Vhi, __nv_bfloat16* __restrict__ Vlo)
{
    extern __shared__ char smem[];
    const uint32_t sb = smem_u32(smem);
    const int tid = threadIdx.x;
    const int bc = blockIdx.x, br = blockIdx.y, z = blockIdx.z;

    __nv_bfloat16 *Chi, *Clo;
    float scale;
    if (z == 0)      { Chi = Qhi; Clo = Qlo; scale = 0.125f; }
    else if (z == 1) { Chi = Khi; Clo = Klo; scale = 1.0f; }
    else             { Chi = Vhi; Clo = Vlo; scale = 1.0f; }

    float acc[2][8][4];
    #pragma unroll
    for (int mt = 0; mt < 2; mt++)
        #pragma unroll
        for (int nt = 0; nt < 8; nt++)
            #pragma unroll
            for (int i = 0; i < 4; i++) acc[mt][nt][i] = 0.0f;

    gemm_core(g_Ahi[z], g_Alo[z], g_Whi[z], g_Wlo[z], sb, tid, bc, br, acc);

    const int lane = tid & 31, wid = tid >> 5;
    const int warp_m = wid >> 1, warp_n = wid & 1;
    #pragma unroll
    for (int mt = 0; mt < 2; mt++) {
        #pragma unroll
        for (int nt = 0; nt < 8; nt++) {
            const int row0 = br * 64 + warp_m * 32 + mt * 16 + (lane >> 2);
            const int col  = bc * 128 + warp_n * 64 + nt * 8 + (lane & 3) * 2;
            const int h = col >> 6, dd = col & 63;
            #pragma unroll
            for (int half = 0; half < 2; half++) {
                const int r = row0 + half * 8;
                const int b = r >> 11, s = r & 2047;
                const long off = ((((long)b * NHEADS + h) * S_LEN + s) * HDIM) + dd;
                uint32_t hi, lo;
                split2(acc[mt][nt][half * 2] * scale,
                       acc[mt][nt][half * 2 + 1] * scale, hi, lo);
                *(uint32_t*)(Chi + off) = hi;
                *(uint32_t*)(Clo + off) = lo;
            }
        }
    }
}

// ============================================================================
// Output projection GEMM: fp32 row-major result. grid (8, 128), 128 threads.
// ============================================================================
__global__ void __launch_bounds__(128, 4)
gemm_out(const __nv_bfloat16* __restrict__ Ahi, const __nv_bfloat16* __restrict__ Alo,
         const __nv_bfloat16* __restrict__ Bhi, const __nv_bfloat16* __restrict__ Blo,
         float* __restrict__ Cf)
{
    extern __shared__ char smem[];
    const uint32_t sb = smem_u32(smem);
    const int tid = threadIdx.x;
    const int bc = blockIdx.x, br = blockIdx.y;

    float acc[2][8][4];
    #pragma unroll
    for (int mt = 0; mt < 2; mt++)
        #pragma unroll
        for (int nt = 0; nt < 8; nt++)
            #pragma unroll
            for (int i = 0; i < 4; i++) acc[mt][nt][i] = 0.0f;

    gemm_core(Ahi, Alo, Bhi, Blo, sb, tid, bc, br, acc);

    const int lane = tid & 31, wid = tid >> 5;
    const int warp_m = wid >> 1, warp_n = wid & 1;
    #pragma unroll
    for (int mt = 0; mt < 2; mt++) {
        #pragma unroll
        for (int nt = 0; nt < 8; nt++) {
            const int row0 = br * 64 + warp_m * 32 + mt * 16 + (lane >> 2);
            const int col  = bc * 128 + warp_n * 64 + nt * 8 + (lane & 3) * 2;
            float2 v01; v01.x = acc[mt][nt][0]; v01.y = acc[mt][nt][1];
            float2 v23; v23.x = acc[mt][nt][2]; v23.y = acc[mt][nt][3];
            *(float2*)&Cf[(long)row0 * DMODEL + col] = v01;
            *(float2*)&Cf[(long)(row0 + 8) * DMODEL + col] = v23;
        }
    }
}

// ============================================================================
// Tensor-core causal flash attention (R8 structure, unchanged).
// 128 threads (4 warps x m16 = 64 q-rows). K ring 2-stage + V ring 2-stage;
// Q staged through V-stage-1 then overwritten. 73.7KB -> 3 CTAs/SM.
// ============================================================================
#define AROWB    144
#define ARR      (64 * AROWB)            // 9216   one array (64 rows)
#define KSTG     (2 * ARR)               // 18432  one K stage (hi+lo)
#define VOFF     (2 * KSTG)              // 36864  V ring base
#define ASMEM    (VOFF + 2 * KSTG)       // 73728

__global__ void __launch_bounds__(128, 3)
attn_mma(const __nv_bfloat16* __restrict__ Qhi, const __nv_bfloat16* __restrict__ Qlo,
         const __nv_bfloat16* __restrict__ Khi, const __nv_bfloat16* __restrict__ Klo,
         const __nv_bfloat16* __restrict__ Vhi, const __nv_bfloat16* __restrict__ Vlo,
         __nv_bfloat16* __restrict__ Ohi, __nv_bfloat16* __restrict__ Olo)
{
    extern __shared__ char smem[];
    const uint32_t sb = smem_u32(smem);
    const int tid = threadIdx.x, wid = tid >> 5, lane = tid & 31;
    const int qblk = (int)gridDim.x - 1 - (int)blockIdx.x;   // longest first
    const int q0 = qblk * 64;
    const int bh = blockIdx.y;
    const long base = (long)bh * S_LEN * HDIM;
    const int ntiles = qblk + 1;

    auto ld2arr = [&](const __nv_bfloat16* hi, const __nv_bfloat16* lo,
                      long grow0, uint32_t smem_base) {
        #pragma unroll
        for (int t = 0; t < 8; t++) {
            const int c = tid + t * 128;            // 0..1023
            const int arr = c >> 9, rem = c & 511;
            const int row = rem >> 3, seg = rem & 7;
            const __nv_bfloat16* src = (arr ? lo : hi)
                                     + base + (grow0 + row) * HDIM + seg * 8;
            cp_async16(smem_base + arr * ARR + row * AROWB + seg * 16, src);
        }
        cp_commit();
    };

    // ---- prologue ----
    ld2arr(Qhi, Qlo, (long)q0, sb + VOFF + KSTG);           // GQ -> V stage 1
    ld2arr(Khi, Klo, 0L, sb);                               // K(0) -> K stage 0
    cp_wait<1>();                                           // GQ done
    __syncthreads();

    uint32_t qhF[4][4], qlF[4][4];
    {
        const uint32_t arow = wid * 16 + (lane & 15);
        #pragma unroll
        for (int kt = 0; kt < 4; kt++) {
            const uint32_t off = arow * AROWB + (kt * 16 + (lane >> 4) * 8) * 2;
            ldsm_x4(qhF[kt], sb + VOFF + KSTG + off);
            ldsm_x4(qlF[kt], sb + VOFF + KSTG + ARR + off);
        }
    }
    __syncthreads();                                        // Q reads done
    ld2arr(Vhi, Vlo, 0L, sb + VOFF);                        // GV_{-1}: V(0)
    {
        const int tk = (1 < ntiles) ? 1 : 0;
        ld2arr(Khi, Klo, (long)tk * 64, sb + KSTG);         // GK_{-1}: K(1)
    }

    float m_s[2] = {-1e30f, -1e30f};
    float l_s[2] = {0.0f, 0.0f};
    float acc_o[8][4];
    #pragma unroll
    for (int nt = 0; nt < 8; nt++)
        #pragma unroll
        for (int i = 0; i < 4; i++) acc_o[nt][i] = 0.0f;

    const int wrow_lo = q0 + wid * 16;

    for (int t = 0; t < ntiles; t++) {
        cp_wait<2>();                 // K(t) resident
        __syncthreads();              // sync1: K(t) visible; V stage (t+1)&1 free
        {
            const int tv = (t + 1 < ntiles) ? t + 1 : ntiles - 1;
            ld2arr(Vhi, Vlo, (long)tv * 64, sb + VOFF + ((t + 1) & 1) * KSTG);
        }

        const uint32_t kbase = sb + (t & 1) * KSTG;
        const uint32_t vbase = sb + VOFF + (t & 1) * KSTG;
        const bool act = (t * 64 <= wrow_lo + 15);

        float acc_s[8][4];
        float tmax[2] = {-1e30f, -1e30f};
        bool act2 = false;

        if (act) {
            #pragma unroll
            for (int nt = 0; nt < 8; nt++)
                #pragma unroll
                for (int i = 0; i < 4; i++) acc_s[nt][i] = 0.0f;

            #pragma unroll
            for (int kt = 0; kt < 4; kt++) {
                uint32_t kh[4][4], kl[4][4];
                const uint32_t brow = (lane & 7) + ((lane & 16) >> 1);
                const uint32_t bcol = kt * 16 + ((lane >> 3) & 1) * 8;
                #pragma unroll
                for (int g = 0; g < 4; g++) {
                    const uint32_t off = (g * 16 + brow) * AROWB + bcol * 2;
                    ldsm_x4(kh[g], kbase + off);
                    ldsm_x4(kl[g], kbase + ARR + off);
                }
                #pragma unroll
                for (int nt = 0; nt < 8; nt++)
                    mma16816(acc_s[nt], qhF[kt], &kh[nt >> 1][(nt & 1) * 2]);
                #pragma unroll
                for (int nt = 0; nt < 8; nt++)
                    mma16816(acc_s[nt], qhF[kt], &kl[nt >> 1][(nt & 1) * 2]);
                #pragma unroll
                for (int nt = 0; nt < 8; nt++)
                    mma16816(acc_s[nt], qlF[kt], &kh[nt >> 1][(nt & 1) * 2]);
            }

            const int r0 = q0 + wid * 16 + (lane >> 2);
            if (t * 64 + 63 > wrow_lo) {
                #pragma unroll
                for (int nt = 0; nt < 8; nt++)
                    #pragma unroll
                    for (int i = 0; i < 4; i++) {
                        const int row = r0 + (i >> 1) * 8;
                        const int col = t * 64 + nt * 8 + 2 * (lane & 3) + (i & 1);
                        if (col > row) acc_s[nt][i] = -1e30f;
                    }
            }

            #pragma unroll
            for (int nt = 0; nt < 8; nt++)
                #pragma unroll
                for (int i = 0; i < 4; i++)
                    tmax[i >> 1] = fmaxf(tmax[i >> 1], acc_s[nt][i]);
            #pragma unroll
            for (int h = 0; h < 2; h++) {
                tmax[h] = fmaxf(tmax[h], __shfl_xor_sync(0xffffffffu, tmax[h], 1));
                tmax[h] = fmaxf(tmax[h], __shfl_xor_sync(0xffffffffu, tmax[h], 2));
            }
            float d = fmaxf(tmax[0] - m_s[0], tmax[1] - m_s[1]);
            d = fmaxf(d, __shfl_xor_sync(0xffffffffu, d, 4));
            d = fmaxf(d, __shfl_xor_sync(0xffffffffu, d, 8));
            d = fmaxf(d, __shfl_xor_sync(0xffffffffu, d, 16));
            act2 = (d >= -44.0f);
        }

        cp_wait<2>();                 // V(t) resident
        __syncthreads();              // sync2: V(t) visible; K stage t&1 reads done
        {
            const int tk = (t + 2 < ntiles) ? t + 2 : ntiles - 1;
            ld2arr(Khi, Klo, (long)tk * 64, sb + (t & 1) * KSTG);
        }

        if (act && act2) {
            float nm[2], corr[2];
            #pragma unroll
            for (int h = 0; h < 2; h++) {
                nm[h]   = fmaxf(m_s[h], tmax[h]);
                corr[h] = __expf(m_s[h] - nm[h]);
                m_s[h]  = nm[h];
            }
            float psum[2] = {0.0f, 0.0f};
            #pragma unroll
            for (int nt = 0; nt < 8; nt++)
                #pragma unroll
                for (int i = 0; i < 4; i++) {
                    const float p = __expf(acc_s[nt][i] - nm[i >> 1]);
                    acc_s[nt][i] = p;
                    psum[i >> 1] += p;
                }
            #pragma unroll
            for (int h = 0; h < 2; h++) {
                psum[h] += __shfl_xor_sync(0xffffffffu, psum[h], 1);
                psum[h] += __shfl_xor_sync(0xffffffffu, psum[h], 2);
                l_s[h] = l_s[h] * corr[h] + psum[h];
            }
            #pragma unroll
            for (int nt = 0; nt < 8; nt++)
                #pragma unroll
                for (int i = 0; i < 4; i++) acc_o[nt][i] *= corr[i >> 1];

            uint32_t ph[4][4], pl[4][4];
            #pragma unroll
            for (int kt = 0; kt < 4; kt++) {
                split2(acc_s[2 * kt][0],     acc_s[2 * kt][1],     ph[kt][0], pl[kt][0]);
                split2(acc_s[2 * kt][2],     acc_s[2 * kt][3],     ph[kt][1], pl[kt][1]);
                split2(acc_s[2 * kt + 1][0], acc_s[2 * kt + 1][1], ph[kt][2], pl[kt][2]);
                split2(acc_s[2 * kt + 1][2], acc_s[2 * kt + 1][3], ph[kt][3], pl[kt][3]);
            }

            #pragma unroll
            for (int kt = 0; kt < 4; kt++) {
                uint32_t vh[4][4], vl[4][4];
                const uint32_t vrow = kt * 16 + (lane & 15);
                const uint32_t vcol = (lane >> 4) * 8;
                #pragma unroll
                for (int g = 0; g < 4; g++) {
                    const uint32_t off = vrow * AROWB + (g * 16 + vcol) * 2;
                    ldsm_x4t(vh[g], vbase + off);
                    ldsm_x4t(vl[g], vbase + ARR + off);
                }
                #pragma unroll
                for (int nt = 0; nt < 8; nt++)
                    mma16816(acc_o[nt], ph[kt], &vh[nt >> 1][(nt & 1) * 2]);
                #pragma unroll
                for (int nt = 0; nt < 8; nt++)
                    mma16816(acc_o[nt], pl[kt], &vh[nt >> 1][(nt & 1) * 2]);
                #pragma unroll
                for (int nt = 0; nt < 8; nt++)
                    mma16816(acc_o[nt], ph[kt], &vl[nt >> 1][(nt & 1) * 2]);
            }
        }
    }

    // ---- epilogue ----
    const float inv0 = 1.0f / l_s[0];
    const float inv1 = 1.0f / l_s[1];
    const int b  = bh >> 4;
    const int hh = bh & 15;
    const int r0 = q0 + wid * 16 + (lane >> 2);
    #pragma unroll
    for (int nt = 0; nt < 8; nt++) {
        const int col = hh * 64 + nt * 8 + 2 * (lane & 3);
        {
            const long idx = ((long)(b * S_LEN + r0)) * DMODEL + col;
            uint32_t hi, lo;
            split2(acc_o[nt][0] * inv0, acc_o[nt][1] * inv0, hi, lo);
            *(uint32_t*)(Ohi + idx) = hi;
            *(uint32_t*)(Olo + idx) = lo;
        }
        {
            const long idx = ((long)(b * S_LEN + r0 + 8)) * DMODEL + col;
            uint32_t hi, lo;
            split2(acc_o[nt][2] * inv1, acc_o[nt][3] * inv1, hi, lo);
            *(uint32_t*)(Ohi + idx) = hi;
            *(uint32_t*)(Olo + idx) = lo;
        }
    }
}

// ============================================================================
// conversion kernels (fused)
// ============================================================================
__global__ void __launch_bounds__(256)
conv_qkv(const float* __restrict__ q, const float* __restrict__ k,
         const float* __restrict__ v)
{
    const int z = blockIdx.y;
    const float* X = (z == 0) ? q : (z == 1) ? k : v;
    const int i = blockIdx.x * 256 + threadIdx.x;   // over float2
    const float2 x = ((const float2*)X)[i];
    uint32_t h, l;
    split2(x.x, x.y, h, l);
    ((uint32_t*)g_Ahi[z])[i] = h;
    ((uint32_t*)g_Alo[z])[i] = l;
}

__global__ void __launch_bounds__(256)
conv_w(const float* __restrict__ W0, const float* __restrict__ W1,
       const float* __restrict__ W2, const float* __restrict__ W3)
{
    __shared__ float t[32][33];
    const int z = blockIdx.z;
    const float* W = (z == 0) ? W0 : (z == 1) ? W1 : (z == 2) ? W2 : W3;
    const int tx = threadIdx.x, ty = threadIdx.y;     // (32, 8)
    const int n0 = blockIdx.x * 32, k0 = blockIdx.y * 32;
    #pragma unroll
    for (int r = 0; r < 4; r++) {
        const int k = ty + r * 8;
        t[k][tx] = W[(long)(k0 + k) * DMODEL + n0 + tx];
    }
    __syncthreads();
    #pragma unroll
    for (int r = 0; r < 4; r++) {
        const int nl = ty + r * 8;
        const float x = t[tx][nl];
        const __nv_bfloat16 h = __float2bfloat16(x);
        const long o = (long)(n0 + nl) * DMODEL + k0 + tx;
        g_Whi[z][o] = h;
        g_Wlo[z][o] = __float2bfloat16(x - __bfloat162float(h));
    }
}

// ============================================================================
extern "C" void kernel_launch(void* const* d_in, const int* in_sizes, int n_in,
                              void* d_out, int out_size)
{
    const float* q = (const float*)d_in[0];
    const float* k = (const float*)d_in[1];
    const float* v = (const float*)d_in[2];
    float* out = (float*)d_out;

    __nv_bfloat16 *whi, *wlo;
    __nv_bfloat16 *qhi, *qlo, *khi, *klo, *vhi, *vlo, *ohi, *olo;
    cudaGetSymbolAddress((void**)&whi, g_Whi);
    cudaGetSymbolAddress((void**)&wlo, g_Wlo);
    cudaGetSymbolAddress((void**)&qhi, g_Qhi);
    cudaGetSymbolAddress((void**)&qlo, g_Qlo);
    cudaGetSymbolAddress((void**)&khi, g_Khi);
    cudaGetSymbolAddress((void**)&klo, g_Klo);
    cudaGetSymbolAddress((void**)&vhi, g_Vhi);
    cudaGetSymbolAddress((void**)&vlo, g_Vlo);
    cudaGetSymbolAddress((void**)&ohi, g_Ohi);
    cudaGetSymbolAddress((void**)&olo, g_Olo);

    cudaFuncSetAttribute((const void*)gemm_qkv,
                         cudaFuncAttributeMaxDynamicSharedMemorySize, GSMEM);
    cudaFuncSetAttribute((const void*)gemm_out,
                         cudaFuncAttributeMaxDynamicSharedMemorySize, GSMEM);
    cudaFuncSetAttribute((const void*)attn_mma,
                         cudaFuncAttributeMaxDynamicSharedMemorySize, ASMEM);

    conv_w<<<dim3(32, 32, 4), dim3(32, 8)>>>(
        (const float*)d_in[3], (const float*)d_in[4],
        (const float*)d_in[5], (const float*)d_in[6]);

    conv_qkv<<<dim3(AELEMS / 2 / 256, 3), 256>>>(q, k, v);

    gemm_qkv<<<dim3(8, 128, 3), 128, GSMEM>>>(qhi, qlo, khi, klo, vhi, vlo);

    attn_mma<<<dim3(S_LEN / 64, BHCNT), 128, ASMEM>>>(qhi, qlo, khi, klo,
                                                      vhi, vlo, ohi, olo);

    gemm_out<<<dim3(8, 128), 128, GSMEM>>>(ohi, olo,
        whi + 3 * (long)WELEMS, wlo + 3 * (long)WELEMS, out);
}

// round 11
// speedup vs baseline: 1.1799x; 1.0489x over previous
#include <cuda_runtime.h>
#include <cuda_bf16.h>
#include <cuda_fp16.h>
#include <cstdint>

#define S_LEN   2048
#define DMODEL  1024
#define NHEADS  16
#define HDIM    64
#define BATCH   4
#define BHCNT   (BATCH * NHEADS)                   // 64
#define MROWS   (BATCH * S_LEN)                    // 8192
#define HS_ELEMS (BATCH * NHEADS * S_LEN * HDIM)   // 8388608
#define AELEMS  (MROWS * DMODEL)                   // 8388608
#define WELEMS  (DMODEL * DMODEL)                  // 1048576

// ---- scratch ----
__device__ __nv_bfloat16 g_Ahi[3][AELEMS];
__device__ __nv_bfloat16 g_Alo[3][AELEMS];
__device__ __nv_bfloat16 g_Whi[4][WELEMS];   // transposed [N][K]
__device__ __nv_bfloat16 g_Wlo[4][WELEMS];
__device__ __nv_bfloat16 g_Qhi[HS_ELEMS], g_Qlo[HS_ELEMS];   // bf16, pre-scaled 1/8
__device__ __nv_bfloat16 g_Khi[HS_ELEMS], g_Klo[HS_ELEMS];   // bf16
__device__ __half        g_Vhi[HS_ELEMS], g_Vlo[HS_ELEMS];   // fp16 hi/lo
__device__ __nv_bfloat16 g_Ohi[AELEMS],  g_Olo[AELEMS];      // row-major [8192][1024]

// ============================================================================
// helpers (baseline PTX only)
// ============================================================================
__device__ __forceinline__ uint32_t smem_u32(const void* p) {
    uint32_t a;
    asm("{ .reg .u64 t; cvta.to.shared.u64 t, %1; cvt.u32.u64 %0, t; }"
        : "=r"(a) : "l"(p));
    return a;
}
__device__ __forceinline__ void cp_async16(uint32_t dst, const void* src) {
    asm volatile("cp.async.cg.shared.global [%0], [%1], 16;"
                 :: "r"(dst), "l"(src));
}
__device__ __forceinline__ void cp_commit() {
    asm volatile("cp.async.commit_group;");
}
template <int N>
__device__ __forceinline__ void cp_wait() {
    asm volatile("cp.async.wait_group %0;" :: "n"(N));
}
__device__ __forceinline__ void ldsm_x4(uint32_t* r, uint32_t addr) {
    asm volatile("ldmatrix.sync.aligned.m8n8.x4.shared.b16 {%0,%1,%2,%3}, [%4];"
                 : "=r"(r[0]), "=r"(r[1]), "=r"(r[2]), "=r"(r[3]) : "r"(addr));
}
__device__ __forceinline__ void ldsm_x4t(uint32_t* r, uint32_t addr) {
    asm volatile("ldmatrix.sync.aligned.m8n8.x4.trans.shared.b16 {%0,%1,%2,%3}, [%4];"
                 : "=r"(r[0]), "=r"(r[1]), "=r"(r[2]), "=r"(r[3]) : "r"(addr));
}
__device__ __forceinline__ void mma16816(float* d, const uint32_t* a,
                                         const uint32_t* b) {
    asm volatile("mma.sync.aligned.m16n8k16.row.col.f32.bf16.bf16.f32 "
                 "{%0,%1,%2,%3}, {%4,%5,%6,%7}, {%8,%9}, {%0,%1,%2,%3};"
                 : "+f"(d[0]), "+f"(d[1]), "+f"(d[2]), "+f"(d[3])
                 : "r"(a[0]), "r"(a[1]), "r"(a[2]), "r"(a[3]),
                   "r"(b[0]), "r"(b[1]));
}
__device__ __forceinline__ void mma16816h(float* d, const uint32_t* a,
                                          const uint32_t* b) {
    asm volatile("mma.sync.aligned.m16n8k16.row.col.f32.f16.f16.f32 "
                 "{%0,%1,%2,%3}, {%4,%5,%6,%7}, {%8,%9}, {%0,%1,%2,%3};"
                 : "+f"(d[0]), "+f"(d[1]), "+f"(d[2]), "+f"(d[3])
                 : "r"(a[0]), "r"(a[1]), "r"(a[2]), "r"(a[3]),
                   "r"(b[0]), "r"(b[1]));
}
// packed bf16 split: hi = bf16x2(a,b) (a low), lo = bf16x2 of residuals
__device__ __forceinline__ void split2(float a, float b,
                                       uint32_t& hi, uint32_t& lo) {
    uint32_t h;
    asm("cvt.rn.bf16x2.f32 %0, %1, %2;" : "=r"(h) : "f"(b), "f"(a));
    const float fa = __uint_as_float(h << 16);
    const float fb = __uint_as_float(h & 0xFFFF0000u);
    uint32_t l;
    asm("cvt.rn.bf16x2.f32 %0, %1, %2;" : "=r"(l) : "f"(b - fb), "f"(a - fa));
    hi = h; lo = l;
}
// packed fp16 split (for V)
__device__ __forceinline__ void split2h(float a, float b,
                                        uint32_t& hi, uint32_t& lo) {
    uint32_t h;
    asm("cvt.rn.f16x2.f32 %0, %1, %2;" : "=r"(h) : "f"(b), "f"(a));
    const float fa = __half2float(__ushort_as_half((unsigned short)(h & 0xFFFFu)));
    const float fb = __half2float(__ushort_as_half((unsigned short)(h >> 16)));
    uint32_t l;
    asm("cvt.rn.f16x2.f32 %0, %1, %2;" : "=r"(l) : "f"(b - fb), "f"(a - fa));
    hi = h; lo = l;
}
// single fp16x2 pack (for P)
__device__ __forceinline__ uint32_t packh2(float a, float b) {
    uint32_t h;
    asm("cvt.rn.f16x2.f32 %0, %1, %2;" : "=r"(h) : "f"(b), "f"(a));
    return h;
}

// ============================================================================
// GEMM mainloop (R10, unchanged): tile 64x128, BK=32, 4 warps, 3-term bf16,
// 2-stage cp.async, XOR-swizzled 64B rows, 48KB/CTA -> 4 CTAs/SM.
// ============================================================================
#define GA_BYTES   (64 * 64)                 // 4096
#define GB_BYTES   (128 * 64)                // 8192
#define STG_BYTES  (2 * GA_BYTES + 2 * GB_BYTES)  // 24576
#define GSMEM      (2 * STG_BYTES)           // 49152

__device__ __forceinline__ uint32_t swz64(uint32_t row, uint32_t seg) {
    return row * 64 + ((seg ^ (row & 3)) * 16);
}

__device__ __forceinline__ void gemm_core(
    const __nv_bfloat16* __restrict__ Ahi, const __nv_bfloat16* __restrict__ Alo,
    const __nv_bfloat16* __restrict__ Bhi, const __nv_bfloat16* __restrict__ Blo,
    uint32_t sb, int tid, int bc, int br, float acc[2][8][4])
{
    const int lane   = tid & 31;
    const int wid    = tid >> 5;
    const int warp_m = wid >> 1;
    const int warp_n = wid & 1;

    auto issue = [&](int kc, int stage) {
        #pragma unroll
        for (int t = 0; t < 12; t++) {
            const int c = tid + t * 128;
            uint32_t dst;
            const __nv_bfloat16* g;
            if (c < 512) {
                const int arr = c >> 8, rem = c & 255;
                const int row = rem >> 2, seg = rem & 3;
                g = (arr ? Alo : Ahi) + (long)(br * 64 + row) * DMODEL
                  + kc * 32 + seg * 8;
                dst = sb + stage * STG_BYTES + arr * GA_BYTES + swz64(row, seg);
            } else {
                const int cb = c - 512;
                const int arr = cb >> 9, rem = cb & 511;
                const int row = rem >> 2, seg = rem & 3;
                g = (arr ? Blo : Bhi) + (long)(bc * 128 + row) * DMODEL
                  + kc * 32 + seg * 8;
                dst = sb + stage * STG_BYTES + 2 * GA_BYTES + arr * GB_BYTES
                    + swz64(row, seg);
            }
            cp_async16(dst, g);
        }
        cp_commit();
    };

    issue(0, 0);

    const int NKC = DMODEL / 32;
    for (int kc = 0; kc < NKC; kc++) {
        cp_wait<0>();
        __syncthreads();
        if (kc + 1 < NKC) issue(kc + 1, (kc + 1) & 1);

        const uint32_t base = sb + (kc & 1) * STG_BYTES;

        #pragma unroll
        for (int kk = 0; kk < 2; kk++) {
            uint32_t ahi[2][4], alo[2][4];
            {
                const uint32_t ar0  = warp_m * 32 + (lane & 15);
                const uint32_t aseg = kk * 2 + (lane >> 4);
                ldsm_x4(ahi[0], base + swz64(ar0, aseg));
                ldsm_x4(ahi[1], base + swz64(ar0 + 16, aseg));
                ldsm_x4(alo[0], base + GA_BYTES + swz64(ar0, aseg));
                ldsm_x4(alo[1], base + GA_BYTES + swz64(ar0 + 16, aseg));
            }
            const uint32_t br0  = warp_n * 64 + (lane & 7) + ((lane & 16) >> 1);
            const uint32_t bseg = kk * 2 + ((lane >> 3) & 1);
            #pragma unroll
            for (int q = 0; q < 4; q++) {
                uint32_t bhi[4], blo[4];
                const uint32_t brow = br0 + q * 16;
                ldsm_x4(bhi, base + 2 * GA_BYTES + swz64(brow, bseg));
                ldsm_x4(blo, base + 2 * GA_BYTES + GB_BYTES + swz64(brow, bseg));
                #pragma unroll
                for (int mt = 0; mt < 2; mt++)
                    #pragma unroll
                    for (int n2 = 0; n2 < 2; n2++)
                        mma16816(acc[mt][2 * q + n2], ahi[mt], &bhi[n2 * 2]);
                #pragma unroll
                for (int mt = 0; mt < 2; mt++)
                    #pragma unroll
                    for (int n2 = 0; n2 < 2; n2++)
                        mma16816(acc[mt][2 * q + n2], ahi[mt], &blo[n2 * 2]);
                #pragma unroll
                for (int mt = 0; mt < 2; mt++)
                    #pragma unroll
                    for (int n2 = 0; n2 < 2; n2++)
                        mma16816(acc[mt][2 * q + n2], alo[mt], &bhi[n2 * 2]);
            }
        }
    }
}

// ============================================================================
// Batched QKV projection GEMM: grid (8, 128, 3), 128 threads, 4 CTAs/SM.
// z==2 (V) emits fp16 hi/lo; z==0/1 emit bf16 hi/lo (Q pre-scaled 1/8).
// ============================================================================
__global__ void __launch_bounds__(128, 4)
gemm_qkv(__nv_bfloat16* __restrict__ Qhi, __nv_bfloat16* __restrict__ Qlo,
         __nv_bfloat16* __restrict__ Khi, __nv_bfloat16* __restrict__ Klo,
         __half* __restrict__ Vhi, __half* __restrict__ Vlo)
{
    extern __shared__ char smem[];
    const uint32_t sb = smem_u32(smem);
    const int tid = threadIdx.x;
    const int bc = blockIdx.x, br = blockIdx.y, z = blockIdx.z;

    uint32_t *Chi, *Clo;
    float scale;
    if (z == 0)      { Chi = (uint32_t*)Qhi; Clo = (uint32_t*)Qlo; scale = 0.125f; }
    else if (z == 1) { Chi = (uint32_t*)Khi; Clo = (uint32_t*)Klo; scale = 1.0f; }
    else             { Chi = (uint32_t*)Vhi; Clo = (uint32_t*)Vlo; scale = 1.0f; }

    float acc[2][8][4];
    #pragma unroll
    for (int mt = 0; mt < 2; mt++)
        #pragma unroll
        for (int nt = 0; nt < 8; nt++)
            #pragma unroll
            for (int i = 0; i < 4; i++) acc[mt][nt][i] = 0.0f;

    gemm_core(g_Ahi[z], g_Alo[z], g_Whi[z], g_Wlo[z], sb, tid, bc, br, acc);

    const int lane = tid & 31, wid = tid >> 5;
    const int warp_m = wid >> 1, warp_n = wid & 1;
    #pragma unroll
    for (int mt = 0; mt < 2; mt++) {
        #pragma unroll
        for (int nt = 0; nt < 8; nt++) {
            const int row0 = br * 64 + warp_m * 32 + mt * 16 + (lane >> 2);
            const int col  = bc * 128 + warp_n * 64 + nt * 8 + (lane & 3) * 2;
            const int h = col >> 6, dd = col & 63;
            #pragma unroll
            for (int half = 0; half < 2; half++) {
                const int r = row0 + half * 8;
                const int b = r >> 11, s = r & 2047;
                const long off = (((((long)b * NHEADS + h) * S_LEN + s) * HDIM) + dd) >> 1;
                uint32_t hi, lo;
                if (z == 2)
                    split2h(acc[mt][nt][half * 2], acc[mt][nt][half * 2 + 1], hi, lo);
                else
                    split2(acc[mt][nt][half * 2] * scale,
                           acc[mt][nt][half * 2 + 1] * scale, hi, lo);
                Chi[off] = hi;
                Clo[off] = lo;
            }
        }
    }
}

// ============================================================================
// Output projection GEMM: fp32 row-major result. grid (8, 128), 128 threads.
// ============================================================================
__global__ void __launch_bounds__(128, 4)
gemm_out(const __nv_bfloat16* __restrict__ Ahi, const __nv_bfloat16* __restrict__ Alo,
         const __nv_bfloat16* __restrict__ Bhi, const __nv_bfloat16* __restrict__ Blo,
         float* __restrict__ Cf)
{
    extern __shared__ char smem[];
    const uint32_t sb = smem_u32(smem);
    const int tid = threadIdx.x;
    const int bc = blockIdx.x, br = blockIdx.y;

    float acc[2][8][4];
    #pragma unroll
    for (int mt = 0; mt < 2; mt++)
        #pragma unroll
        for (int nt = 0; nt < 8; nt++)
            #pragma unroll
            for (int i = 0; i < 4; i++) acc[mt][nt][i] = 0.0f;

    gemm_core(Ahi, Alo, Bhi, Blo, sb, tid, bc, br, acc);

    const int lane = tid & 31, wid = tid >> 5;
    const int warp_m = wid >> 1, warp_n = wid & 1;
    #pragma unroll
    for (int mt = 0; mt < 2; mt++) {
        #pragma unroll
        for (int nt = 0; nt < 8; nt++) {
            const int row0 = br * 64 + warp_m * 32 + mt * 16 + (lane >> 2);
            const int col  = bc * 128 + warp_n * 64 + nt * 8 + (lane & 3) * 2;
            float2 v01; v01.x = acc[mt][nt][0]; v01.y = acc[mt][nt][1];
            float2 v23; v23.x = acc[mt][nt][2]; v23.y = acc[mt][nt][3];
            *(float2*)&Cf[(long)row0 * DMODEL + col] = v01;
            *(float2*)&Cf[(long)(row0 + 8) * DMODEL + col] = v23;
        }
    }
}

// ============================================================================
// Tensor-core causal flash attention (R8/R10 structure).
// QK: bf16 3-term. PV: fp16, P single + V hi/lo = 2 terms.
// ============================================================================
#define AROWB    144
#define ARR      (64 * AROWB)            // 9216
#define KSTG     (2 * ARR)               // 18432
#define VOFF     (2 * KSTG)              // 36864
#define ASMEM    (VOFF + 2 * KSTG)       // 73728

__global__ void __launch_bounds__(128, 3)
attn_mma(const __nv_bfloat16* __restrict__ Qhi, const __nv_bfloat16* __restrict__ Qlo,
         const __nv_bfloat16* __restrict__ Khi, const __nv_bfloat16* __restrict__ Klo,
         const __half* __restrict__ Vhi, const __half* __restrict__ Vlo,
         __nv_bfloat16* __restrict__ Ohi, __nv_bfloat16* __restrict__ Olo)
{
    extern __shared__ char smem[];
    const uint32_t sb = smem_u32(smem);
    const int tid = threadIdx.x, wid = tid >> 5, lane = tid & 31;
    const int qblk = (int)gridDim.x - 1 - (int)blockIdx.x;   // longest first
    const int q0 = qblk * 64;
    const int bh = blockIdx.y;
    const long base = (long)bh * S_LEN * HDIM;
    const int ntiles = qblk + 1;

    auto ld2arr = [&](const void* hi, const void* lo,
                      long grow0, uint32_t smem_base) {
        #pragma unroll
        for (int t = 0; t < 8; t++) {
            const int c = tid + t * 128;            // 0..1023
            const int arr = c >> 9, rem = c & 511;
            const int row = rem >> 3, seg = rem & 7;
            const char* src = (const char*)(arr ? lo : hi)
                            + ((base + (grow0 + row) * HDIM + seg * 8) << 1);
            cp_async16(smem_base + arr * ARR + row * AROWB + seg * 16, src);
        }
        cp_commit();
    };

    // ---- prologue ----
    ld2arr(Qhi, Qlo, (long)q0, sb + VOFF + KSTG);           // GQ -> V stage 1
    ld2arr(Khi, Klo, 0L, sb);                               // K(0) -> K stage 0
    cp_wait<1>();                                           // GQ done
    __syncthreads();

    uint32_t qhF[4][4], qlF[4][4];
    {
        const uint32_t arow = wid * 16 + (lane & 15);
        #pragma unroll
        for (int kt = 0; kt < 4; kt++) {
            const uint32_t off = arow * AROWB + (kt * 16 + (lane >> 4) * 8) * 2;
            ldsm_x4(qhF[kt], sb + VOFF + KSTG + off);
            ldsm_x4(qlF[kt], sb + VOFF + KSTG + ARR + off);
        }
    }
    __syncthreads();                                        // Q reads done
    ld2arr(Vhi, Vlo, 0L, sb + VOFF);                        // GV_{-1}: V(0)
    {
        const int tk = (1 < ntiles) ? 1 : 0;
        ld2arr(Khi, Klo, (long)tk * 64, sb + KSTG);         // GK_{-1}: K(1)
    }

    float m_s[2] = {-1e30f, -1e30f};
    float l_s[2] = {0.0f, 0.0f};
    float acc_o[8][4];
    #pragma unroll
    for (int nt = 0; nt < 8; nt++)
        #pragma unroll
        for (int i = 0; i < 4; i++) acc_o[nt][i] = 0.0f;

    const int wrow_lo = q0 + wid * 16;

    for (int t = 0; t < ntiles; t++) {
        cp_wait<2>();                 // K(t) resident
        __syncthreads();              // sync1
        {
            const int tv = (t + 1 < ntiles) ? t + 1 : ntiles - 1;
            ld2arr(Vhi, Vlo, (long)tv * 64, sb + VOFF + ((t + 1) & 1) * KSTG);
        }

        const uint32_t kbase = sb + (t & 1) * KSTG;
        const uint32_t vbase = sb + VOFF + (t & 1) * KSTG;
        const bool act = (t * 64 <= wrow_lo + 15);

        float acc_s[8][4];
        float tmax[2] = {-1e30f, -1e30f};
        bool act2 = false;

        if (act) {
            #pragma unroll
            for (int nt = 0; nt < 8; nt++)
                #pragma unroll
                for (int i = 0; i < 4; i++) acc_s[nt][i] = 0.0f;

            #pragma unroll
            for (int kt = 0; kt < 4; kt++) {
                uint32_t kh[4][4], kl[4][4];
                const uint32_t brow = (lane & 7) + ((lane & 16) >> 1);
                const uint32_t bcol = kt * 16 + ((lane >> 3) & 1) * 8;
                #pragma unroll
                for (int g = 0; g < 4; g++) {
                    const uint32_t off = (g * 16 + brow) * AROWB + bcol * 2;
                    ldsm_x4(kh[g], kbase + off);
                    ldsm_x4(kl[g], kbase + ARR + off);
                }
                #pragma unroll
                for (int nt = 0; nt < 8; nt++)
                    mma16816(acc_s[nt], qhF[kt], &kh[nt >> 1][(nt & 1) * 2]);
                #pragma unroll
                for (int nt = 0; nt < 8; nt++)
                    mma16816(acc_s[nt], qhF[kt], &kl[nt >> 1][(nt & 1) * 2]);
                #pragma unroll
                for (int nt = 0; nt < 8; nt++)
                    mma16816(acc_s[nt], qlF[kt], &kh[nt >> 1][(nt & 1) * 2]);
            }

            const int r0 = q0 + wid * 16 + (lane >> 2);
            if (t * 64 + 63 > wrow_lo) {
                #pragma unroll
                for (int nt = 0; nt < 8; nt++)
                    #pragma unroll
                    for (int i = 0; i < 4; i++) {
                        const int row = r0 + (i >> 1) * 8;
                        const int col = t * 64 + nt * 8 + 2 * (lane & 3) + (i & 1);
                        if (col > row) acc_s[nt][i] = -1e30f;
                    }
            }

            #pragma unroll
            for (int nt = 0; nt < 8; nt++)
                #pragma unroll
                for (int i = 0; i < 4; i++)
                    tmax[i >> 1] = fmaxf(tmax[i >> 1], acc_s[nt][i]);
            #pragma unroll
            for (int h = 0; h < 2; h++) {
                tmax[h] = fmaxf(tmax[h], __shfl_xor_sync(0xffffffffu, tmax[h], 1));
                tmax[h] = fmaxf(tmax[h], __shfl_xor_sync(0xffffffffu, tmax[h], 2));
            }
            float d = fmaxf(tmax[0] - m_s[0], tmax[1] - m_s[1]);
            d = fmaxf(d, __shfl_xor_sync(0xffffffffu, d, 4));
            d = fmaxf(d, __shfl_xor_sync(0xffffffffu, d, 8));
            d = fmaxf(d, __shfl_xor_sync(0xffffffffu, d, 16));
            act2 = (d >= -44.0f);
        }

        cp_wait<2>();                 // V(t) resident
        __syncthreads();              // sync2
        {
            const int tk = (t + 2 < ntiles) ? t + 2 : ntiles - 1;
            ld2arr(Khi, Klo, (long)tk * 64, sb + (t & 1) * KSTG);
        }

        if (act && act2) {
            float nm[2], corr[2];
            #pragma unroll
            for (int h = 0; h < 2; h++) {
                nm[h]   = fmaxf(m_s[h], tmax[h]);
                corr[h] = __expf(m_s[h] - nm[h]);
                m_s[h]  = nm[h];
            }
            float psum[2] = {0.0f, 0.0f};
            #pragma unroll
            for (int nt = 0; nt < 8; nt++)
                #pragma unroll
                for (int i = 0; i < 4; i++) {
                    const float p = __expf(acc_s[nt][i] - nm[i >> 1]);
                    acc_s[nt][i] = p;
                    psum[i >> 1] += p;
                }
            #pragma unroll
            for (int h = 0; h < 2; h++) {
                psum[h] += __shfl_xor_sync(0xffffffffu, psum[h], 1);
                psum[h] += __shfl_xor_sync(0xffffffffu, psum[h], 2);
                l_s[h] = l_s[h] * corr[h] + psum[h];
            }
            #pragma unroll
            for (int nt = 0; nt < 8; nt++)
                #pragma unroll
                for (int i = 0; i < 4; i++) acc_o[nt][i] *= corr[i >> 1];

            // ---- pack P as single fp16 (C-frag -> A-frag identity) ----
            uint32_t ph[4][4];
            #pragma unroll
            for (int kt = 0; kt < 4; kt++) {
                ph[kt][0] = packh2(acc_s[2 * kt][0],     acc_s[2 * kt][1]);
                ph[kt][1] = packh2(acc_s[2 * kt][2],     acc_s[2 * kt][3]);
                ph[kt][2] = packh2(acc_s[2 * kt + 1][0], acc_s[2 * kt + 1][1]);
                ph[kt][3] = packh2(acc_s[2 * kt + 1][2], acc_s[2 * kt + 1][3]);
            }

            // ---- O += P @ (Vhi + Vlo), fp16, 2 terms ----
            #pragma unroll
            for (int kt = 0; kt < 4; kt++) {
                uint32_t vh[4][4], vl[4][4];
                const uint32_t vrow = kt * 16 + (lane & 15);
                const uint32_t vcol = (lane >> 4) * 8;
                #pragma unroll
                for (int g = 0; g < 4; g++) {
                    const uint32_t off = vrow * AROWB + (g * 16 + vcol) * 2;
                    ldsm_x4t(vh[g], vbase + off);
                    ldsm_x4t(vl[g], vbase + ARR + off);
                }
                #pragma unroll
                for (int nt = 0; nt < 8; nt++)
                    mma16816h(acc_o[nt], ph[kt], &vh[nt >> 1][(nt & 1) * 2]);
                #pragma unroll
                for (int nt = 0; nt < 8; nt++)
                    mma16816h(acc_o[nt], ph[kt], &vl[nt >> 1][(nt & 1) * 2]);
            }
        }
    }

    // ---- epilogue: bf16 hi/lo for the O-projection ----
    const float inv0 = 1.0f / l_s[0];
    const float inv1 = 1.0f / l_s[1];
    const int b  = bh >> 4;
    const int hh = bh & 15;
    const int r0 = q0 + wid * 16 + (lane >> 2);
    #pragma unroll
    for (int nt = 0; nt < 8; nt++) {
        const int col = hh * 64 + nt * 8 + 2 * (lane & 3);
        {
            const long idx = ((long)(b * S_LEN + r0)) * DMODEL + col;
            uint32_t hi, lo;
            split2(acc_o[nt][0] * inv0, acc_o[nt][1] * inv0, hi, lo);
            *(uint32_t*)(Ohi + idx) = hi;
            *(uint32_t*)(Olo + idx) = lo;
        }
        {
            const long idx = ((long)(b * S_LEN + r0 + 8)) * DMODEL + col;
            uint32_t hi, lo;
            split2(acc_o[nt][2] * inv1, acc_o[nt][3] * inv1, hi, lo);
            *(uint32_t*)(Ohi + idx) = hi;
            *(uint32_t*)(Olo + idx) = lo;
        }
    }
}

// ============================================================================
// conversion kernels (fused)
// ============================================================================
__global__ void __launch_bounds__(256)
conv_qkv(const float* __restrict__ q, const float* __restrict__ k,
         const float* __restrict__ v)
{
    const int z = blockIdx.y;
    const float* X = (z == 0) ? q : (z == 1) ? k : v;
    const int i = blockIdx.x * 256 + threadIdx.x;
    const float2 x = ((const float2*)X)[i];
    uint32_t h, l;
    split2(x.x, x.y, h, l);
    ((uint32_t*)g_Ahi[z])[i] = h;
    ((uint32_t*)g_Alo[z])[i] = l;
}

__global__ void __launch_bounds__(256)
conv_w(const float* __restrict__ W0, const float* __restrict__ W1,
       const float* __restrict__ W2, const float* __restrict__ W3)
{
    __shared__ float t[32][33];
    const int z = blockIdx.z;
    const float* W = (z == 0) ? W0 : (z == 1) ? W1 : (z == 2) ? W2 : W3;
    const int tx = threadIdx.x, ty = threadIdx.y;
    const int n0 = blockIdx.x * 32, k0 = blockIdx.y * 32;
    #pragma unroll
    for (int r = 0; r < 4; r++) {
        const int k = ty + r * 8;
        t[k][tx] = W[(long)(k0 + k) * DMODEL + n0 + tx];
    }
    __syncthreads();
    #pragma unroll
    for (int r = 0; r < 4; r++) {
        const int nl = ty + r * 8;
        const float x = t[tx][nl];
        const __nv_bfloat16 h = __float2bfloat16(x);
        const long o = (long)(n0 + nl) * DMODEL + k0 + tx;
        g_Whi[z][o] = h;
        g_Wlo[z][o] = __float2bfloat16(x - __bfloat162float(h));
    }
}

// ============================================================================
extern "C" void kernel_launch(void* const* d_in, const int* in_sizes, int n_in,
                              void* d_out, int out_size)
{
    const float* q = (const float*)d_in[0];
    const float* k = (const float*)d_in[1];
    const float* v = (const float*)d_in[2];
    float* out = (float*)d_out;

    __nv_bfloat16 *whi, *wlo;
    __nv_bfloat16 *qhi, *qlo, *khi, *klo, *ohi, *olo;
    __half *vhi, *vlo;
    cudaGetSymbolAddress((void**)&whi, g_Whi);
    cudaGetSymbolAddress((void**)&wlo, g_Wlo);
    cudaGetSymbolAddress((void**)&qhi, g_Qhi);
    cudaGetSymbolAddress((void**)&qlo, g_Qlo);
    cudaGetSymbolAddress((void**)&khi, g_Khi);
    cudaGetSymbolAddress((void**)&klo, g_Klo);
    cudaGetSymbolAddress((void**)&vhi, g_Vhi);
    cudaGetSymbolAddress((void**)&vlo, g_Vlo);
    cudaGetSymbolAddress((void**)&ohi, g_Ohi);
    cudaGetSymbolAddress((void**)&olo, g_Olo);

    cudaFuncSetAttribute((const void*)gemm_qkv,
                         cudaFuncAttributeMaxDynamicSharedMemorySize, GSMEM);
    cudaFuncSetAttribute((const void*)gemm_out,
                         cudaFuncAttributeMaxDynamicSharedMemorySize, GSMEM);
    cudaFuncSetAttribute((const void*)attn_mma,
                         cudaFuncAttributeMaxDynamicSharedMemorySize, ASMEM);

    conv_w<<<dim3(32, 32, 4), dim3(32, 8)>>>(
        (const float*)d_in[3], (const float*)d_in[4],
        (const float*)d_in[5], (const float*)d_in[6]);

    conv_qkv<<<dim3(AELEMS / 2 / 256, 3), 256>>>(q, k, v);

    gemm_qkv<<<dim3(8, 128, 3), 128, GSMEM>>>(qhi, qlo, khi, klo, vhi, vlo);

    attn_mma<<<dim3(S_LEN / 64, BHCNT), 128, ASMEM>>>(qhi, qlo, khi, klo,
                                                      vhi, vlo, ohi, olo);

    gemm_out<<<dim3(8, 128), 128, GSMEM>>>(ohi, olo,
        whi + 3 * (long)WELEMS, wlo + 3 * (long)WELEMS, out);
}

// round 12
// speedup vs baseline: 1.2104x; 1.0259x over previous
#include <cuda_runtime.h>
#include <cuda_bf16.h>
#include <cuda_fp16.h>
#include <cstdint>

#define S_LEN   2048
#define DMODEL  1024
#define NHEADS  16
#define HDIM    64
#define BATCH   4
#define BHCNT   (BATCH * NHEADS)                   // 64
#define MROWS   (BATCH * S_LEN)                    // 8192
#define HS_ELEMS (BATCH * NHEADS * S_LEN * HDIM)   // 8388608
#define AELEMS  (MROWS * DMODEL)                   // 8388608
#define WELEMS  (DMODEL * DMODEL)                  // 1048576

// ---- scratch ----
__device__ __nv_bfloat16 g_Ahi[3][AELEMS];
__device__ __nv_bfloat16 g_Alo[3][AELEMS];
__device__ __nv_bfloat16 g_Whi[4][WELEMS];   // transposed [N][K]
__device__ __nv_bfloat16 g_Wlo[4][WELEMS];
__device__ __nv_bfloat16 g_Qhi[HS_ELEMS], g_Qlo[HS_ELEMS];   // bf16, pre-scaled 1/8
__device__ __nv_bfloat16 g_Khi[HS_ELEMS], g_Klo[HS_ELEMS];   // bf16
__device__ __half        g_Vh[HS_ELEMS];                     // fp16 single
__device__ __nv_bfloat16 g_Ohi[AELEMS],  g_Olo[AELEMS];      // row-major [8192][1024]

// ============================================================================
// helpers (baseline PTX only)
// ============================================================================
__device__ __forceinline__ uint32_t smem_u32(const void* p) {
    uint32_t a;
    asm("{ .reg .u64 t; cvta.to.shared.u64 t, %1; cvt.u32.u64 %0, t; }"
        : "=r"(a) : "l"(p));
    return a;
}
__device__ __forceinline__ void cp_async16(uint32_t dst, const void* src) {
    asm volatile("cp.async.cg.shared.global [%0], [%1], 16;"
                 :: "r"(dst), "l"(src));
}
__device__ __forceinline__ void cp_commit() {
    asm volatile("cp.async.commit_group;");
}
template <int N>
__device__ __forceinline__ void cp_wait() {
    asm volatile("cp.async.wait_group %0;" :: "n"(N));
}
__device__ __forceinline__ void ldsm_x4(uint32_t* r, uint32_t addr) {
    asm volatile("ldmatrix.sync.aligned.m8n8.x4.shared.b16 {%0,%1,%2,%3}, [%4];"
                 : "=r"(r[0]), "=r"(r[1]), "=r"(r[2]), "=r"(r[3]) : "r"(addr));
}
__device__ __forceinline__ void ldsm_x4t(uint32_t* r, uint32_t addr) {
    asm volatile("ldmatrix.sync.aligned.m8n8.x4.trans.shared.b16 {%0,%1,%2,%3}, [%4];"
                 : "=r"(r[0]), "=r"(r[1]), "=r"(r[2]), "=r"(r[3]) : "r"(addr));
}
__device__ __forceinline__ void mma16816(float* d, const uint32_t* a,
                                         const uint32_t* b) {
    asm volatile("mma.sync.aligned.m16n8k16.row.col.f32.bf16.bf16.f32 "
                 "{%0,%1,%2,%3}, {%4,%5,%6,%7}, {%8,%9}, {%0,%1,%2,%3};"
                 : "+f"(d[0]), "+f"(d[1]), "+f"(d[2]), "+f"(d[3])
                 : "r"(a[0]), "r"(a[1]), "r"(a[2]), "r"(a[3]),
                   "r"(b[0]), "r"(b[1]));
}
__device__ __forceinline__ void mma16816h(float* d, const uint32_t* a,
                                          const uint32_t* b) {
    asm volatile("mma.sync.aligned.m16n8k16.row.col.f32.f16.f16.f32 "
                 "{%0,%1,%2,%3}, {%4,%5,%6,%7}, {%8,%9}, {%0,%1,%2,%3};"
                 : "+f"(d[0]), "+f"(d[1]), "+f"(d[2]), "+f"(d[3])
                 : "r"(a[0]), "r"(a[1]), "r"(a[2]), "r"(a[3]),
                   "r"(b[0]), "r"(b[1]));
}
// packed bf16 split: hi = bf16x2(a,b) (a low), lo = bf16x2 of residuals
__device__ __forceinline__ void split2(float a, float b,
                                       uint32_t& hi, uint32_t& lo) {
    uint32_t h;
    asm("cvt.rn.bf16x2.f32 %0, %1, %2;" : "=r"(h) : "f"(b), "f"(a));
    const float fa = __uint_as_float(h << 16);
    const float fb = __uint_as_float(h & 0xFFFF0000u);
    uint32_t l;
    asm("cvt.rn.bf16x2.f32 %0, %1, %2;" : "=r"(l) : "f"(b - fb), "f"(a - fa));
    hi = h; lo = l;
}
// single fp16x2 pack
__device__ __forceinline__ uint32_t packh2(float a, float b) {
    uint32_t h;
    asm("cvt.rn.f16x2.f32 %0, %1, %2;" : "=r"(h) : "f"(b), "f"(a));
    return h;
}

// ============================================================================
// GEMM mainloop (R10/R11, unchanged): tile 64x128, BK=32, 4 warps, bf16 3-term,
// 2-stage cp.async, XOR-swizzled 64B rows, 48KB/CTA -> 4 CTAs/SM.
// ============================================================================
#define GA_BYTES   (64 * 64)                 // 4096
#define GB_BYTES   (128 * 64)                // 8192
#define STG_BYTES  (2 * GA_BYTES + 2 * GB_BYTES)  // 24576
#define GSMEM      (2 * STG_BYTES)           // 49152

__device__ __forceinline__ uint32_t swz64(uint32_t row, uint32_t seg) {
    return row * 64 + ((seg ^ (row & 3)) * 16);
}

__device__ __forceinline__ void gemm_core(
    const __nv_bfloat16* __restrict__ Ahi, const __nv_bfloat16* __restrict__ Alo,
    const __nv_bfloat16* __restrict__ Bhi, const __nv_bfloat16* __restrict__ Blo,
    uint32_t sb, int tid, int bc, int br, float acc[2][8][4])
{
    const int lane   = tid & 31;
    const int wid    = tid >> 5;
    const int warp_m = wid >> 1;
    const int warp_n = wid & 1;

    auto issue = [&](int kc, int stage) {
        #pragma unroll
        for (int t = 0; t < 12; t++) {
            const int c = tid + t * 128;
            uint32_t dst;
            const __nv_bfloat16* g;
            if (c < 512) {
                const int arr = c >> 8, rem = c & 255;
                const int row = rem >> 2, seg = rem & 3;
                g = (arr ? Alo : Ahi) + (long)(br * 64 + row) * DMODEL
                  + kc * 32 + seg * 8;
                dst = sb + stage * STG_BYTES + arr * GA_BYTES + swz64(row, seg);
            } else {
                const int cb = c - 512;
                const int arr = cb >> 9, rem = cb & 511;
                const int row = rem >> 2, seg = rem & 3;
                g = (arr ? Blo : Bhi) + (long)(bc * 128 + row) * DMODEL
                  + kc * 32 + seg * 8;
                dst = sb + stage * STG_BYTES + 2 * GA_BYTES + arr * GB_BYTES
                    + swz64(row, seg);
            }
            cp_async16(dst, g);
        }
        cp_commit();
    };

    issue(0, 0);

    const int NKC = DMODEL / 32;
    for (int kc = 0; kc < NKC; kc++) {
        cp_wait<0>();
        __syncthreads();
        if (kc + 1 < NKC) issue(kc + 1, (kc + 1) & 1);

        const uint32_t base = sb + (kc & 1) * STG_BYTES;

        #pragma unroll
        for (int kk = 0; kk < 2; kk++) {
            uint32_t ahi[2][4], alo[2][4];
            {
                const uint32_t ar0  = warp_m * 32 + (lane & 15);
                const uint32_t aseg = kk * 2 + (lane >> 4);
                ldsm_x4(ahi[0], base + swz64(ar0, aseg));
                ldsm_x4(ahi[1], base + swz64(ar0 + 16, aseg));
                ldsm_x4(alo[0], base + GA_BYTES + swz64(ar0, aseg));
                ldsm_x4(alo[1], base + GA_BYTES + swz64(ar0 + 16, aseg));
            }
            const uint32_t br0  = warp_n * 64 + (lane & 7) + ((lane & 16) >> 1);
            const uint32_t bseg = kk * 2 + ((lane >> 3) & 1);
            #pragma unroll
            for (int q = 0; q < 4; q++) {
                uint32_t bhi[4], blo[4];
                const uint32_t brow = br0 + q * 16;
                ldsm_x4(bhi, base + 2 * GA_BYTES + swz64(brow, bseg));
                ldsm_x4(blo, base + 2 * GA_BYTES + GB_BYTES + swz64(brow, bseg));
                #pragma unroll
                for (int mt = 0; mt < 2; mt++)
                    #pragma unroll
                    for (int n2 = 0; n2 < 2; n2++)
                        mma16816(acc[mt][2 * q + n2], ahi[mt], &bhi[n2 * 2]);
                #pragma unroll
                for (int mt = 0; mt < 2; mt++)
                    #pragma unroll
                    for (int n2 = 0; n2 < 2; n2++)
                        mma16816(acc[mt][2 * q + n2], ahi[mt], &blo[n2 * 2]);
                #pragma unroll
                for (int mt = 0; mt < 2; mt++)
                    #pragma unroll
                    for (int n2 = 0; n2 < 2; n2++)
                        mma16816(acc[mt][2 * q + n2], alo[mt], &bhi[n2 * 2]);
            }
        }
    }
}

// ============================================================================
// Batched QKV projection GEMM: grid (8, 128, 3), 128 threads, 4 CTAs/SM.
// z==2 (V) emits SINGLE fp16; z==0/1 emit bf16 hi/lo (Q pre-scaled 1/8).
// ============================================================================
__global__ void __launch_bounds__(128, 4)
gemm_qkv(__nv_bfloat16* __restrict__ Qhi, __nv_bfloat16* __restrict__ Qlo,
         __nv_bfloat16* __restrict__ Khi, __nv_bfloat16* __restrict__ Klo,
         __half* __restrict__ Vh)
{
    extern __shared__ char smem[];
    const uint32_t sb = smem_u32(smem);
    const int tid = threadIdx.x;
    const int bc = blockIdx.x, br = blockIdx.y, z = blockIdx.z;

    uint32_t *Chi, *Clo;
    float scale;
    if (z == 0)      { Chi = (uint32_t*)Qhi; Clo = (uint32_t*)Qlo; scale = 0.125f; }
    else if (z == 1) { Chi = (uint32_t*)Khi; Clo = (uint32_t*)Klo; scale = 1.0f; }
    else             { Chi = (uint32_t*)Vh;  Clo = nullptr;        scale = 1.0f; }

    float acc[2][8][4];
    #pragma unroll
    for (int mt = 0; mt < 2; mt++)
        #pragma unroll
        for (int nt = 0; nt < 8; nt++)
            #pragma unroll
            for (int i = 0; i < 4; i++) acc[mt][nt][i] = 0.0f;

    gemm_core(g_Ahi[z], g_Alo[z], g_Whi[z], g_Wlo[z], sb, tid, bc, br, acc);

    const int lane = tid & 31, wid = tid >> 5;
    const int warp_m = wid >> 1, warp_n = wid & 1;
    #pragma unroll
    for (int mt = 0; mt < 2; mt++) {
        #pragma unroll
        for (int nt = 0; nt < 8; nt++) {
            const int row0 = br * 64 + warp_m * 32 + mt * 16 + (lane >> 2);
            const int col  = bc * 128 + warp_n * 64 + nt * 8 + (lane & 3) * 2;
            const int h = col >> 6, dd = col & 63;
            #pragma unroll
            for (int half = 0; half < 2; half++) {
                const int r = row0 + half * 8;
                const int b = r >> 11, s = r & 2047;
                const long off = (((((long)b * NHEADS + h) * S_LEN + s) * HDIM) + dd) >> 1;
                if (z == 2) {
                    Chi[off] = packh2(acc[mt][nt][half * 2],
                                      acc[mt][nt][half * 2 + 1]);
                } else {
                    uint32_t hi, lo;
                    split2(acc[mt][nt][half * 2] * scale,
                           acc[mt][nt][half * 2 + 1] * scale, hi, lo);
                    Chi[off] = hi;
                    Clo[off] = lo;
                }
            }
        }
    }
}

// ============================================================================
// Output projection GEMM: fp32 row-major result. grid (8, 128), 128 threads.
// ============================================================================
__global__ void __launch_bounds__(128, 4)
gemm_out(const __nv_bfloat16* __restrict__ Ahi, const __nv_bfloat16* __restrict__ Alo,
         const __nv_bfloat16* __restrict__ Bhi, const __nv_bfloat16* __restrict__ Blo,
         float* __restrict__ Cf)
{
    extern __shared__ char smem[];
    const uint32_t sb = smem_u32(smem);
    const int tid = threadIdx.x;
    const int bc = blockIdx.x, br = blockIdx.y;

    float acc[2][8][4];
    #pragma unroll
    for (int mt = 0; mt < 2; mt++)
        #pragma unroll
        for (int nt = 0; nt < 8; nt++)
            #pragma unroll
            for (int i = 0; i < 4; i++) acc[mt][nt][i] = 0.0f;

    gemm_core(Ahi, Alo, Bhi, Blo, sb, tid, bc, br, acc);

    const int lane = tid & 31, wid = tid >> 5;
    const int warp_m = wid >> 1, warp_n = wid & 1;
    #pragma unroll
    for (int mt = 0; mt < 2; mt++) {
        #pragma unroll
        for (int nt = 0; nt < 8; nt++) {
            const int row0 = br * 64 + warp_m * 32 + mt * 16 + (lane >> 2);
            const int col  = bc * 128 + warp_n * 64 + nt * 8 + (lane & 3) * 2;
            float2 v01; v01.x = acc[mt][nt][0]; v01.y = acc[mt][nt][1];
            float2 v23; v23.x = acc[mt][nt][2]; v23.y = acc[mt][nt][3];
            *(float2*)&Cf[(long)row0 * DMODEL + col] = v01;
            *(float2*)&Cf[(long)(row0 + 8) * DMODEL + col] = v23;
        }
    }
}

// ============================================================================
// Tensor-core causal flash attention.
// QK: bf16 3-term (K frags loaded per-g to cap regs). PV: fp16 SINGLE term.
// K ring 2-stage (hi+lo), V ring 2-stage (single). Q staged through K stage 1.
// smem 55.3KB -> 4 CTAs/SM. grid (32, 64); q-blocks longest-first.
// ============================================================================
#define AROWB    144
#define ARR      (64 * AROWB)            // 9216
#define KSTG     (2 * ARR)               // 18432  one K stage (hi+lo)
#define VOFF     (2 * KSTG)              // 36864  V ring base
#define ASMEM    (VOFF + 2 * ARR)        // 55296

__global__ void __launch_bounds__(128, 4)
attn_mma(const __nv_bfloat16* __restrict__ Qhi, const __nv_bfloat16* __restrict__ Qlo,
         const __nv_bfloat16* __restrict__ Khi, const __nv_bfloat16* __restrict__ Klo,
         const __half* __restrict__ Vh,
         __nv_bfloat16* __restrict__ Ohi, __nv_bfloat16* __restrict__ Olo)
{
    extern __shared__ char smem[];
    const uint32_t sb = smem_u32(smem);
    const int tid = threadIdx.x, wid = tid >> 5, lane = tid & 31;
    const int qblk = (int)gridDim.x - 1 - (int)blockIdx.x;   // longest first
    const int q0 = qblk * 64;
    const int bh = blockIdx.y;
    const long base = (long)bh * S_LEN * HDIM;
    const int ntiles = qblk + 1;

    // hi+lo pair loader (K, Q): 1024 chunks, 8/thread
    auto ld2arr = [&](const void* hi, const void* lo,
                      long grow0, uint32_t smem_base) {
        #pragma unroll
        for (int t = 0; t < 8; t++) {
            const int c = tid + t * 128;
            const int arr = c >> 9, rem = c & 511;
            const int row = rem >> 3, seg = rem & 7;
            const char* src = (const char*)(arr ? lo : hi)
                            + ((base + (grow0 + row) * HDIM + seg * 8) << 1);
            cp_async16(smem_base + arr * ARR + row * AROWB + seg * 16, src);
        }
        cp_commit();
    };
    // single-array loader (V): 512 chunks, 4/thread
    auto ld1arr = [&](const void* p, long grow0, uint32_t smem_base) {
        #pragma unroll
        for (int t = 0; t < 4; t++) {
            const int c = tid + t * 128;
            const int row = c >> 3, seg = c & 7;
            const char* src = (const char*)p
                            + ((base + (grow0 + row) * HDIM + seg * 8) << 1);
            cp_async16(smem_base + row * AROWB + seg * 16, src);
        }
        cp_commit();
    };

    // ---- prologue ----
    ld2arr(Qhi, Qlo, (long)q0, sb + KSTG);                  // GQ -> K stage 1
    ld2arr(Khi, Klo, 0L, sb);                               // K(0) -> K stage 0
    cp_wait<1>();                                           // GQ done
    __syncthreads();

    uint32_t qhF[4][4], qlF[4][4];
    {
        const uint32_t arow = wid * 16 + (lane & 15);
        #pragma unroll
        for (int kt = 0; kt < 4; kt++) {
            const uint32_t off = arow * AROWB + (kt * 16 + (lane >> 4) * 8) * 2;
            ldsm_x4(qhF[kt], sb + KSTG + off);
            ldsm_x4(qlF[kt], sb + KSTG + ARR + off);
        }
    }
    __syncthreads();                                        // Q reads done
    ld1arr(Vh, 0L, sb + VOFF);                              // V(0) -> V stage 0
    {
        const int tk = (1 < ntiles) ? 1 : 0;
        ld2arr(Khi, Klo, (long)tk * 64, sb + KSTG);         // K(1) -> K stage 1
    }

    float m_s[2] = {-1e30f, -1e30f};
    float l_s[2] = {0.0f, 0.0f};
    float acc_o[8][4];
    #pragma unroll
    for (int nt = 0; nt < 8; nt++)
        #pragma unroll
        for (int i = 0; i < 4; i++) acc_o[nt][i] = 0.0f;

    const int wrow_lo = q0 + wid * 16;

    for (int t = 0; t < ntiles; t++) {
        cp_wait<2>();                 // K(t) resident (order: K(t), V(t), K(t+1))
        __syncthreads();              // sync1: K(t) visible; V stage (t+1)&1 free
        {
            const int tv = (t + 1 < ntiles) ? t + 1 : ntiles - 1;
            ld1arr(Vh, (long)tv * 64, sb + VOFF + ((t + 1) & 1) * ARR);
        }

        const uint32_t kbase = sb + (t & 1) * KSTG;
        const uint32_t vbase = sb + VOFF + (t & 1) * ARR;
        const bool act = (t * 64 <= wrow_lo + 15);

        float acc_s[8][4];
        float tmax[2] = {-1e30f, -1e30f};
        bool act2 = false;

        if (act) {
            #pragma unroll
            for (int nt = 0; nt < 8; nt++)
                #pragma unroll
                for (int i = 0; i < 4; i++) acc_s[nt][i] = 0.0f;

            // ---- S = Q @ K^T: K frags loaded per-g (regs capped) ----
            #pragma unroll
            for (int kt = 0; kt < 4; kt++) {
                const uint32_t brow = (lane & 7) + ((lane & 16) >> 1);
                const uint32_t bcol = kt * 16 + ((lane >> 3) & 1) * 8;
                #pragma unroll
                for (int g = 0; g < 4; g++) {
                    uint32_t kh[4], kl[4];
                    const uint32_t off = (g * 16 + brow) * AROWB + bcol * 2;
                    ldsm_x4(kh, kbase + off);
                    ldsm_x4(kl, kbase + ARR + off);
                    mma16816(acc_s[2 * g],     qhF[kt], &kh[0]);
                    mma16816(acc_s[2 * g + 1], qhF[kt], &kh[2]);
                    mma16816(acc_s[2 * g],     qhF[kt], &kl[0]);
                    mma16816(acc_s[2 * g + 1], qhF[kt], &kl[2]);
                    mma16816(acc_s[2 * g],     qlF[kt], &kh[0]);
                    mma16816(acc_s[2 * g + 1], qlF[kt], &kh[2]);
                }
            }

            const int r0 = q0 + wid * 16 + (lane >> 2);
            if (t * 64 + 63 > wrow_lo) {
                #pragma unroll
                for (int nt = 0; nt < 8; nt++)
                    #pragma unroll
                    for (int i = 0; i < 4; i++) {
                        const int row = r0 + (i >> 1) * 8;
                        const int col = t * 64 + nt * 8 + 2 * (lane & 3) + (i & 1);
                        if (col > row) acc_s[nt][i] = -1e30f;
                    }
            }

            #pragma unroll
            for (int nt = 0; nt < 8; nt++)
                #pragma unroll
                for (int i = 0; i < 4; i++)
                    tmax[i >> 1] = fmaxf(tmax[i >> 1], acc_s[nt][i]);
            #pragma unroll
            for (int h = 0; h < 2; h++) {
                tmax[h] = fmaxf(tmax[h], __shfl_xor_sync(0xffffffffu, tmax[h], 1));
                tmax[h] = fmaxf(tmax[h], __shfl_xor_sync(0xffffffffu, tmax[h], 2));
            }
            float d = fmaxf(tmax[0] - m_s[0], tmax[1] - m_s[1]);
            d = fmaxf(d, __shfl_xor_sync(0xffffffffu, d, 4));
            d = fmaxf(d, __shfl_xor_sync(0xffffffffu, d, 8));
            d = fmaxf(d, __shfl_xor_sync(0xffffffffu, d, 16));
            act2 = (d >= -44.0f);
        }

        cp_wait<2>();                 // V(t) resident
        __syncthreads();              // sync2: V(t) visible; K stage t&1 reads done
        {
            const int tk = (t + 2 < ntiles) ? t + 2 : ntiles - 1;
            ld2arr(Khi, Klo, (long)tk * 64, sb + (t & 1) * KSTG);
        }

        if (act && act2) {
            float nm[2], corr[2];
            #pragma unroll
            for (int h = 0; h < 2; h++) {
                nm[h]   = fmaxf(m_s[h], tmax[h]);
                corr[h] = __expf(m_s[h] - nm[h]);
                m_s[h]  = nm[h];
            }
            float psum[2] = {0.0f, 0.0f};
            #pragma unroll
            for (int nt = 0; nt < 8; nt++)
                #pragma unroll
                for (int i = 0; i < 4; i++) {
                    const float p = __expf(acc_s[nt][i] - nm[i >> 1]);
                    acc_s[nt][i] = p;
                    psum[i >> 1] += p;
                }
            #pragma unroll
            for (int h = 0; h < 2; h++) {
                psum[h] += __shfl_xor_sync(0xffffffffu, psum[h], 1);
                psum[h] += __shfl_xor_sync(0xffffffffu, psum[h], 2);
                l_s[h] = l_s[h] * corr[h] + psum[h];
            }
            #pragma unroll
            for (int nt = 0; nt < 8; nt++)
                #pragma unroll
                for (int i = 0; i < 4; i++) acc_o[nt][i] *= corr[i >> 1];

            // ---- pack P as fp16 (C-frag -> A-frag identity) ----
            uint32_t ph[4][4];
            #pragma unroll
            for (int kt = 0; kt < 4; kt++) {
                ph[kt][0] = packh2(acc_s[2 * kt][0],     acc_s[2 * kt][1]);
                ph[kt][1] = packh2(acc_s[2 * kt][2],     acc_s[2 * kt][3]);
                ph[kt][2] = packh2(acc_s[2 * kt + 1][0], acc_s[2 * kt + 1][1]);
                ph[kt][3] = packh2(acc_s[2 * kt + 1][2], acc_s[2 * kt + 1][3]);
            }

            // ---- O += P @ V, fp16 single term, V frags per-g ----
            #pragma unroll
            for (int kt = 0; kt < 4; kt++) {
                const uint32_t vrow = kt * 16 + (lane & 15);
                const uint32_t vcol = (lane >> 4) * 8;
                #pragma unroll
                for (int g = 0; g < 4; g++) {
                    uint32_t vh[4];
                    const uint32_t off = vrow * AROWB + (g * 16 + vcol) * 2;
                    ldsm_x4t(vh, vbase + off);
                    mma16816h(acc_o[2 * g],     ph[kt], &vh[0]);
                    mma16816h(acc_o[2 * g + 1], ph[kt], &vh[2]);
                }
            }
        }
    }

    // ---- epilogue: bf16 hi/lo for the O-projection ----
    const float inv0 = 1.0f / l_s[0];
    const float inv1 = 1.0f / l_s[1];
    const int b  = bh >> 4;
    const int hh = bh & 15;
    const int r0 = q0 + wid * 16 + (lane >> 2);
    #pragma unroll
    for (int nt = 0; nt < 8; nt++) {
        const int col = hh * 64 + nt * 8 + 2 * (lane & 3);
        {
            const long idx = ((long)(b * S_LEN + r0)) * DMODEL + col;
            uint32_t hi, lo;
            split2(acc_o[nt][0] * inv0, acc_o[nt][1] * inv0, hi, lo);
            *(uint32_t*)(Ohi + idx) = hi;
            *(uint32_t*)(Olo + idx) = lo;
        }
        {
            const long idx = ((long)(b * S_LEN + r0 + 8)) * DMODEL + col;
            uint32_t hi, lo;
            split2(acc_o[nt][2] * inv1, acc_o[nt][3] * inv1, hi, lo);
            *(uint32_t*)(Ohi + idx) = hi;
            *(uint32_t*)(Olo + idx) = lo;
        }
    }
}

// ============================================================================
// conversion kernels (fused)
// ============================================================================
__global__ void __launch_bounds__(256)
conv_qkv(const float* __restrict__ q, const float* __restrict__ k,
         const float* __restrict__ v)
{
    const int z = blockIdx.y;
    const float* X = (z == 0) ? q : (z == 1) ? k : v;
    const int i = blockIdx.x * 256 + threadIdx.x;
    const float2 x = ((const float2*)X)[i];
    uint32_t h, l;
    split2(x.x, x.y, h, l);
    ((uint32_t*)g_Ahi[z])[i] = h;
    ((uint32_t*)g_Alo[z])[i] = l;
}

__global__ void __launch_bounds__(256)
conv_w(const float* __restrict__ W0, const float* __restrict__ W1,
       const float* __restrict__ W2, const float* __restrict__ W3)
{
    __shared__ float t[32][33];
    const int z = blockIdx.z;
    const float* W = (z == 0) ? W0 : (z == 1) ? W1 : (z == 2) ? W2 : W3;
    const int tx = threadIdx.x, ty = threadIdx.y;
    const int n0 = blockIdx.x * 32, k0 = blockIdx.y * 32;
    #pragma unroll
    for (int r = 0; r < 4; r++) {
        const int k = ty + r * 8;
        t[k][tx] = W[(long)(k0 + k) * DMODEL + n0 + tx];
    }
    __syncthreads();
    #pragma unroll
    for (int r = 0; r < 4; r++) {
        const int nl = ty + r * 8;
        const float x = t[tx][nl];
        const __nv_bfloat16 h = __float2bfloat16(x);
        const long o = (long)(n0 + nl) * DMODEL + k0 + tx;
        g_Whi[z][o] = h;
        g_Wlo[z][o] = __float2bfloat16(x - __bfloat162float(h));
    }
}

// ============================================================================
extern "C" void kernel_launch(void* const* d_in, const int* in_sizes, int n_in,
                              void* d_out, int out_size)
{
    const float* q = (const float*)d_in[0];
    const float* k = (const float*)d_in[1];
    const float* v = (const float*)d_in[2];
    float* out = (float*)d_out;

    __nv_bfloat16 *whi, *wlo;
    __nv_bfloat16 *qhi, *qlo, *khi, *klo, *ohi, *olo;
    __half *vh;
    cudaGetSymbolAddress((void**)&whi, g_Whi);
    cudaGetSymbolAddress((void**)&wlo, g_Wlo);
    cudaGetSymbolAddress((void**)&qhi, g_Qhi);
    cudaGetSymbolAddress((void**)&qlo, g_Qlo);
    cudaGetSymbolAddress((void**)&khi, g_Khi);
    cudaGetSymbolAddress((void**)&klo, g_Klo);
    cudaGetSymbolAddress((void**)&vh,  g_Vh);
    cudaGetSymbolAddress((void**)&ohi, g_Ohi);
    cudaGetSymbolAddress((void**)&olo, g_Olo);

    cudaFuncSetAttribute((const void*)gemm_qkv,
                         cudaFuncAttributeMaxDynamicSharedMemorySize, GSMEM);
    cudaFuncSetAttribute((const void*)gemm_out,
                         cudaFuncAttributeMaxDynamicSharedMemorySize, GSMEM);
    cudaFuncSetAttribute((const void*)attn_mma,
                         cudaFuncAttributeMaxDynamicSharedMemorySize, ASMEM);

    conv_w<<<dim3(32, 32, 4), dim3(32, 8)>>>(
        (const float*)d_in[3], (const float*)d_in[4],
        (const float*)d_in[5], (const float*)d_in[6]);

    conv_qkv<<<dim3(AELEMS / 2 / 256, 3), 256>>>(q, k, v);

    gemm_qkv<<<dim3(8, 128, 3), 128, GSMEM>>>(qhi, qlo, khi, klo, vh);

    attn_mma<<<dim3(S_LEN / 64, BHCNT), 128, ASMEM>>>(qhi, qlo, khi, klo,
                                                      vh, ohi, olo);

    gemm_out<<<dim3(8, 128), 128, GSMEM>>>(ohi, olo,
        whi + 3 * (long)WELEMS, wlo + 3 * (long)WELEMS, out);
}

// round 13
// speedup vs baseline: 1.2973x; 1.0718x over previous
#include <cuda_runtime.h>
#include <cuda_bf16.h>
#include <cuda_fp16.h>
#include <cstdint>

#define S_LEN   2048
#define DMODEL  1024
#define NHEADS  16
#define HDIM    64
#define BATCH   4
#define BHCNT   (BATCH * NHEADS)                   // 64
#define MROWS   (BATCH * S_LEN)                    // 8192
#define HS_ELEMS (BATCH * NHEADS * S_LEN * HDIM)   // 8388608
#define AELEMS  (MROWS * DMODEL)                   // 8388608
#define WELEMS  (DMODEL * DMODEL)                  // 1048576

// ---- scratch ----
__device__ __nv_bfloat16 g_Ahi[3][AELEMS];
__device__ __nv_bfloat16 g_Alo[3][AELEMS];
__device__ __nv_bfloat16 g_Whi[3][WELEMS];   // Wq,Wk,Wv transposed [N][K], bf16
__device__ __nv_bfloat16 g_Wlo[3][WELEMS];
__device__ __half        g_W4h[WELEMS];      // Wo transposed, fp16 hi/lo
__device__ __half        g_W4l[WELEMS];
__device__ __nv_bfloat16 g_Qhi[HS_ELEMS], g_Qlo[HS_ELEMS];   // bf16, pre-scaled 1/8
__device__ __nv_bfloat16 g_Khi[HS_ELEMS], g_Klo[HS_ELEMS];   // bf16
__device__ __half        g_Vh[HS_ELEMS];                     // fp16 single
__device__ __half        g_Oh[AELEMS];                       // fp16, row-major

// ============================================================================
// helpers (baseline PTX only)
// ============================================================================
__device__ __forceinline__ uint32_t smem_u32(const void* p) {
    uint32_t a;
    asm("{ .reg .u64 t; cvta.to.shared.u64 t, %1; cvt.u32.u64 %0, t; }"
        : "=r"(a) : "l"(p));
    return a;
}
__device__ __forceinline__ void cp_async16(uint32_t dst, const void* src) {
    asm volatile("cp.async.cg.shared.global [%0], [%1], 16;"
                 :: "r"(dst), "l"(src));
}
__device__ __forceinline__ void cp_commit() {
    asm volatile("cp.async.commit_group;");
}
template <int N>
__device__ __forceinline__ void cp_wait() {
    asm volatile("cp.async.wait_group %0;" :: "n"(N));
}
__device__ __forceinline__ void ldsm_x4(uint32_t* r, uint32_t addr) {
    asm volatile("ldmatrix.sync.aligned.m8n8.x4.shared.b16 {%0,%1,%2,%3}, [%4];"
                 : "=r"(r[0]), "=r"(r[1]), "=r"(r[2]), "=r"(r[3]) : "r"(addr));
}
__device__ __forceinline__ void ldsm_x4t(uint32_t* r, uint32_t addr) {
    asm volatile("ldmatrix.sync.aligned.m8n8.x4.trans.shared.b16 {%0,%1,%2,%3}, [%4];"
                 : "=r"(r[0]), "=r"(r[1]), "=r"(r[2]), "=r"(r[3]) : "r"(addr));
}
__device__ __forceinline__ void mma16816(float* d, const uint32_t* a,
                                         const uint32_t* b) {
    asm volatile("mma.sync.aligned.m16n8k16.row.col.f32.bf16.bf16.f32 "
                 "{%0,%1,%2,%3}, {%4,%5,%6,%7}, {%8,%9}, {%0,%1,%2,%3};"
                 : "+f"(d[0]), "+f"(d[1]), "+f"(d[2]), "+f"(d[3])
                 : "r"(a[0]), "r"(a[1]), "r"(a[2]), "r"(a[3]),
                   "r"(b[0]), "r"(b[1]));
}
__device__ __forceinline__ void mma16816h(float* d, const uint32_t* a,
                                          const uint32_t* b) {
    asm volatile("mma.sync.aligned.m16n8k16.row.col.f32.f16.f16.f32 "
                 "{%0,%1,%2,%3}, {%4,%5,%6,%7}, {%8,%9}, {%0,%1,%2,%3};"
                 : "+f"(d[0]), "+f"(d[1]), "+f"(d[2]), "+f"(d[3])
                 : "r"(a[0]), "r"(a[1]), "r"(a[2]), "r"(a[3]),
                   "r"(b[0]), "r"(b[1]));
}
// packed bf16 split
__device__ __forceinline__ void split2(float a, float b,
                                       uint32_t& hi, uint32_t& lo) {
    uint32_t h;
    asm("cvt.rn.bf16x2.f32 %0, %1, %2;" : "=r"(h) : "f"(b), "f"(a));
    const float fa = __uint_as_float(h << 16);
    const float fb = __uint_as_float(h & 0xFFFF0000u);
    uint32_t l;
    asm("cvt.rn.bf16x2.f32 %0, %1, %2;" : "=r"(l) : "f"(b - fb), "f"(a - fa));
    hi = h; lo = l;
}
// single fp16x2 pack
__device__ __forceinline__ uint32_t packh2(float a, float b) {
    uint32_t h;
    asm("cvt.rn.f16x2.f32 %0, %1, %2;" : "=r"(h) : "f"(b), "f"(a));
    return h;
}

#define GA_BYTES   (64 * 64)                 // 4096
#define GB_BYTES   (128 * 64)                // 8192
#define STG_BYTES  (2 * GA_BYTES + 2 * GB_BYTES)  // 24576
#define GSMEM      (2 * STG_BYTES)           // 49152

__device__ __forceinline__ uint32_t swz64(uint32_t row, uint32_t seg) {
    return row * 64 + ((seg ^ (row & 3)) * 16);
}

// ============================================================================
// bf16 3-term GEMM core (QKV projections): tile 64x128, BK=32, 4 warps,
// 2-stage cp.async, XOR-swizzled. 48KB/CTA -> 4 CTAs/SM.
// ============================================================================
__device__ __forceinline__ void gemm_core(
    const __nv_bfloat16* __restrict__ Ahi, const __nv_bfloat16* __restrict__ Alo,
    const __nv_bfloat16* __restrict__ Bhi, const __nv_bfloat16* __restrict__ Blo,
    uint32_t sb, int tid, int bc, int br, float acc[2][8][4])
{
    const int lane   = tid & 31;
    const int wid    = tid >> 5;
    const int warp_m = wid >> 1;
    const int warp_n = wid & 1;

    auto issue = [&](int kc, int stage) {
        #pragma unroll
        for (int t = 0; t < 12; t++) {
            const int c = tid + t * 128;
            uint32_t dst;
            const __nv_bfloat16* g;
            if (c < 512) {
                const int arr = c >> 8, rem = c & 255;
                const int row = rem >> 2, seg = rem & 3;
                g = (arr ? Alo : Ahi) + (long)(br * 64 + row) * DMODEL
                  + kc * 32 + seg * 8;
                dst = sb + stage * STG_BYTES + arr * GA_BYTES + swz64(row, seg);
            } else {
                const int cb = c - 512;
                const int arr = cb >> 9, rem = cb & 511;
                const int row = rem >> 2, seg = rem & 3;
                g = (arr ? Blo : Bhi) + (long)(bc * 128 + row) * DMODEL
                  + kc * 32 + seg * 8;
                dst = sb + stage * STG_BYTES + 2 * GA_BYTES + arr * GB_BYTES
                    + swz64(row, seg);
            }
            cp_async16(dst, g);
        }
        cp_commit();
    };

    issue(0, 0);

    const int NKC = DMODEL / 32;
    for (int kc = 0; kc < NKC; kc++) {
        cp_wait<0>();
        __syncthreads();
        if (kc + 1 < NKC) issue(kc + 1, (kc + 1) & 1);

        const uint32_t base = sb + (kc & 1) * STG_BYTES;

        #pragma unroll
        for (int kk = 0; kk < 2; kk++) {
            uint32_t ahi[2][4], alo[2][4];
            {
                const uint32_t ar0  = warp_m * 32 + (lane & 15);
                const uint32_t aseg = kk * 2 + (lane >> 4);
                ldsm_x4(ahi[0], base + swz64(ar0, aseg));
                ldsm_x4(ahi[1], base + swz64(ar0 + 16, aseg));
                ldsm_x4(alo[0], base + GA_BYTES + swz64(ar0, aseg));
                ldsm_x4(alo[1], base + GA_BYTES + swz64(ar0 + 16, aseg));
            }
            const uint32_t br0  = warp_n * 64 + (lane & 7) + ((lane & 16) >> 1);
            const uint32_t bseg = kk * 2 + ((lane >> 3) & 1);
            #pragma unroll
            for (int q = 0; q < 4; q++) {
                uint32_t bhi[4], blo[4];
                const uint32_t brow = br0 + q * 16;
                ldsm_x4(bhi, base + 2 * GA_BYTES + swz64(brow, bseg));
                ldsm_x4(blo, base + 2 * GA_BYTES + GB_BYTES + swz64(brow, bseg));
                #pragma unroll
                for (int mt = 0; mt < 2; mt++)
                    #pragma unroll
                    for (int n2 = 0; n2 < 2; n2++)
                        mma16816(acc[mt][2 * q + n2], ahi[mt], &bhi[n2 * 2]);
                #pragma unroll
                for (int mt = 0; mt < 2; mt++)
                    #pragma unroll
                    for (int n2 = 0; n2 < 2; n2++)
                        mma16816(acc[mt][2 * q + n2], ahi[mt], &blo[n2 * 2]);
                #pragma unroll
                for (int mt = 0; mt < 2; mt++)
                    #pragma unroll
                    for (int n2 = 0; n2 < 2; n2++)
                        mma16816(acc[mt][2 * q + n2], alo[mt], &bhi[n2 * 2]);
            }
        }
    }
}

// ============================================================================
// Batched QKV projection GEMM: grid (8, 128, 3), 128 threads, 4 CTAs/SM.
// ============================================================================
__global__ void __launch_bounds__(128, 4)
gemm_qkv(__nv_bfloat16* __restrict__ Qhi, __nv_bfloat16* __restrict__ Qlo,
         __nv_bfloat16* __restrict__ Khi, __nv_bfloat16* __restrict__ Klo,
         __half* __restrict__ Vh)
{
    extern __shared__ char smem[];
    const uint32_t sb = smem_u32(smem);
    const int tid = threadIdx.x;
    const int bc = blockIdx.x, br = blockIdx.y, z = blockIdx.z;

    uint32_t *Chi, *Clo;
    float scale;
    if (z == 0)      { Chi = (uint32_t*)Qhi; Clo = (uint32_t*)Qlo; scale = 0.125f; }
    else if (z == 1) { Chi = (uint32_t*)Khi; Clo = (uint32_t*)Klo; scale = 1.0f; }
    else             { Chi = (uint32_t*)Vh;  Clo = nullptr;        scale = 1.0f; }

    float acc[2][8][4];
    #pragma unroll
    for (int mt = 0; mt < 2; mt++)
        #pragma unroll
        for (int nt = 0; nt < 8; nt++)
            #pragma unroll
            for (int i = 0; i < 4; i++) acc[mt][nt][i] = 0.0f;

    gemm_core(g_Ahi[z], g_Alo[z], g_Whi[z], g_Wlo[z], sb, tid, bc, br, acc);

    const int lane = tid & 31, wid = tid >> 5;
    const int warp_m = wid >> 1, warp_n = wid & 1;
    #pragma unroll
    for (int mt = 0; mt < 2; mt++) {
        #pragma unroll
        for (int nt = 0; nt < 8; nt++) {
            const int row0 = br * 64 + warp_m * 32 + mt * 16 + (lane >> 2);
            const int col  = bc * 128 + warp_n * 64 + nt * 8 + (lane & 3) * 2;
            const int h = col >> 6, dd = col & 63;
            #pragma unroll
            for (int half = 0; half < 2; half++) {
                const int r = row0 + half * 8;
                const int b = r >> 11, s = r & 2047;
                const long off = (((((long)b * NHEADS + h) * S_LEN + s) * HDIM) + dd) >> 1;
                if (z == 2) {
                    Chi[off] = packh2(acc[mt][nt][half * 2],
                                      acc[mt][nt][half * 2 + 1]);
                } else {
                    uint32_t hi, lo;
                    split2(acc[mt][nt][half * 2] * scale,
                           acc[mt][nt][half * 2 + 1] * scale, hi, lo);
                    Chi[off] = hi;
                    Clo[off] = lo;
                }
            }
        }
    }
}

// ============================================================================
// Output projection GEMM: fp16 2-term (A single fp16, W fp16 hi/lo).
// grid (8, 128), 128 threads, 2-stage, 40KB/CTA.
// ============================================================================
#define OSTG   (GA_BYTES + 2 * GB_BYTES)    // 20480
#define OSMEM  (2 * OSTG)                   // 40960

__global__ void __launch_bounds__(128, 4)
gemm_out(const __half* __restrict__ Ah,
         const __half* __restrict__ Whi, const __half* __restrict__ Wlo,
         float* __restrict__ Cf)
{
    extern __shared__ char smem[];
    const uint32_t sb = smem_u32(smem);
    const int tid = threadIdx.x;
    const int bc = blockIdx.x, br = blockIdx.y;
    const int lane = tid & 31, wid = tid >> 5;
    const int warp_m = wid >> 1, warp_n = wid & 1;

    float acc[2][8][4];
    #pragma unroll
    for (int mt = 0; mt < 2; mt++)
        #pragma unroll
        for (int nt = 0; nt < 8; nt++)
            #pragma unroll
            for (int i = 0; i < 4; i++) acc[mt][nt][i] = 0.0f;

    auto issue = [&](int kc, int stage) {
        #pragma unroll
        for (int t = 0; t < 10; t++) {
            const int c = tid + t * 128;      // 0..1279
            uint32_t dst;
            const __half* g;
            if (c < 256) {
                const int row = c >> 2, seg = c & 3;
                g = Ah + (long)(br * 64 + row) * DMODEL + kc * 32 + seg * 8;
                dst = sb + stage * OSTG + swz64(row, seg);
            } else {
                const int cb = c - 256;
                const int arr = cb >> 9, rem = cb & 511;
                const int row = rem >> 2, seg = rem & 3;
                g = (arr ? Wlo : Whi) + (long)(bc * 128 + row) * DMODEL
                  + kc * 32 + seg * 8;
                dst = sb + stage * OSTG + GA_BYTES + arr * GB_BYTES
                    + swz64(row, seg);
            }
            cp_async16(dst, g);
        }
        cp_commit();
    };

    issue(0, 0);

    const int NKC = DMODEL / 32;
    for (int kc = 0; kc < NKC; kc++) {
        cp_wait<0>();
        __syncthreads();
        if (kc + 1 < NKC) issue(kc + 1, (kc + 1) & 1);

        const uint32_t base = sb + (kc & 1) * OSTG;

        #pragma unroll
        for (int kk = 0; kk < 2; kk++) {
            uint32_t ah[2][4];
            {
                const uint32_t ar0  = warp_m * 32 + (lane & 15);
                const uint32_t aseg = kk * 2 + (lane >> 4);
                ldsm_x4(ah[0], base + swz64(ar0, aseg));
                ldsm_x4(ah[1], base + swz64(ar0 + 16, aseg));
            }
            const uint32_t br0  = warp_n * 64 + (lane & 7) + ((lane & 16) >> 1);
            const uint32_t bseg = kk * 2 + ((lane >> 3) & 1);
            #pragma unroll
            for (int q = 0; q < 4; q++) {
                uint32_t bhi[4], blo[4];
                const uint32_t brow = br0 + q * 16;
                ldsm_x4(bhi, base + GA_BYTES + swz64(brow, bseg));
                ldsm_x4(blo, base + GA_BYTES + GB_BYTES + swz64(brow, bseg));
                #pragma unroll
                for (int mt = 0; mt < 2; mt++)
                    #pragma unroll
                    for (int n2 = 0; n2 < 2; n2++)
                        mma16816h(acc[mt][2 * q + n2], ah[mt], &bhi[n2 * 2]);
                #pragma unroll
                for (int mt = 0; mt < 2; mt++)
                    #pragma unroll
                    for (int n2 = 0; n2 < 2; n2++)
                        mma16816h(acc[mt][2 * q + n2], ah[mt], &blo[n2 * 2]);
            }
        }
    }

    #pragma unroll
    for (int mt = 0; mt < 2; mt++) {
        #pragma unroll
        for (int nt = 0; nt < 8; nt++) {
            const int row0 = br * 64 + warp_m * 32 + mt * 16 + (lane >> 2);
            const int col  = bc * 128 + warp_n * 64 + nt * 8 + (lane & 3) * 2;
            float2 v01; v01.x = acc[mt][nt][0]; v01.y = acc[mt][nt][1];
            float2 v23; v23.x = acc[mt][nt][2]; v23.y = acc[mt][nt][3];
            *(float2*)&Cf[(long)row0 * DMODEL + col] = v01;
            *(float2*)&Cf[(long)(row0 + 8) * DMODEL + col] = v23;
        }
    }
}

// ============================================================================
// Tensor-core causal flash attention.
// QK: bf16 3-term. PV: fp16 single. Merged KV stage (Khi+Klo+V), 2-stage ring,
// ONE wait + ONE sync per tile. Q staged through stage 1. 55.3KB -> 4 CTAs/SM.
// ============================================================================
#define AROWB    144
#define ARR      (64 * AROWB)            // 9216
#define KVSTG    (3 * ARR)               // 27648: Khi, Klo, V
#define ASMEM    (2 * KVSTG)             // 55296

__global__ void __launch_bounds__(128, 4)
attn_mma(const __nv_bfloat16* __restrict__ Qhi, const __nv_bfloat16* __restrict__ Qlo,
         const __nv_bfloat16* __restrict__ Khi, const __nv_bfloat16* __restrict__ Klo,
         const __half* __restrict__ Vh,
         __half* __restrict__ Oh)
{
    extern __shared__ char smem[];
    const uint32_t sb = smem_u32(smem);
    const int tid = threadIdx.x, wid = tid >> 5, lane = tid & 31;
    const int qblk = (int)gridDim.x - 1 - (int)blockIdx.x;   // longest first
    const int q0 = qblk * 64;
    const int bh = blockIdx.y;
    const long base = (long)bh * S_LEN * HDIM;
    const int ntiles = qblk + 1;

    // Q loader (hi+lo): 1024 chunks, 8/thread
    auto ldq = [&](uint32_t smem_base) {
        #pragma unroll
        for (int t = 0; t < 8; t++) {
            const int c = tid + t * 128;
            const int arr = c >> 9, rem = c & 511;
            const int row = rem >> 3, seg = rem & 7;
            const char* src = (const char*)(arr ? Qlo : Qhi)
                            + ((base + ((long)q0 + row) * HDIM + seg * 8) << 1);
            cp_async16(smem_base + arr * ARR + row * AROWB + seg * 16, src);
        }
        cp_commit();
    };
    // merged KV loader: Khi, Klo, V = 1536 chunks, 12/thread
    auto ldkv = [&](int t, int stage) {
        const long grow0 = (long)t * 64;
        #pragma unroll
        for (int i = 0; i < 12; i++) {
            const int c = tid + i * 128;
            const int arr = c >> 9, rem = c & 511;
            const int row = rem >> 3, seg = rem & 7;
            const char* p;
            if (arr == 0)      p = (const char*)Khi;
            else if (arr == 1) p = (const char*)Klo;
            else               p = (const char*)Vh;
            cp_async16(sb + stage * KVSTG + arr * ARR + row * AROWB + seg * 16,
                       p + ((base + (grow0 + row) * HDIM + seg * 8) << 1));
        }
        cp_commit();
    };

    // ---- prologue ----
    ldq(sb + KVSTG);                 // Q -> stage 1 (Khi/Klo slots)
    ldkv(0, 0);                      // KV(0) -> stage 0
    cp_wait<1>();                    // Q done
    __syncthreads();

    uint32_t qhF[4][4], qlF[4][4];
    {
        const uint32_t arow = wid * 16 + (lane & 15);
        #pragma unroll
        for (int kt = 0; kt < 4; kt++) {
            const uint32_t off = arow * AROWB + (kt * 16 + (lane >> 4) * 8) * 2;
            ldsm_x4(qhF[kt], sb + KVSTG + off);
            ldsm_x4(qlF[kt], sb + KVSTG + ARR + off);
        }
    }

    float m_s[2] = {-1e30f, -1e30f};
    float l_s[2] = {0.0f, 0.0f};
    float acc_o[8][4];
    #pragma unroll
    for (int nt = 0; nt < 8; nt++)
        #pragma unroll
        for (int i = 0; i < 4; i++) acc_o[nt][i] = 0.0f;

    const int wrow_lo = q0 + wid * 16;

    for (int t = 0; t < ntiles; t++) {
        cp_wait<0>();                 // KV(t) resident
        __syncthreads();              // stage (t+1)&1 readers done (incl. Q frags)
        if (t + 1 < ntiles) ldkv(t + 1, (t + 1) & 1);

        const uint32_t kbase = sb + (t & 1) * KVSTG;
        const uint32_t vbase = kbase + 2 * ARR;
        const bool act = (t * 64 <= wrow_lo + 15);

        float acc_s[8][4];
        float tmax[2] = {-1e30f, -1e30f};
        bool act2 = false;

        if (act) {
            #pragma unroll
            for (int nt = 0; nt < 8; nt++)
                #pragma unroll
                for (int i = 0; i < 4; i++) acc_s[nt][i] = 0.0f;

            #pragma unroll
            for (int kt = 0; kt < 4; kt++) {
                const uint32_t brow = (lane & 7) + ((lane & 16) >> 1);
                const uint32_t bcol = kt * 16 + ((lane >> 3) & 1) * 8;
                #pragma unroll
                for (int g = 0; g < 4; g++) {
                    uint32_t kh[4], kl[4];
                    const uint32_t off = (g * 16 + brow) * AROWB + bcol * 2;
                    ldsm_x4(kh, kbase + off);
                    ldsm_x4(kl, kbase + ARR + off);
                    mma16816(acc_s[2 * g],     qhF[kt], &kh[0]);
                    mma16816(acc_s[2 * g + 1], qhF[kt], &kh[2]);
                    mma16816(acc_s[2 * g],     qhF[kt], &kl[0]);
                    mma16816(acc_s[2 * g + 1], qhF[kt], &kl[2]);
                    mma16816(acc_s[2 * g],     qlF[kt], &kh[0]);
                    mma16816(acc_s[2 * g + 1], qlF[kt], &kh[2]);
                }
            }

            const int r0 = q0 + wid * 16 + (lane >> 2);
            if (t * 64 + 63 > wrow_lo) {
                #pragma unroll
                for (int nt = 0; nt < 8; nt++)
                    #pragma unroll
                    for (int i = 0; i < 4; i++) {
                        const int row = r0 + (i >> 1) * 8;
                        const int col = t * 64 + nt * 8 + 2 * (lane & 3) + (i & 1);
                        if (col > row) acc_s[nt][i] = -1e30f;
                    }
            }

            #pragma unroll
            for (int nt = 0; nt < 8; nt++)
                #pragma unroll
                for (int i = 0; i < 4; i++)
                    tmax[i >> 1] = fmaxf(tmax[i >> 1], acc_s[nt][i]);
            #pragma unroll
            for (int h = 0; h < 2; h++) {
                tmax[h] = fmaxf(tmax[h], __shfl_xor_sync(0xffffffffu, tmax[h], 1));
                tmax[h] = fmaxf(tmax[h], __shfl_xor_sync(0xffffffffu, tmax[h], 2));
            }
            float d = fmaxf(tmax[0] - m_s[0], tmax[1] - m_s[1]);
            d = fmaxf(d, __shfl_xor_sync(0xffffffffu, d, 4));
            d = fmaxf(d, __shfl_xor_sync(0xffffffffu, d, 8));
            d = fmaxf(d, __shfl_xor_sync(0xffffffffu, d, 16));
            act2 = (d >= -44.0f);
        }

        if (act && act2) {
            float nm[2], corr[2];
            #pragma unroll
            for (int h = 0; h < 2; h++) {
                nm[h]   = fmaxf(m_s[h], tmax[h]);
                corr[h] = __expf(m_s[h] - nm[h]);
                m_s[h]  = nm[h];
            }
            float psum[2] = {0.0f, 0.0f};
            #pragma unroll
            for (int nt = 0; nt < 8; nt++)
                #pragma unroll
                for (int i = 0; i < 4; i++) {
                    const float p = __expf(acc_s[nt][i] - nm[i >> 1]);
                    acc_s[nt][i] = p;
                    psum[i >> 1] += p;
                }
            #pragma unroll
            for (int h = 0; h < 2; h++) {
                psum[h] += __shfl_xor_sync(0xffffffffu, psum[h], 1);
                psum[h] += __shfl_xor_sync(0xffffffffu, psum[h], 2);
                l_s[h] = l_s[h] * corr[h] + psum[h];
            }
            #pragma unroll
            for (int nt = 0; nt < 8; nt++)
                #pragma unroll
                for (int i = 0; i < 4; i++) acc_o[nt][i] *= corr[i >> 1];

            uint32_t ph[4][4];
            #pragma unroll
            for (int kt = 0; kt < 4; kt++) {
                ph[kt][0] = packh2(acc_s[2 * kt][0],     acc_s[2 * kt][1]);
                ph[kt][1] = packh2(acc_s[2 * kt][2],     acc_s[2 * kt][3]);
                ph[kt][2] = packh2(acc_s[2 * kt + 1][0], acc_s[2 * kt + 1][1]);
                ph[kt][3] = packh2(acc_s[2 * kt + 1][2], acc_s[2 * kt + 1][3]);
            }

            #pragma unroll
            for (int kt = 0; kt < 4; kt++) {
                const uint32_t vrow = kt * 16 + (lane & 15);
                const uint32_t vcol = (lane >> 4) * 8;
                #pragma unroll
                for (int g = 0; g < 4; g++) {
                    uint32_t vh[4];
                    const uint32_t off = vrow * AROWB + (g * 16 + vcol) * 2;
                    ldsm_x4t(vh, vbase + off);
                    mma16816h(acc_o[2 * g],     ph[kt], &vh[0]);
                    mma16816h(acc_o[2 * g + 1], ph[kt], &vh[2]);
                }
            }
        }
    }

    // ---- epilogue: single fp16 O ----
    const float inv0 = 1.0f / l_s[0];
    const float inv1 = 1.0f / l_s[1];
    const int b  = bh >> 4;
    const int hh = bh & 15;
    const int r0 = q0 + wid * 16 + (lane >> 2);
    #pragma unroll
    for (int nt = 0; nt < 8; nt++) {
        const int col = hh * 64 + nt * 8 + 2 * (lane & 3);
        {
            const long idx = ((long)(b * S_LEN + r0)) * DMODEL + col;
            *(uint32_t*)(Oh + idx) = packh2(acc_o[nt][0] * inv0,
                                            acc_o[nt][1] * inv0);
        }
        {
            const long idx = ((long)(b * S_LEN + r0 + 8)) * DMODEL + col;
            *(uint32_t*)(Oh + idx) = packh2(acc_o[nt][2] * inv1,
                                            acc_o[nt][3] * inv1);
        }
    }
}

// ============================================================================
// conversion kernels
// ============================================================================
__global__ void __launch_bounds__(256)
conv_qkv(const float* __restrict__ q, const float* __restrict__ k,
         const float* __restrict__ v)
{
    const int z = blockIdx.y;
    const float* X = (z == 0) ? q : (z == 1) ? k : v;
    const int i = blockIdx.x * 256 + threadIdx.x;
    const float2 x = ((const float2*)X)[i];
    uint32_t h, l;
    split2(x.x, x.y, h, l);
    ((uint32_t*)g_Ahi[z])[i] = h;
    ((uint32_t*)g_Alo[z])[i] = l;
}

__global__ void __launch_bounds__(256)
conv_w(const float* __restrict__ W0, const float* __restrict__ W1,
       const float* __restrict__ W2, const float* __restrict__ W3)
{
    __shared__ float t[32][33];
    const int z = blockIdx.z;
    const float* W = (z == 0) ? W0 : (z == 1) ? W1 : (z == 2) ? W2 : W3;
    const int tx = threadIdx.x, ty = threadIdx.y;
    const int n0 = blockIdx.x * 32, k0 = blockIdx.y * 32;
    #pragma unroll
    for (int r = 0; r < 4; r++) {
        const int k = ty + r * 8;
        t[k][tx] = W[(long)(k0 + k) * DMODEL + n0 + tx];
    }
    __syncthreads();
    #pragma unroll
    for (int r = 0; r < 4; r++) {
        const int nl = ty + r * 8;
        const float x = t[tx][nl];
        const long o = (long)(n0 + nl) * DMODEL + k0 + tx;
        if (z < 3) {
            const __nv_bfloat16 h = __float2bfloat16(x);
            g_Whi[z][o] = h;
            g_Wlo[z][o] = __float2bfloat16(x - __bfloat162float(h));
        } else {
            const __half h = __float2half_rn(x);
            g_W4h[o] = h;
            g_W4l[o] = __float2half_rn(x - __half2float(h));
        }
    }
}

// ============================================================================
extern "C" void kernel_launch(void* const* d_in, const int* in_sizes, int n_in,
                              void* d_out, int out_size)
{
    const float* q = (const float*)d_in[0];
    const float* k = (const float*)d_in[1];
    const float* v = (const float*)d_in[2];
    float* out = (float*)d_out;

    __nv_bfloat16 *qhi, *qlo, *khi, *klo;
    __half *vh, *oh, *w4h, *w4l;
    cudaGetSymbolAddress((void**)&qhi, g_Qhi);
    cudaGetSymbolAddress((void**)&qlo, g_Qlo);
    cudaGetSymbolAddress((void**)&khi, g_Khi);
    cudaGetSymbolAddress((void**)&klo, g_Klo);
    cudaGetSymbolAddress((void**)&vh,  g_Vh);
    cudaGetSymbolAddress((void**)&oh,  g_Oh);
    cudaGetSymbolAddress((void**)&w4h, g_W4h);
    cudaGetSymbolAddress((void**)&w4l, g_W4l);

    cudaFuncSetAttribute((const void*)gemm_qkv,
                         cudaFuncAttributeMaxDynamicSharedMemorySize, GSMEM);
    cudaFuncSetAttribute((const void*)gemm_out,
                         cudaFuncAttributeMaxDynamicSharedMemorySize, OSMEM);
    cudaFuncSetAttribute((const void*)attn_mma,
                         cudaFuncAttributeMaxDynamicSharedMemorySize, ASMEM);

    conv_w<<<dim3(32, 32, 4), dim3(32, 8)>>>(
        (const float*)d_in[3], (const float*)d_in[4],
        (const float*)d_in[5], (const float*)d_in[6]);

    conv_qkv<<<dim3(AELEMS / 2 / 256, 3), 256>>>(q, k, v);

    gemm_qkv<<<dim3(8, 128, 3), 128, GSMEM>>>(qhi, qlo, khi, klo, vh);

    attn_mma<<<dim3(S_LEN / 64, BHCNT), 128, ASMEM>>>(qhi, qlo, khi, klo,
                                                      vh, oh);

    gemm_out<<<dim3(8, 128), 128, OSMEM>>>(oh, w4h, w4l, out);
}

// round 14
// speedup vs baseline: 1.3052x; 1.0061x over previous
#include <cuda_runtime.h>
#include <cuda_bf16.h>
#include <cuda_fp16.h>
#include <cstdint>

#define S_LEN   2048
#define DMODEL  1024
#define NHEADS  16
#define HDIM    64
#define BATCH   4
#define BHCNT   (BATCH * NHEADS)                   // 64
#define MROWS   (BATCH * S_LEN)                    // 8192
#define HS_ELEMS (BATCH * NHEADS * S_LEN * HDIM)   // 8388608
#define AELEMS  (MROWS * DMODEL)                   // 8388608
#define WELEMS  (DMODEL * DMODEL)                  // 1048576

// ---- scratch ----
__device__ __nv_bfloat16 g_Ahi[2][AELEMS];   // q,k inputs bf16 hi/lo
__device__ __nv_bfloat16 g_Alo[2][AELEMS];
__device__ __half        g_Avh[AELEMS];      // v input, fp16 single
__device__ __nv_bfloat16 g_Whi[2][WELEMS];   // Wq,Wk transposed [N][K], bf16
__device__ __nv_bfloat16 g_Wlo[2][WELEMS];
__device__ __half        g_Wvh[WELEMS];      // Wv transposed, fp16 hi/lo
__device__ __half        g_Wvl[WELEMS];
__device__ __half        g_W4h[WELEMS];      // Wo transposed, fp16 hi/lo
__device__ __half        g_W4l[WELEMS];
__device__ __nv_bfloat16 g_Qhi[HS_ELEMS], g_Qlo[HS_ELEMS];   // bf16, pre-scaled 1/8
__device__ __nv_bfloat16 g_Khi[HS_ELEMS], g_Klo[HS_ELEMS];   // bf16
__device__ __half        g_Vh[HS_ELEMS];                     // fp16 single
__device__ __half        g_Oh[AELEMS];                       // fp16, row-major

// ============================================================================
// helpers (baseline PTX only)
// ============================================================================
__device__ __forceinline__ uint32_t smem_u32(const void* p) {
    uint32_t a;
    asm("{ .reg .u64 t; cvta.to.shared.u64 t, %1; cvt.u32.u64 %0, t; }"
        : "=r"(a) : "l"(p));
    return a;
}
__device__ __forceinline__ void cp_async16(uint32_t dst, const void* src) {
    asm volatile("cp.async.cg.shared.global [%0], [%1], 16;"
                 :: "r"(dst), "l"(src));
}
__device__ __forceinline__ void cp_commit() {
    asm volatile("cp.async.commit_group;");
}
template <int N>
__device__ __forceinline__ void cp_wait() {
    asm volatile("cp.async.wait_group %0;" :: "n"(N));
}
__device__ __forceinline__ void ldsm_x4(uint32_t* r, uint32_t addr) {
    asm volatile("ldmatrix.sync.aligned.m8n8.x4.shared.b16 {%0,%1,%2,%3}, [%4];"
                 : "=r"(r[0]), "=r"(r[1]), "=r"(r[2]), "=r"(r[3]) : "r"(addr));
}
__device__ __forceinline__ void ldsm_x4t(uint32_t* r, uint32_t addr) {
    asm volatile("ldmatrix.sync.aligned.m8n8.x4.trans.shared.b16 {%0,%1,%2,%3}, [%4];"
                 : "=r"(r[0]), "=r"(r[1]), "=r"(r[2]), "=r"(r[3]) : "r"(addr));
}
__device__ __forceinline__ void mma16816(float* d, const uint32_t* a,
                                         const uint32_t* b) {
    asm volatile("mma.sync.aligned.m16n8k16.row.col.f32.bf16.bf16.f32 "
                 "{%0,%1,%2,%3}, {%4,%5,%6,%7}, {%8,%9}, {%0,%1,%2,%3};"
                 : "+f"(d[0]), "+f"(d[1]), "+f"(d[2]), "+f"(d[3])
                 : "r"(a[0]), "r"(a[1]), "r"(a[2]), "r"(a[3]),
                   "r"(b[0]), "r"(b[1]));
}
__device__ __forceinline__ void mma16816h(float* d, const uint32_t* a,
                                          const uint32_t* b) {
    asm volatile("mma.sync.aligned.m16n8k16.row.col.f32.f16.f16.f32 "
                 "{%0,%1,%2,%3}, {%4,%5,%6,%7}, {%8,%9}, {%0,%1,%2,%3};"
                 : "+f"(d[0]), "+f"(d[1]), "+f"(d[2]), "+f"(d[3])
                 : "r"(a[0]), "r"(a[1]), "r"(a[2]), "r"(a[3]),
                   "r"(b[0]), "r"(b[1]));
}
__device__ __forceinline__ void split2(float a, float b,
                                       uint32_t& hi, uint32_t& lo) {
    uint32_t h;
    asm("cvt.rn.bf16x2.f32 %0, %1, %2;" : "=r"(h) : "f"(b), "f"(a));
    const float fa = __uint_as_float(h << 16);
    const float fb = __uint_as_float(h & 0xFFFF0000u);
    uint32_t l;
    asm("cvt.rn.bf16x2.f32 %0, %1, %2;" : "=r"(l) : "f"(b - fb), "f"(a - fa));
    hi = h; lo = l;
}
__device__ __forceinline__ uint32_t packh2(float a, float b) {
    uint32_t h;
    asm("cvt.rn.f16x2.f32 %0, %1, %2;" : "=r"(h) : "f"(b), "f"(a));
    return h;
}

#define GA_BYTES   (64 * 64)                 // 4096
#define GB_BYTES   (128 * 64)                // 8192
#define STG_BYTES  (2 * GA_BYTES + 2 * GB_BYTES)  // 24576
#define GSMEM      (2 * STG_BYTES)           // 49152

__device__ __forceinline__ uint32_t swz64(uint32_t row, uint32_t seg) {
    return row * 64 + ((seg ^ (row & 3)) * 16);
}

// ============================================================================
// bf16 3-term GEMM core (Q,K projections): tile 64x128, BK=32, 4 warps,
// 2-stage cp.async, XOR-swizzled. 48KB/CTA -> 4 CTAs/SM.
// ============================================================================
__device__ __forceinline__ void gemm_core(
    const __nv_bfloat16* __restrict__ Ahi, const __nv_bfloat16* __restrict__ Alo,
    const __nv_bfloat16* __restrict__ Bhi, const __nv_bfloat16* __restrict__ Blo,
    uint32_t sb, int tid, int bc, int br, float acc[2][8][4])
{
    const int lane   = tid & 31;
    const int wid    = tid >> 5;
    const int warp_m = wid >> 1;
    const int warp_n = wid & 1;

    auto issue = [&](int kc, int stage) {
        #pragma unroll
        for (int t = 0; t < 12; t++) {
            const int c = tid + t * 128;
            uint32_t dst;
            const __nv_bfloat16* g;
            if (c < 512) {
                const int arr = c >> 8, rem = c & 255;
                const int row = rem >> 2, seg = rem & 3;
                g = (arr ? Alo : Ahi) + (long)(br * 64 + row) * DMODEL
                  + kc * 32 + seg * 8;
                dst = sb + stage * STG_BYTES + arr * GA_BYTES + swz64(row, seg);
            } else {
                const int cb = c - 512;
                const int arr = cb >> 9, rem = cb & 511;
                const int row = rem >> 2, seg = rem & 3;
                g = (arr ? Blo : Bhi) + (long)(bc * 128 + row) * DMODEL
                  + kc * 32 + seg * 8;
                dst = sb + stage * STG_BYTES + 2 * GA_BYTES + arr * GB_BYTES
                    + swz64(row, seg);
            }
            cp_async16(dst, g);
        }
        cp_commit();
    };

    issue(0, 0);

    const int NKC = DMODEL / 32;
    for (int kc = 0; kc < NKC; kc++) {
        cp_wait<0>();
        __syncthreads();
        if (kc + 1 < NKC) issue(kc + 1, (kc + 1) & 1);

        const uint32_t base = sb + (kc & 1) * STG_BYTES;

        #pragma unroll
        for (int kk = 0; kk < 2; kk++) {
            uint32_t ahi[2][4], alo[2][4];
            {
                const uint32_t ar0  = warp_m * 32 + (lane & 15);
                const uint32_t aseg = kk * 2 + (lane >> 4);
                ldsm_x4(ahi[0], base + swz64(ar0, aseg));
                ldsm_x4(ahi[1], base + swz64(ar0 + 16, aseg));
                ldsm_x4(alo[0], base + GA_BYTES + swz64(ar0, aseg));
                ldsm_x4(alo[1], base + GA_BYTES + swz64(ar0 + 16, aseg));
            }
            const uint32_t br0  = warp_n * 64 + (lane & 7) + ((lane & 16) >> 1);
            const uint32_t bseg = kk * 2 + ((lane >> 3) & 1);
            #pragma unroll
            for (int q = 0; q < 4; q++) {
                uint32_t bhi[4], blo[4];
                const uint32_t brow = br0 + q * 16;
                ldsm_x4(bhi, base + 2 * GA_BYTES + swz64(brow, bseg));
                ldsm_x4(blo, base + 2 * GA_BYTES + GB_BYTES + swz64(brow, bseg));
                #pragma unroll
                for (int mt = 0; mt < 2; mt++)
                    #pragma unroll
                    for (int n2 = 0; n2 < 2; n2++)
                        mma16816(acc[mt][2 * q + n2], ahi[mt], &bhi[n2 * 2]);
                #pragma unroll
                for (int mt = 0; mt < 2; mt++)
                    #pragma unroll
                    for (int n2 = 0; n2 < 2; n2++)
                        mma16816(acc[mt][2 * q + n2], ahi[mt], &blo[n2 * 2]);
                #pragma unroll
                for (int mt = 0; mt < 2; mt++)
                    #pragma unroll
                    for (int n2 = 0; n2 < 2; n2++)
                        mma16816(acc[mt][2 * q + n2], alo[mt], &bhi[n2 * 2]);
            }
        }
    }
}

// ============================================================================
// fp16 2-term GEMM core (A single fp16, W fp16 hi/lo): tile 64x128, BK=32.
// ============================================================================
#define OSTG   (GA_BYTES + 2 * GB_BYTES)    // 20480
#define OSMEM  (2 * OSTG)                   // 40960

__device__ __forceinline__ void h16_core(
    const __half* __restrict__ Ah,
    const __half* __restrict__ Whi, const __half* __restrict__ Wlo,
    uint32_t sb, int tid, int bc, int br, float acc[2][8][4])
{
    const int lane   = tid & 31;
    const int wid    = tid >> 5;
    const int warp_m = wid >> 1;
    const int warp_n = wid & 1;

    auto issue = [&](int kc, int stage) {
        #pragma unroll
        for (int t = 0; t < 10; t++) {
            const int c = tid + t * 128;      // 0..1279
            uint32_t dst;
            const __half* g;
            if (c < 256) {
                const int row = c >> 2, seg = c & 3;
                g = Ah + (long)(br * 64 + row) * DMODEL + kc * 32 + seg * 8;
                dst = sb + stage * OSTG + swz64(row, seg);
            } else {
                const int cb = c - 256;
                const int arr = cb >> 9, rem = cb & 511;
                const int row = rem >> 2, seg = rem & 3;
                g = (arr ? Wlo : Whi) + (long)(bc * 128 + row) * DMODEL
                  + kc * 32 + seg * 8;
                dst = sb + stage * OSTG + GA_BYTES + arr * GB_BYTES
                    + swz64(row, seg);
            }
            cp_async16(dst, g);
        }
        cp_commit();
    };

    issue(0, 0);

    const int NKC = DMODEL / 32;
    for (int kc = 0; kc < NKC; kc++) {
        cp_wait<0>();
        __syncthreads();
        if (kc + 1 < NKC) issue(kc + 1, (kc + 1) & 1);

        const uint32_t base = sb + (kc & 1) * OSTG;

        #pragma unroll
        for (int kk = 0; kk < 2; kk++) {
            uint32_t ah[2][4];
            {
                const uint32_t ar0  = warp_m * 32 + (lane & 15);
                const uint32_t aseg = kk * 2 + (lane >> 4);
                ldsm_x4(ah[0], base + swz64(ar0, aseg));
                ldsm_x4(ah[1], base + swz64(ar0 + 16, aseg));
            }
            const uint32_t br0  = warp_n * 64 + (lane & 7) + ((lane & 16) >> 1);
            const uint32_t bseg = kk * 2 + ((lane >> 3) & 1);
            #pragma unroll
            for (int q = 0; q < 4; q++) {
                uint32_t bhi[4], blo[4];
                const uint32_t brow = br0 + q * 16;
                ldsm_x4(bhi, base + GA_BYTES + swz64(brow, bseg));
                ldsm_x4(blo, base + GA_BYTES + GB_BYTES + swz64(brow, bseg));
                #pragma unroll
                for (int mt = 0; mt < 2; mt++)
                    #pragma unroll
                    for (int n2 = 0; n2 < 2; n2++)
                        mma16816h(acc[mt][2 * q + n2], ah[mt], &bhi[n2 * 2]);
                #pragma unroll
                for (int mt = 0; mt < 2; mt++)
                    #pragma unroll
                    for (int n2 = 0; n2 < 2; n2++)
                        mma16816h(acc[mt][2 * q + n2], ah[mt], &blo[n2 * 2]);
            }
        }
    }
}

// ============================================================================
// Q,K projection GEMM: grid (8, 128, 2), 128 threads, 4 CTAs/SM.
// ============================================================================
__global__ void __launch_bounds__(128, 4)
gemm_qk(__nv_bfloat16* __restrict__ Qhi, __nv_bfloat16* __restrict__ Qlo,
        __nv_bfloat16* __restrict__ Khi, __nv_bfloat16* __restrict__ Klo)
{
    extern __shared__ char smem[];
    const uint32_t sb = smem_u32(smem);
    const int tid = threadIdx.x;
    const int bc = blockIdx.x, br = blockIdx.y, z = blockIdx.z;

    uint32_t* Chi = (uint32_t*)(z == 0 ? Qhi : Khi);
    uint32_t* Clo = (uint32_t*)(z == 0 ? Qlo : Klo);
    const float scale = (z == 0) ? 0.125f : 1.0f;

    float acc[2][8][4];
    #pragma unroll
    for (int mt = 0; mt < 2; mt++)
        #pragma unroll
        for (int nt = 0; nt < 8; nt++)
            #pragma unroll
            for (int i = 0; i < 4; i++) acc[mt][nt][i] = 0.0f;

    gemm_core(g_Ahi[z], g_Alo[z], g_Whi[z], g_Wlo[z], sb, tid, bc, br, acc);

    const int lane = tid & 31, wid = tid >> 5;
    const int warp_m = wid >> 1, warp_n = wid & 1;
    #pragma unroll
    for (int mt = 0; mt < 2; mt++) {
        #pragma unroll
        for (int nt = 0; nt < 8; nt++) {
            const int row0 = br * 64 + warp_m * 32 + mt * 16 + (lane >> 2);
            const int col  = bc * 128 + warp_n * 64 + nt * 8 + (lane & 3) * 2;
            const int h = col >> 6, dd = col & 63;
            #pragma unroll
            for (int half = 0; half < 2; half++) {
                const int r = row0 + half * 8;
                const int b = r >> 11, s = r & 2047;
                const long off = (((((long)b * NHEADS + h) * S_LEN + s) * HDIM) + dd) >> 1;
                uint32_t hi, lo;
                split2(acc[mt][nt][half * 2] * scale,
                       acc[mt][nt][half * 2 + 1] * scale, hi, lo);
                Chi[off] = hi;
                Clo[off] = lo;
            }
        }
    }
}

// ============================================================================
// V projection GEMM: fp16 2-term, scatter head-split fp16. grid (8, 128).
// ============================================================================
__global__ void __launch_bounds__(128, 4)
gemm_v(const __half* __restrict__ Ah,
       const __half* __restrict__ Whi, const __half* __restrict__ Wlo,
       __half* __restrict__ Vh)
{
    extern __shared__ char smem[];
    const uint32_t sb = smem_u32(smem);
    const int tid = threadIdx.x;
    const int bc = blockIdx.x, br = blockIdx.y;

    float acc[2][8][4];
    #pragma unroll
    for (int mt = 0; mt < 2; mt++)
        #pragma unroll
        for (int nt = 0; nt < 8; nt++)
            #pragma unroll
            for (int i = 0; i < 4; i++) acc[mt][nt][i] = 0.0f;

    h16_core(Ah, Whi, Wlo, sb, tid, bc, br, acc);

    const int lane = tid & 31, wid = tid >> 5;
    const int warp_m = wid >> 1, warp_n = wid & 1;
    uint32_t* C = (uint32_t*)Vh;
    #pragma unroll
    for (int mt = 0; mt < 2; mt++) {
        #pragma unroll
        for (int nt = 0; nt < 8; nt++) {
            const int row0 = br * 64 + warp_m * 32 + mt * 16 + (lane >> 2);
            const int col  = bc * 128 + warp_n * 64 + nt * 8 + (lane & 3) * 2;
            const int h = col >> 6, dd = col & 63;
            #pragma unroll
            for (int half = 0; half < 2; half++) {
                const int r = row0 + half * 8;
                const int b = r >> 11, s = r & 2047;
                const long off = (((((long)b * NHEADS + h) * S_LEN + s) * HDIM) + dd) >> 1;
                C[off] = packh2(acc[mt][nt][half * 2], acc[mt][nt][half * 2 + 1]);
            }
        }
    }
}

// ============================================================================
// Output projection GEMM: fp16 2-term, fp32 row-major out. grid (8, 128).
// ============================================================================
__global__ void __launch_bounds__(128, 4)
gemm_out(const __half* __restrict__ Ah,
         const __half* __restrict__ Whi, const __half* __restrict__ Wlo,
         float* __restrict__ Cf)
{
    extern __shared__ char smem[];
    const uint32_t sb = smem_u32(smem);
    const int tid = threadIdx.x;
    const int bc = blockIdx.x, br = blockIdx.y;

    float acc[2][8][4];
    #pragma unroll
    for (int mt = 0; mt < 2; mt++)
        #pragma unroll
        for (int nt = 0; nt < 8; nt++)
            #pragma unroll
            for (int i = 0; i < 4; i++) acc[mt][nt][i] = 0.0f;

    h16_core(Ah, Whi, Wlo, sb, tid, bc, br, acc);

    const int lane = tid & 31, wid = tid >> 5;
    const int warp_m = wid >> 1, warp_n = wid & 1;
    #pragma unroll
    for (int mt = 0; mt < 2; mt++) {
        #pragma unroll
        for (int nt = 0; nt < 8; nt++) {
            const int row0 = br * 64 + warp_m * 32 + mt * 16 + (lane >> 2);
            const int col  = bc * 128 + warp_n * 64 + nt * 8 + (lane & 3) * 2;
            float2 v01; v01.x = acc[mt][nt][0]; v01.y = acc[mt][nt][1];
            float2 v23; v23.x = acc[mt][nt][2]; v23.y = acc[mt][nt][3];
            *(float2*)&Cf[(long)row0 * DMODEL + col] = v01;
            *(float2*)&Cf[(long)(row0 + 8) * DMODEL + col] = v23;
        }
    }
}

// ============================================================================
// Tensor-core causal flash attention.
// QK: bf16 3-term. PV: fp16 single. Merged KV stage, ONE wait + ONE sync/tile.
// Deferred l-reduction (per-lane partials, reduced once in epilogue).
// 55.3KB -> 4 CTAs/SM. grid (32, 64); q-blocks longest-first.
// ============================================================================
#define AROWB    144
#define ARR      (64 * AROWB)            // 9216
#define KVSTG    (3 * ARR)               // 27648: Khi, Klo, V
#define ASMEM    (2 * KVSTG)             // 55296

__global__ void __launch_bounds__(128, 4)
attn_mma(const __nv_bfloat16* __restrict__ Qhi, const __nv_bfloat16* __restrict__ Qlo,
         const __nv_bfloat16* __restrict__ Khi, const __nv_bfloat16* __restrict__ Klo,
         const __half* __restrict__ Vh,
         __half* __restrict__ Oh)
{
    extern __shared__ char smem[];
    const uint32_t sb = smem_u32(smem);
    const int tid = threadIdx.x, wid = tid >> 5, lane = tid & 31;
    const int qblk = (int)gridDim.x - 1 - (int)blockIdx.x;   // longest first
    const int q0 = qblk * 64;
    const int bh = blockIdx.y;
    const long base = (long)bh * S_LEN * HDIM;
    const int ntiles = qblk + 1;

    auto ldq = [&](uint32_t smem_base) {
        #pragma unroll
        for (int t = 0; t < 8; t++) {
            const int c = tid + t * 128;
            const int arr = c >> 9, rem = c & 511;
            const int row = rem >> 3, seg = rem & 7;
            const char* src = (const char*)(arr ? Qlo : Qhi)
                            + ((base + ((long)q0 + row) * HDIM + seg * 8) << 1);
            cp_async16(smem_base + arr * ARR + row * AROWB + seg * 16, src);
        }
        cp_commit();
    };
    auto ldkv = [&](int t, int stage) {
        const long grow0 = (long)t * 64;
        #pragma unroll
        for (int i = 0; i < 12; i++) {
            const int c = tid + i * 128;
            const int arr = c >> 9, rem = c & 511;
            const int row = rem >> 3, seg = rem & 7;
            const char* p;
            if (arr == 0)      p = (const char*)Khi;
            else if (arr == 1) p = (const char*)Klo;
            else               p = (const char*)Vh;
            cp_async16(sb + stage * KVSTG + arr * ARR + row * AROWB + seg * 16,
                       p + ((base + (grow0 + row) * HDIM + seg * 8) << 1));
        }
        cp_commit();
    };

    // ---- prologue ----
    ldq(sb + KVSTG);
    ldkv(0, 0);
    cp_wait<1>();
    __syncthreads();

    uint32_t qhF[4][4], qlF[4][4];
    {
        const uint32_t arow = wid * 16 + (lane & 15);
        #pragma unroll
        for (int kt = 0; kt < 4; kt++) {
            const uint32_t off = arow * AROWB + (kt * 16 + (lane >> 4) * 8) * 2;
            ldsm_x4(qhF[kt], sb + KVSTG + off);
            ldsm_x4(qlF[kt], sb + KVSTG + ARR + off);
        }
    }

    float m_s[2] = {-1e30f, -1e30f};
    float l_s[2] = {0.0f, 0.0f};         // per-lane partials; reduced at end
    float acc_o[8][4];
    #pragma unroll
    for (int nt = 0; nt < 8; nt++)
        #pragma unroll
        for (int i = 0; i < 4; i++) acc_o[nt][i] = 0.0f;

    const int wrow_lo = q0 + wid * 16;

    for (int t = 0; t < ntiles; t++) {
        cp_wait<0>();
        __syncthreads();
        if (t + 1 < ntiles) ldkv(t + 1, (t + 1) & 1);

        const uint32_t kbase = sb + (t & 1) * KVSTG;
        const uint32_t vbase = kbase + 2 * ARR;
        const bool act = (t * 64 <= wrow_lo + 15);

        if (act) {
            float acc_s[8][4];
            #pragma unroll
            for (int nt = 0; nt < 8; nt++)
                #pragma unroll
                for (int i = 0; i < 4; i++) acc_s[nt][i] = 0.0f;

            #pragma unroll
            for (int kt = 0; kt < 4; kt++) {
                const uint32_t brow = (lane & 7) + ((lane & 16) >> 1);
                const uint32_t bcol = kt * 16 + ((lane >> 3) & 1) * 8;
                #pragma unroll
                for (int g = 0; g < 4; g++) {
                    uint32_t kh[4], kl[4];
                    const uint32_t off = (g * 16 + brow) * AROWB + bcol * 2;
                    ldsm_x4(kh, kbase + off);
                    ldsm_x4(kl, kbase + ARR + off);
                    mma16816(acc_s[2 * g],     qhF[kt], &kh[0]);
                    mma16816(acc_s[2 * g + 1], qhF[kt], &kh[2]);
                    mma16816(acc_s[2 * g],     qhF[kt], &kl[0]);
                    mma16816(acc_s[2 * g + 1], qhF[kt], &kl[2]);
                    mma16816(acc_s[2 * g],     qlF[kt], &kh[0]);
                    mma16816(acc_s[2 * g + 1], qlF[kt], &kh[2]);
                }
            }

            const int r0 = q0 + wid * 16 + (lane >> 2);
            if (t * 64 + 63 > wrow_lo) {
                #pragma unroll
                for (int nt = 0; nt < 8; nt++)
                    #pragma unroll
                    for (int i = 0; i < 4; i++) {
                        const int row = r0 + (i >> 1) * 8;
                        const int col = t * 64 + nt * 8 + 2 * (lane & 3) + (i & 1);
                        if (col > row) acc_s[nt][i] = -1e30f;
                    }
            }

            // ---- row max (cross-lane reduce required) ----
            float tmax[2] = {-1e30f, -1e30f};
            #pragma unroll
            for (int nt = 0; nt < 8; nt++)
                #pragma unroll
                for (int i = 0; i < 4; i++)
                    tmax[i >> 1] = fmaxf(tmax[i >> 1], acc_s[nt][i]);
            #pragma unroll
            for (int h = 0; h < 2; h++) {
                tmax[h] = fmaxf(tmax[h], __shfl_xor_sync(0xffffffffu, tmax[h], 1));
                tmax[h] = fmaxf(tmax[h], __shfl_xor_sync(0xffffffffu, tmax[h], 2));
            }

            float nm[2], corr[2];
            #pragma unroll
            for (int h = 0; h < 2; h++) {
                nm[h]   = fmaxf(m_s[h], tmax[h]);
                corr[h] = __expf(m_s[h] - nm[h]);
                m_s[h]  = nm[h];
            }
            float psum[2] = {0.0f, 0.0f};
            #pragma unroll
            for (int nt = 0; nt < 8; nt++)
                #pragma unroll
                for (int i = 0; i < 4; i++) {
                    const float p = __expf(acc_s[nt][i] - nm[i >> 1]);
                    acc_s[nt][i] = p;
                    psum[i >> 1] += p;
                }
            #pragma unroll
            for (int h = 0; h < 2; h++)
                l_s[h] = l_s[h] * corr[h] + psum[h];   // per-lane partial
            #pragma unroll
            for (int nt = 0; nt < 8; nt++)
                #pragma unroll
                for (int i = 0; i < 4; i++) acc_o[nt][i] *= corr[i >> 1];

            uint32_t ph[4][4];
            #pragma unroll
            for (int kt = 0; kt < 4; kt++) {
                ph[kt][0] = packh2(acc_s[2 * kt][0],     acc_s[2 * kt][1]);
                ph[kt][1] = packh2(acc_s[2 * kt][2],     acc_s[2 * kt][3]);
                ph[kt][2] = packh2(acc_s[2 * kt + 1][0], acc_s[2 * kt + 1][1]);
                ph[kt][3] = packh2(acc_s[2 * kt + 1][2], acc_s[2 * kt + 1][3]);
            }

            #pragma unroll
            for (int kt = 0; kt < 4; kt++) {
                const uint32_t vrow = kt * 16 + (lane & 15);
                const uint32_t vcol = (lane >> 4) * 8;
                #pragma unroll
                for (int g = 0; g < 4; g++) {
                    uint32_t vh[4];
                    const uint32_t off = vrow * AROWB + (g * 16 + vcol) * 2;
                    ldsm_x4t(vh, vbase + off);
                    mma16816h(acc_o[2 * g],     ph[kt], &vh[0]);
                    mma16816h(acc_o[2 * g + 1], ph[kt], &vh[2]);
                }
            }
        }
    }

    // ---- epilogue: reduce l once, normalize, single fp16 O ----
    float inv[2];
    #pragma unroll
    for (int h = 0; h < 2; h++) {
        float l = l_s[h];
        l += __shfl_xor_sync(0xffffffffu, l, 1);
        l += __shfl_xor_sync(0xffffffffu, l, 2);
        inv[h] = 1.0f / l;
    }
    const int b  = bh >> 4;
    const int hh = bh & 15;
    const int r0 = q0 + wid * 16 + (lane >> 2);
    #pragma unroll
    for (int nt = 0; nt < 8; nt++) {
        const int col = hh * 64 + nt * 8 + 2 * (lane & 3);
        {
            const long idx = ((long)(b * S_LEN + r0)) * DMODEL + col;
            *(uint32_t*)(Oh + idx) = packh2(acc_o[nt][0] * inv[0],
                                            acc_o[nt][1] * inv[0]);
        }
        {
            const long idx = ((long)(b * S_LEN + r0 + 8)) * DMODEL + col;
            *(uint32_t*)(Oh + idx) = packh2(acc_o[nt][2] * inv[1],
                                            acc_o[nt][3] * inv[1]);
        }
    }
}

// ============================================================================
// conversion kernels
// ============================================================================
__global__ void __launch_bounds__(256)
conv_qkv(const float* __restrict__ q, const float* __restrict__ k,
         const float* __restrict__ v)
{
    const int z = blockIdx.y;
    const float* X = (z == 0) ? q : (z == 1) ? k : v;
    const int i = blockIdx.x * 256 + threadIdx.x;
    const float2 x = ((const float2*)X)[i];
    if (z == 2) {
        ((uint32_t*)g_Avh)[i] = packh2(x.x, x.y);
    } else {
        uint32_t h, l;
        split2(x.x, x.y, h, l);
        ((uint32_t*)g_Ahi[z])[i] = h;
        ((uint32_t*)g_Alo[z])[i] = l;
    }
}

__global__ void __launch_bounds__(256)
conv_w(const float* __restrict__ W0, const float* __restrict__ W1,
       const float* __restrict__ W2, const float* __restrict__ W3)
{
    __shared__ float t[32][33];
    const int z = blockIdx.z;
    const float* W = (z == 0) ? W0 : (z == 1) ? W1 : (z == 2) ? W2 : W3;
    const int tx = threadIdx.x, ty = threadIdx.y;
    const int n0 = blockIdx.x * 32, k0 = blockIdx.y * 32;
    #pragma unroll
    for (int r = 0; r < 4; r++) {
        const int k = ty + r * 8;
        t[k][tx] = W[(long)(k0 + k) * DMODEL + n0 + tx];
    }
    __syncthreads();
    #pragma unroll
    for (int r = 0; r < 4; r++) {
        const int nl = ty + r * 8;
        const float x = t[tx][nl];
        const long o = (long)(n0 + nl) * DMODEL + k0 + tx;
        if (z < 2) {
            const __nv_bfloat16 h = __float2bfloat16(x);
            g_Whi[z][o] = h;
            g_Wlo[z][o] = __float2bfloat16(x - __bfloat162float(h));
        } else {
            const __half h = __float2half_rn(x);
            const __half l = __float2half_rn(x - __half2float(h));
            if (z == 2) { g_Wvh[o] = h; g_Wvl[o] = l; }
            else        { g_W4h[o] = h; g_W4l[o] = l; }
        }
    }
}

// ============================================================================
extern "C" void kernel_launch(void* const* d_in, const int* in_sizes, int n_in,
                              void* d_out, int out_size)
{
    const float* q = (const float*)d_in[0];
    const float* k = (const float*)d_in[1];
    const float* v = (const float*)d_in[2];
    float* out = (float*)d_out;

    __nv_bfloat16 *qhi, *qlo, *khi, *klo;
    __half *vh, *oh, *w4h, *w4l, *wvh, *wvl, *avh;
    cudaGetSymbolAddress((void**)&qhi, g_Qhi);
    cudaGetSymbolAddress((void**)&qlo, g_Qlo);
    cudaGetSymbolAddress((void**)&khi, g_Khi);
    cudaGetSymbolAddress((void**)&klo, g_Klo);
    cudaGetSymbolAddress((void**)&vh,  g_Vh);
    cudaGetSymbolAddress((void**)&oh,  g_Oh);
    cudaGetSymbolAddress((void**)&w4h, g_W4h);
    cudaGetSymbolAddress((void**)&w4l, g_W4l);
    cudaGetSymbolAddress((void**)&wvh, g_Wvh);
    cudaGetSymbolAddress((void**)&wvl, g_Wvl);
    cudaGetSymbolAddress((void**)&avh, g_Avh);

    cudaFuncSetAttribute((const void*)gemm_qk,
                         cudaFuncAttributeMaxDynamicSharedMemorySize, GSMEM);
    cudaFuncSetAttribute((const void*)gemm_v,
                         cudaFuncAttributeMaxDynamicSharedMemorySize, OSMEM);
    cudaFuncSetAttribute((const void*)gemm_out,
                         cudaFuncAttributeMaxDynamicSharedMemorySize, OSMEM);
    cudaFuncSetAttribute((const void*)attn_mma,
                         cudaFuncAttributeMaxDynamicSharedMemorySize, ASMEM);

    conv_w<<<dim3(32, 32, 4), dim3(32, 8)>>>(
        (const float*)d_in[3], (const float*)d_in[4],
        (const float*)d_in[5], (const float*)d_in[6]);

    conv_qkv<<<dim3(AELEMS / 2 / 256, 3), 256>>>(q, k, v);

    gemm_qk<<<dim3(8, 128, 2), 128, GSMEM>>>(qhi, qlo, khi, klo);
    gemm_v<<<dim3(8, 128), 128, OSMEM>>>(avh, wvh, wvl, vh);

    attn_mma<<<dim3(S_LEN / 64, BHCNT), 128, ASMEM>>>(qhi, qlo, khi, klo,
                                                      vh, oh);

    gemm_out<<<dim3(8, 128), 128, OSMEM>>>(oh, w4h, w4l, out);
}

// round 15
// speedup vs baseline: 1.3575x; 1.0401x over previous
#include <cuda_runtime.h>
#include <cuda_bf16.h>
#include <cuda_fp16.h>
#include <cstdint>

#define S_LEN   2048
#define DMODEL  1024
#define NHEADS  16
#define HDIM    64
#define BATCH   4
#define BHCNT   (BATCH * NHEADS)                   // 64
#define MROWS   (BATCH * S_LEN)                    // 8192
#define HS_ELEMS (BATCH * NHEADS * S_LEN * HDIM)   // 8388608
#define AELEMS  (MROWS * DMODEL)                   // 8388608
#define WELEMS  (DMODEL * DMODEL)                  // 1048576

// ---- scratch ----
__device__ __nv_bfloat16 g_Ahi[2][AELEMS];   // q,k inputs bf16 hi/lo
__device__ __nv_bfloat16 g_Alo[2][AELEMS];
__device__ __half        g_Avh[AELEMS];      // v input, fp16 single
__device__ __nv_bfloat16 g_Whi[2][WELEMS];   // Wq,Wk transposed [N][K], bf16
__device__ __nv_bfloat16 g_Wlo[2][WELEMS];
__device__ __half        g_Wvh[WELEMS];      // Wv transposed, fp16 hi/lo
__device__ __half        g_Wvl[WELEMS];
__device__ __half        g_W4h[WELEMS];      // Wo transposed, fp16 hi/lo
__device__ __half        g_W4l[WELEMS];
__device__ __nv_bfloat16 g_Qhi[HS_ELEMS], g_Qlo[HS_ELEMS];   // bf16, pre-scaled 1/8
__device__ __nv_bfloat16 g_Khi[HS_ELEMS], g_Klo[HS_ELEMS];   // bf16
__device__ __half        g_Vh[HS_ELEMS];                     // fp16 single
__device__ __half        g_Oh[AELEMS];                       // fp16, row-major

// ============================================================================
// helpers (baseline PTX only)
// ============================================================================
__device__ __forceinline__ uint32_t smem_u32(const void* p) {
    uint32_t a;
    asm("{ .reg .u64 t; cvta.to.shared.u64 t, %1; cvt.u32.u64 %0, t; }"
        : "=r"(a) : "l"(p));
    return a;
}
__device__ __forceinline__ void cp_async16(uint32_t dst, const void* src) {
    asm volatile("cp.async.cg.shared.global [%0], [%1], 16;"
                 :: "r"(dst), "l"(src));
}
__device__ __forceinline__ void cp_commit() {
    asm volatile("cp.async.commit_group;");
}
template <int N>
__device__ __forceinline__ void cp_wait() {
    asm volatile("cp.async.wait_group %0;" :: "n"(N));
}
__device__ __forceinline__ void ldsm_x4(uint32_t* r, uint32_t addr) {
    asm volatile("ldmatrix.sync.aligned.m8n8.x4.shared.b16 {%0,%1,%2,%3}, [%4];"
                 : "=r"(r[0]), "=r"(r[1]), "=r"(r[2]), "=r"(r[3]) : "r"(addr));
}
__device__ __forceinline__ void ldsm_x4t(uint32_t* r, uint32_t addr) {
    asm volatile("ldmatrix.sync.aligned.m8n8.x4.trans.shared.b16 {%0,%1,%2,%3}, [%4];"
                 : "=r"(r[0]), "=r"(r[1]), "=r"(r[2]), "=r"(r[3]) : "r"(addr));
}
__device__ __forceinline__ void mma16816(float* d, const uint32_t* a,
                                         const uint32_t* b) {
    asm volatile("mma.sync.aligned.m16n8k16.row.col.f32.bf16.bf16.f32 "
                 "{%0,%1,%2,%3}, {%4,%5,%6,%7}, {%8,%9}, {%0,%1,%2,%3};"
                 : "+f"(d[0]), "+f"(d[1]), "+f"(d[2]), "+f"(d[3])
                 : "r"(a[0]), "r"(a[1]), "r"(a[2]), "r"(a[3]),
                   "r"(b[0]), "r"(b[1]));
}
__device__ __forceinline__ void mma16816h(float* d, const uint32_t* a,
                                          const uint32_t* b) {
    asm volatile("mma.sync.aligned.m16n8k16.row.col.f32.f16.f16.f32 "
                 "{%0,%1,%2,%3}, {%4,%5,%6,%7}, {%8,%9}, {%0,%1,%2,%3};"
                 : "+f"(d[0]), "+f"(d[1]), "+f"(d[2]), "+f"(d[3])
                 : "r"(a[0]), "r"(a[1]), "r"(a[2]), "r"(a[3]),
                   "r"(b[0]), "r"(b[1]));
}
__device__ __forceinline__ void split2(float a, float b,
                                       uint32_t& hi, uint32_t& lo) {
    uint32_t h;
    asm("cvt.rn.bf16x2.f32 %0, %1, %2;" : "=r"(h) : "f"(b), "f"(a));
    const float fa = __uint_as_float(h << 16);
    const float fb = __uint_as_float(h & 0xFFFF0000u);
    uint32_t l;
    asm("cvt.rn.bf16x2.f32 %0, %1, %2;" : "=r"(l) : "f"(b - fb), "f"(a - fa));
    hi = h; lo = l;
}
__device__ __forceinline__ uint32_t packh2(float a, float b) {
    uint32_t h;
    asm("cvt.rn.f16x2.f32 %0, %1, %2;" : "=r"(h) : "f"(b), "f"(a));
    return h;
}

#define GA_BYTES   (64 * 64)                 // 4096
#define GB_BYTES   (128 * 64)                // 8192
#define STG_BYTES  (2 * GA_BYTES + 2 * GB_BYTES)  // 24576
#define GSMEM      (2 * STG_BYTES)           // 49152
#define OSTG       (GA_BYTES + 2 * GB_BYTES) // 20480
#define OSMEM      (2 * OSTG)                // 40960

__device__ __forceinline__ uint32_t swz64(uint32_t row, uint32_t seg) {
    return row * 64 + ((seg ^ (row & 3)) * 16);
}

// ============================================================================
// bf16 3-term GEMM core: tile 64x128, BK=32, 4 warps as 1M x 4N (warp 64x32).
// LDSM:MMA ratio 12:48 (was 12:24) -> smem-port pressure halved.
// ============================================================================
__device__ __forceinline__ void gemm_core(
    const __nv_bfloat16* __restrict__ Ahi, const __nv_bfloat16* __restrict__ Alo,
    const __nv_bfloat16* __restrict__ Bhi, const __nv_bfloat16* __restrict__ Blo,
    uint32_t sb, int tid, int bc, int br, float acc[4][4][4])
{
    const int lane   = tid & 31;
    const int warp_n = tid >> 5;          // 0..3 (N slices)

    auto issue = [&](int kc, int stage) {
        #pragma unroll
        for (int t = 0; t < 12; t++) {
            const int c = tid + t * 128;
            uint32_t dst;
            const __nv_bfloat16* g;
            if (c < 512) {
                const int arr = c >> 8, rem = c & 255;
                const int row = rem >> 2, seg = rem & 3;
                g = (arr ? Alo : Ahi) + (long)(br * 64 + row) * DMODEL
                  + kc * 32 + seg * 8;
                dst = sb + stage * STG_BYTES + arr * GA_BYTES + swz64(row, seg);
            } else {
                const int cb = c - 512;
                const int arr = cb >> 9, rem = cb & 511;
                const int row = rem >> 2, seg = rem & 3;
                g = (arr ? Blo : Bhi) + (long)(bc * 128 + row) * DMODEL
                  + kc * 32 + seg * 8;
                dst = sb + stage * STG_BYTES + 2 * GA_BYTES + arr * GB_BYTES
                    + swz64(row, seg);
            }
            cp_async16(dst, g);
        }
        cp_commit();
    };

    issue(0, 0);

    const int NKC = DMODEL / 32;
    for (int kc = 0; kc < NKC; kc++) {
        cp_wait<0>();
        __syncthreads();
        if (kc + 1 < NKC) issue(kc + 1, (kc + 1) & 1);

        const uint32_t base = sb + (kc & 1) * STG_BYTES;

        #pragma unroll
        for (int kk = 0; kk < 2; kk++) {
            uint32_t ahi[4][4], alo[4][4];
            {
                const uint32_t ar0  = lane & 15;
                const uint32_t aseg = kk * 2 + (lane >> 4);
                #pragma unroll
                for (int mt = 0; mt < 4; mt++) {
                    ldsm_x4(ahi[mt], base + swz64(mt * 16 + ar0, aseg));
                    ldsm_x4(alo[mt], base + GA_BYTES + swz64(mt * 16 + ar0, aseg));
                }
            }
            const uint32_t br0  = warp_n * 32 + (lane & 7) + ((lane & 16) >> 1);
            const uint32_t bseg = kk * 2 + ((lane >> 3) & 1);
            #pragma unroll
            for (int q = 0; q < 2; q++) {
                uint32_t bhi[4], blo[4];
                const uint32_t brow = br0 + q * 16;
                ldsm_x4(bhi, base + 2 * GA_BYTES + swz64(brow, bseg));
                ldsm_x4(blo, base + 2 * GA_BYTES + GB_BYTES + swz64(brow, bseg));
                #pragma unroll
                for (int mt = 0; mt < 4; mt++)
                    #pragma unroll
                    for (int n2 = 0; n2 < 2; n2++)
                        mma16816(acc[mt][2 * q + n2], ahi[mt], &bhi[n2 * 2]);
                #pragma unroll
                for (int mt = 0; mt < 4; mt++)
                    #pragma unroll
                    for (int n2 = 0; n2 < 2; n2++)
                        mma16816(acc[mt][2 * q + n2], ahi[mt], &blo[n2 * 2]);
                #pragma unroll
                for (int mt = 0; mt < 4; mt++)
                    #pragma unroll
                    for (int n2 = 0; n2 < 2; n2++)
                        mma16816(acc[mt][2 * q + n2], alo[mt], &bhi[n2 * 2]);
            }
        }
    }
}

// ============================================================================
// fp16 2-term GEMM core (A single fp16, W hi/lo): same 1M x 4N layout.
// LDSM:MMA ratio 8:32.
// ============================================================================
__device__ __forceinline__ void h16_core(
    const __half* __restrict__ Ah,
    const __half* __restrict__ Whi, const __half* __restrict__ Wlo,
    uint32_t sb, int tid, int bc, int br, float acc[4][4][4])
{
    const int lane   = tid & 31;
    const int warp_n = tid >> 5;

    auto issue = [&](int kc, int stage) {
        #pragma unroll
        for (int t = 0; t < 10; t++) {
            const int c = tid + t * 128;
            uint32_t dst;
            const __half* g;
            if (c < 256) {
                const int row = c >> 2, seg = c & 3;
                g = Ah + (long)(br * 64 + row) * DMODEL + kc * 32 + seg * 8;
                dst = sb + stage * OSTG + swz64(row, seg);
            } else {
                const int cb = c - 256;
                const int arr = cb >> 9, rem = cb & 511;
                const int row = rem >> 2, seg = rem & 3;
                g = (arr ? Wlo : Whi) + (long)(bc * 128 + row) * DMODEL
                  + kc * 32 + seg * 8;
                dst = sb + stage * OSTG + GA_BYTES + arr * GB_BYTES
                    + swz64(row, seg);
            }
            cp_async16(dst, g);
        }
        cp_commit();
    };

    issue(0, 0);

    const int NKC = DMODEL / 32;
    for (int kc = 0; kc < NKC; kc++) {
        cp_wait<0>();
        __syncthreads();
        if (kc + 1 < NKC) issue(kc + 1, (kc + 1) & 1);

        const uint32_t base = sb + (kc & 1) * OSTG;

        #pragma unroll
        for (int kk = 0; kk < 2; kk++) {
            uint32_t ah[4][4];
            {
                const uint32_t ar0  = lane & 15;
                const uint32_t aseg = kk * 2 + (lane >> 4);
                #pragma unroll
                for (int mt = 0; mt < 4; mt++)
                    ldsm_x4(ah[mt], base + swz64(mt * 16 + ar0, aseg));
            }
            const uint32_t br0  = warp_n * 32 + (lane & 7) + ((lane & 16) >> 1);
            const uint32_t bseg = kk * 2 + ((lane >> 3) & 1);
            #pragma unroll
            for (int q = 0; q < 2; q++) {
                uint32_t bhi[4], blo[4];
                const uint32_t brow = br0 + q * 16;
                ldsm_x4(bhi, base + GA_BYTES + swz64(brow, bseg));
                ldsm_x4(blo, base + GA_BYTES + GB_BYTES + swz64(brow, bseg));
                #pragma unroll
                for (int mt = 0; mt < 4; mt++)
                    #pragma unroll
                    for (int n2 = 0; n2 < 2; n2++)
                        mma16816h(acc[mt][2 * q + n2], ah[mt], &bhi[n2 * 2]);
                #pragma unroll
                for (int mt = 0; mt < 4; mt++)
                    #pragma unroll
                    for (int n2 = 0; n2 < 2; n2++)
                        mma16816h(acc[mt][2 * q + n2], ah[mt], &blo[n2 * 2]);
            }
        }
    }
}

// ============================================================================
// Fused QKV projection GEMM: grid (8, 128, 3), 128 threads, 4 CTAs/SM.
// z 0/1: bf16 3-term (Q scaled 1/8, K), bf16 hi/lo head-split out.
// z 2:   fp16 2-term V, single fp16 head-split out.
// ============================================================================
__global__ void __launch_bounds__(128, 4)
gemm_proj(__nv_bfloat16* __restrict__ Qhi, __nv_bfloat16* __restrict__ Qlo,
          __nv_bfloat16* __restrict__ Khi, __nv_bfloat16* __restrict__ Klo,
          __half* __restrict__ Vh)
{
    extern __shared__ char smem[];
    const uint32_t sb = smem_u32(smem);
    const int tid = threadIdx.x;
    const int bc = blockIdx.x, br = blockIdx.y, z = blockIdx.z;
    const int lane = tid & 31, warp_n = tid >> 5;

    float acc[4][4][4];
    #pragma unroll
    for (int mt = 0; mt < 4; mt++)
        #pragma unroll
        for (int nt = 0; nt < 4; nt++)
            #pragma unroll
            for (int i = 0; i < 4; i++) acc[mt][nt][i] = 0.0f;

    if (z == 2) {
        h16_core(g_Avh, g_Wvh, g_Wvl, sb, tid, bc, br, acc);
        uint32_t* C = (uint32_t*)Vh;
        #pragma unroll
        for (int mt = 0; mt < 4; mt++) {
            #pragma unroll
            for (int nt = 0; nt < 4; nt++) {
                const int row0 = br * 64 + mt * 16 + (lane >> 2);
                const int col  = bc * 128 + warp_n * 32 + nt * 8 + (lane & 3) * 2;
                const int h = col >> 6, dd = col & 63;
                #pragma unroll
                for (int half = 0; half < 2; half++) {
                    const int r = row0 + half * 8;
                    const int b = r >> 11, s = r & 2047;
                    const long off = (((((long)b * NHEADS + h) * S_LEN + s) * HDIM) + dd) >> 1;
                    C[off] = packh2(acc[mt][nt][half * 2], acc[mt][nt][half * 2 + 1]);
                }
            }
        }
    } else {
        uint32_t* Chi = (uint32_t*)(z == 0 ? Qhi : Khi);
        uint32_t* Clo = (uint32_t*)(z == 0 ? Qlo : Klo);
        const float scale = (z == 0) ? 0.125f : 1.0f;
        gemm_core(g_Ahi[z], g_Alo[z], g_Whi[z], g_Wlo[z], sb, tid, bc, br, acc);
        #pragma unroll
        for (int mt = 0; mt < 4; mt++) {
            #pragma unroll
            for (int nt = 0; nt < 4; nt++) {
                const int row0 = br * 64 + mt * 16 + (lane >> 2);
                const int col  = bc * 128 + warp_n * 32 + nt * 8 + (lane & 3) * 2;
                const int h = col >> 6, dd = col & 63;
                #pragma unroll
                for (int half = 0; half < 2; half++) {
                    const int r = row0 + half * 8;
                    const int b = r >> 11, s = r & 2047;
                    const long off = (((((long)b * NHEADS + h) * S_LEN + s) * HDIM) + dd) >> 1;
                    uint32_t hi, lo;
                    split2(acc[mt][nt][half * 2] * scale,
                           acc[mt][nt][half * 2 + 1] * scale, hi, lo);
                    Chi[off] = hi;
                    Clo[off] = lo;
                }
            }
        }
    }
}

// ============================================================================
// Output projection GEMM: fp16 2-term, fp32 row-major out. grid (8, 128).
// ============================================================================
__global__ void __launch_bounds__(128, 4)
gemm_out(const __half* __restrict__ Ah,
         const __half* __restrict__ Whi, const __half* __restrict__ Wlo,
         float* __restrict__ Cf)
{
    extern __shared__ char smem[];
    const uint32_t sb = smem_u32(smem);
    const int tid = threadIdx.x;
    const int bc = blockIdx.x, br = blockIdx.y;
    const int lane = tid & 31, warp_n = tid >> 5;

    float acc[4][4][4];
    #pragma unroll
    for (int mt = 0; mt < 4; mt++)
        #pragma unroll
        for (int nt = 0; nt < 4; nt++)
            #pragma unroll
            for (int i = 0; i < 4; i++) acc[mt][nt][i] = 0.0f;

    h16_core(Ah, Whi, Wlo, sb, tid, bc, br, acc);

    #pragma unroll
    for (int mt = 0; mt < 4; mt++) {
        #pragma unroll
        for (int nt = 0; nt < 4; nt++) {
            const int row0 = br * 64 + mt * 16 + (lane >> 2);
            const int col  = bc * 128 + warp_n * 32 + nt * 8 + (lane & 3) * 2;
            float2 v01; v01.x = acc[mt][nt][0]; v01.y = acc[mt][nt][1];
            float2 v23; v23.x = acc[mt][nt][2]; v23.y = acc[mt][nt][3];
            *(float2*)&Cf[(long)row0 * DMODEL + col] = v01;
            *(float2*)&Cf[(long)(row0 + 8) * DMODEL + col] = v23;
        }
    }
}

// ============================================================================
// Tensor-core causal flash attention (R14, unchanged).
// ============================================================================
#define AROWB    144
#define ARR      (64 * AROWB)            // 9216
#define KVSTG    (3 * ARR)               // 27648: Khi, Klo, V
#define ASMEM    (2 * KVSTG)             // 55296

__global__ void __launch_bounds__(128, 4)
attn_mma(const __nv_bfloat16* __restrict__ Qhi, const __nv_bfloat16* __restrict__ Qlo,
         const __nv_bfloat16* __restrict__ Khi, const __nv_bfloat16* __restrict__ Klo,
         const __half* __restrict__ Vh,
         __half* __restrict__ Oh)
{
    extern __shared__ char smem[];
    const uint32_t sb = smem_u32(smem);
    const int tid = threadIdx.x, wid = tid >> 5, lane = tid & 31;
    const int qblk = (int)gridDim.x - 1 - (int)blockIdx.x;   // longest first
    const int q0 = qblk * 64;
    const int bh = blockIdx.y;
    const long base = (long)bh * S_LEN * HDIM;
    const int ntiles = qblk + 1;

    auto ldq = [&](uint32_t smem_base) {
        #pragma unroll
        for (int t = 0; t < 8; t++) {
            const int c = tid + t * 128;
            const int arr = c >> 9, rem = c & 511;
            const int row = rem >> 3, seg = rem & 7;
            const char* src = (const char*)(arr ? Qlo : Qhi)
                            + ((base + ((long)q0 + row) * HDIM + seg * 8) << 1);
            cp_async16(smem_base + arr * ARR + row * AROWB + seg * 16, src);
        }
        cp_commit();
    };
    auto ldkv = [&](int t, int stage) {
        const long grow0 = (long)t * 64;
        #pragma unroll
        for (int i = 0; i < 12; i++) {
            const int c = tid + i * 128;
            const int arr = c >> 9, rem = c & 511;
            const int row = rem >> 3, seg = rem & 7;
            const char* p;
            if (arr == 0)      p = (const char*)Khi;
            else if (arr == 1) p = (const char*)Klo;
            else               p = (const char*)Vh;
            cp_async16(sb + stage * KVSTG + arr * ARR + row * AROWB + seg * 16,
                       p + ((base + (grow0 + row) * HDIM + seg * 8) << 1));
        }
        cp_commit();
    };

    ldq(sb + KVSTG);
    ldkv(0, 0);
    cp_wait<1>();
    __syncthreads();

    uint32_t qhF[4][4], qlF[4][4];
    {
        const uint32_t arow = wid * 16 + (lane & 15);
        #pragma unroll
        for (int kt = 0; kt < 4; kt++) {
            const uint32_t off = arow * AROWB + (kt * 16 + (lane >> 4) * 8) * 2;
            ldsm_x4(qhF[kt], sb + KVSTG + off);
            ldsm_x4(qlF[kt], sb + KVSTG + ARR + off);
        }
    }

    float m_s[2] = {-1e30f, -1e30f};
    float l_s[2] = {0.0f, 0.0f};
    float acc_o[8][4];
    #pragma unroll
    for (int nt = 0; nt < 8; nt++)
        #pragma unroll
        for (int i = 0; i < 4; i++) acc_o[nt][i] = 0.0f;

    const int wrow_lo = q0 + wid * 16;

    for (int t = 0; t < ntiles; t++) {
        cp_wait<0>();
        __syncthreads();
        if (t + 1 < ntiles) ldkv(t + 1, (t + 1) & 1);

        const uint32_t kbase = sb + (t & 1) * KVSTG;
        const uint32_t vbase = kbase + 2 * ARR;
        const bool act = (t * 64 <= wrow_lo + 15);

        if (act) {
            float acc_s[8][4];
            #pragma unroll
            for (int nt = 0; nt < 8; nt++)
                #pragma unroll
                for (int i = 0; i < 4; i++) acc_s[nt][i] = 0.0f;

            #pragma unroll
            for (int kt = 0; kt < 4; kt++) {
                const uint32_t brow = (lane & 7) + ((lane & 16) >> 1);
                const uint32_t bcol = kt * 16 + ((lane >> 3) & 1) * 8;
                #pragma unroll
                for (int g = 0; g < 4; g++) {
                    uint32_t kh[4], kl[4];
                    const uint32_t off = (g * 16 + brow) * AROWB + bcol * 2;
                    ldsm_x4(kh, kbase + off);
                    ldsm_x4(kl, kbase + ARR + off);
                    mma16816(acc_s[2 * g],     qhF[kt], &kh[0]);
                    mma16816(acc_s[2 * g + 1], qhF[kt], &kh[2]);
                    mma16816(acc_s[2 * g],     qhF[kt], &kl[0]);
                    mma16816(acc_s[2 * g + 1], qhF[kt], &kl[2]);
                    mma16816(acc_s[2 * g],     qlF[kt], &kh[0]);
                    mma16816(acc_s[2 * g + 1], qlF[kt], &kh[2]);
                }
            }

            const int r0 = q0 + wid * 16 + (lane >> 2);
            if (t * 64 + 63 > wrow_lo) {
                #pragma unroll
                for (int nt = 0; nt < 8; nt++)
                    #pragma unroll
                    for (int i = 0; i < 4; i++) {
                        const int row = r0 + (i >> 1) * 8;
                        const int col = t * 64 + nt * 8 + 2 * (lane & 3) + (i & 1);
                        if (col > row) acc_s[nt][i] = -1e30f;
                    }
            }

            float tmax[2] = {-1e30f, -1e30f};
            #pragma unroll
            for (int nt = 0; nt < 8; nt++)
                #pragma unroll
                for (int i = 0; i < 4; i++)
                    tmax[i >> 1] = fmaxf(tmax[i >> 1], acc_s[nt][i]);
            #pragma unroll
            for (int h = 0; h < 2; h++) {
                tmax[h] = fmaxf(tmax[h], __shfl_xor_sync(0xffffffffu, tmax[h], 1));
                tmax[h] = fmaxf(tmax[h], __shfl_xor_sync(0xffffffffu, tmax[h], 2));
            }

            float nm[2], corr[2];
            #pragma unroll
            for (int h = 0; h < 2; h++) {
                nm[h]   = fmaxf(m_s[h], tmax[h]);
                corr[h] = __expf(m_s[h] - nm[h]);
                m_s[h]  = nm[h];
            }
            float psum[2] = {0.0f, 0.0f};
            #pragma unroll
            for (int nt = 0; nt < 8; nt++)
                #pragma unroll
                for (int i = 0; i < 4; i++) {
                    const float p = __expf(acc_s[nt][i] - nm[i >> 1]);
                    acc_s[nt][i] = p;
                    psum[i >> 1] += p;
                }
            #pragma unroll
            for (int h = 0; h < 2; h++)
                l_s[h] = l_s[h] * corr[h] + psum[h];
            #pragma unroll
            for (int nt = 0; nt < 8; nt++)
                #pragma unroll
                for (int i = 0; i < 4; i++) acc_o[nt][i] *= corr[i >> 1];

            uint32_t ph[4][4];
            #pragma unroll
            for (int kt = 0; kt < 4; kt++) {
                ph[kt][0] = packh2(acc_s[2 * kt][0],     acc_s[2 * kt][1]);
                ph[kt][1] = packh2(acc_s[2 * kt][2],     acc_s[2 * kt][3]);
                ph[kt][2] = packh2(acc_s[2 * kt + 1][0], acc_s[2 * kt + 1][1]);
                ph[kt][3] = packh2(acc_s[2 * kt + 1][2], acc_s[2 * kt + 1][3]);
            }

            #pragma unroll
            for (int kt = 0; kt < 4; kt++) {
                const uint32_t vrow = kt * 16 + (lane & 15);
                const uint32_t vcol = (lane >> 4) * 8;
                #pragma unroll
                for (int g = 0; g < 4; g++) {
                    uint32_t vh[4];
                    const uint32_t off = vrow * AROWB + (g * 16 + vcol) * 2;
                    ldsm_x4t(vh, vbase + off);
                    mma16816h(acc_o[2 * g],     ph[kt], &vh[0]);
                    mma16816h(acc_o[2 * g + 1], ph[kt], &vh[2]);
                }
            }
        }
    }

    float inv[2];
    #pragma unroll
    for (int h = 0; h < 2; h++) {
        float l = l_s[h];
        l += __shfl_xor_sync(0xffffffffu, l, 1);
        l += __shfl_xor_sync(0xffffffffu, l, 2);
        inv[h] = 1.0f / l;
    }
    const int b  = bh >> 4;
    const int hh = bh & 15;
    const int r0 = q0 + wid * 16 + (lane >> 2);
    #pragma unroll
    for (int nt = 0; nt < 8; nt++) {
        const int col = hh * 64 + nt * 8 + 2 * (lane & 3);
        {
            const long idx = ((long)(b * S_LEN + r0)) * DMODEL + col;
            *(uint32_t*)(Oh + idx) = packh2(acc_o[nt][0] * inv[0],
                                            acc_o[nt][1] * inv[0]);
        }
        {
            const long idx = ((long)(b * S_LEN + r0 + 8)) * DMODEL + col;
            *(uint32_t*)(Oh + idx) = packh2(acc_o[nt][2] * inv[1],
                                            acc_o[nt][3] * inv[1]);
        }
    }
}

// ============================================================================
// conversion kernels (float4-vectorized)
// ============================================================================
__global__ void __launch_bounds__(256)
conv_qkv(const float* __restrict__ q, const float* __restrict__ k,
         const float* __restrict__ v)
{
    const int z = blockIdx.y;
    const float* X = (z == 0) ? q : (z == 1) ? k : v;
    const int i = blockIdx.x * 256 + threadIdx.x;   // over float4
    const float4 x = ((const float4*)X)[i];
    if (z == 2) {
        uint2 o;
        o.x = packh2(x.x, x.y);
        o.y = packh2(x.z, x.w);
        ((uint2*)g_Avh)[i] = o;
    } else {
        uint32_t h0, l0, h1, l1;
        split2(x.x, x.y, h0, l0);
        split2(x.z, x.w, h1, l1);
        uint2 hv; hv.x = h0; hv.y = h1;
        uint2 lv; lv.x = l0; lv.y = l1;
        ((uint2*)g_Ahi[z])[i] = hv;
        ((uint2*)g_Alo[z])[i] = lv;
    }
}

__global__ void __launch_bounds__(256)
conv_w(const float* __restrict__ W0, const float* __restrict__ W1,
       const float* __restrict__ W2, const float* __restrict__ W3)
{
    __shared__ float t[32][33];
    const int z = blockIdx.z;
    const float* W = (z == 0) ? W0 : (z == 1) ? W1 : (z == 2) ? W2 : W3;
    const int tx = threadIdx.x, ty = threadIdx.y;
    const int n0 = blockIdx.x * 32, k0 = blockIdx.y * 32;
    #pragma unroll
    for (int r = 0; r < 4; r++) {
        const int k = ty + r * 8;
        t[k][tx] = W[(long)(k0 + k) * DMODEL + n0 + tx];
    }
    __syncthreads();
    #pragma unroll
    for (int r = 0; r < 4; r++) {
        const int nl = ty + r * 8;
        const float x = t[tx][nl];
        const long o = (long)(n0 + nl) * DMODEL + k0 + tx;
        if (z < 2) {
            const __nv_bfloat16 h = __float2bfloat16(x);
            g_Whi[z][o] = h;
            g_Wlo[z][o] = __float2bfloat16(x - __bfloat162float(h));
        } else {
            const __half h = __float2half_rn(x);
            const __half l = __float2half_rn(x - __half2float(h));
            if (z == 2) { g_Wvh[o] = h; g_Wvl[o] = l; }
            else        { g_W4h[o] = h; g_W4l[o] = l; }
        }
    }
}

// ============================================================================
extern "C" void kernel_launch(void* const* d_in, const int* in_sizes, int n_in,
                              void* d_out, int out_size)
{
    const float* q = (const float*)d_in[0];
    const float* k = (const float*)d_in[1];
    const float* v = (const float*)d_in[2];
    float* out = (float*)d_out;

    __nv_bfloat16 *qhi, *qlo, *khi, *klo;
    __half *vh, *oh, *w4h, *w4l;
    cudaGetSymbolAddress((void**)&qhi, g_Qhi);
    cudaGetSymbolAddress((void**)&qlo, g_Qlo);
    cudaGetSymbolAddress((void**)&khi, g_Khi);
    cudaGetSymbolAddress((void**)&klo, g_Klo);
    cudaGetSymbolAddress((void**)&vh,  g_Vh);
    cudaGetSymbolAddress((void**)&oh,  g_Oh);
    cudaGetSymbolAddress((void**)&w4h, g_W4h);
    cudaGetSymbolAddress((void**)&w4l, g_W4l);

    cudaFuncSetAttribute((const void*)gemm_proj,
                         cudaFuncAttributeMaxDynamicSharedMemorySize, GSMEM);
    cudaFuncSetAttribute((const void*)gemm_out,
                         cudaFuncAttributeMaxDynamicSharedMemorySize, OSMEM);
    cudaFuncSetAttribute((const void*)attn_mma,
                         cudaFuncAttributeMaxDynamicSharedMemorySize, ASMEM);

    conv_w<<<dim3(32, 32, 4), dim3(32, 8)>>>(
        (const float*)d_in[3], (const float*)d_in[4],
        (const float*)d_in[5], (const float*)d_in[6]);

    conv_qkv<<<dim3(AELEMS / 4 / 256, 3), 256>>>(q, k, v);

    gemm_proj<<<dim3(8, 128, 3), 128, GSMEM>>>(qhi, qlo, khi, klo, vh);

    attn_mma<<<dim3(S_LEN / 64, BHCNT), 128, ASMEM>>>(qhi, qlo, khi, klo,
                                                      vh, oh);

    gemm_out<<<dim3(8, 128), 128, OSMEM>>>(oh, w4h, w4l, out);
}

// round 16
// speedup vs baseline: 1.3915x; 1.0250x over previous
#include <cuda_runtime.h>
#include <cuda_bf16.h>
#include <cuda_fp16.h>
#include <cstdint>

#define S_LEN   2048
#define DMODEL  1024
#define NHEADS  16
#define HDIM    64
#define BATCH   4
#define BHCNT   (BATCH * NHEADS)                   // 64
#define MROWS   (BATCH * S_LEN)                    // 8192
#define HS_ELEMS (BATCH * NHEADS * S_LEN * HDIM)   // 8388608
#define AELEMS  (MROWS * DMODEL)                   // 8388608
#define WELEMS  (DMODEL * DMODEL)                  // 1048576

// ---- scratch ----
__device__ __nv_bfloat16 g_Ahi[2][AELEMS];   // q,k inputs bf16 hi/lo
__device__ __nv_bfloat16 g_Alo[2][AELEMS];
__device__ __half        g_Avh[AELEMS];      // v input, fp16 single
__device__ __nv_bfloat16 g_Whi[2][WELEMS];   // Wq,Wk transposed [N][K], bf16
__device__ __nv_bfloat16 g_Wlo[2][WELEMS];
__device__ __half        g_Wvh[WELEMS];      // Wv transposed, fp16 hi/lo
__device__ __half        g_Wvl[WELEMS];
__device__ __half        g_W4h[WELEMS];      // Wo transposed, fp16 hi/lo
__device__ __half        g_W4l[WELEMS];
__device__ __nv_bfloat16 g_Qhi[HS_ELEMS], g_Qlo[HS_ELEMS];   // bf16, scaled log2e/8
__device__ __nv_bfloat16 g_Khi[HS_ELEMS], g_Klo[HS_ELEMS];   // bf16
__device__ __half        g_Vh[HS_ELEMS];                     // fp16 single
__device__ __half        g_Oh[AELEMS];                       // fp16, row-major

// ============================================================================
// helpers (baseline PTX only)
// ============================================================================
__device__ __forceinline__ uint32_t smem_u32(const void* p) {
    uint32_t a;
    asm("{ .reg .u64 t; cvta.to.shared.u64 t, %1; cvt.u32.u64 %0, t; }"
        : "=r"(a) : "l"(p));
    return a;
}
__device__ __forceinline__ void cp_async16(uint32_t dst, const void* src) {
    asm volatile("cp.async.cg.shared.global [%0], [%1], 16;"
                 :: "r"(dst), "l"(src));
}
__device__ __forceinline__ void cp_commit() {
    asm volatile("cp.async.commit_group;");
}
template <int N>
__device__ __forceinline__ void cp_wait() {
    asm volatile("cp.async.wait_group %0;" :: "n"(N));
}
__device__ __forceinline__ void ldsm_x4(uint32_t* r, uint32_t addr) {
    asm volatile("ldmatrix.sync.aligned.m8n8.x4.shared.b16 {%0,%1,%2,%3}, [%4];"
                 : "=r"(r[0]), "=r"(r[1]), "=r"(r[2]), "=r"(r[3]) : "r"(addr));
}
__device__ __forceinline__ void ldsm_x4t(uint32_t* r, uint32_t addr) {
    asm volatile("ldmatrix.sync.aligned.m8n8.x4.trans.shared.b16 {%0,%1,%2,%3}, [%4];"
                 : "=r"(r[0]), "=r"(r[1]), "=r"(r[2]), "=r"(r[3]) : "r"(addr));
}
__device__ __forceinline__ void mma16816(float* d, const uint32_t* a,
                                         const uint32_t* b) {
    asm volatile("mma.sync.aligned.m16n8k16.row.col.f32.bf16.bf16.f32 "
                 "{%0,%1,%2,%3}, {%4,%5,%6,%7}, {%8,%9}, {%0,%1,%2,%3};"
                 : "+f"(d[0]), "+f"(d[1]), "+f"(d[2]), "+f"(d[3])
                 : "r"(a[0]), "r"(a[1]), "r"(a[2]), "r"(a[3]),
                   "r"(b[0]), "r"(b[1]));
}
__device__ __forceinline__ void mma16816h(float* d, const uint32_t* a,
                                          const uint32_t* b) {
    asm volatile("mma.sync.aligned.m16n8k16.row.col.f32.f16.f16.f32 "
                 "{%0,%1,%2,%3}, {%4,%5,%6,%7}, {%8,%9}, {%0,%1,%2,%3};"
                 : "+f"(d[0]), "+f"(d[1]), "+f"(d[2]), "+f"(d[3])
                 : "r"(a[0]), "r"(a[1]), "r"(a[2]), "r"(a[3]),
                   "r"(b[0]), "r"(b[1]));
}
__device__ __forceinline__ void split2(float a, float b,
                                       uint32_t& hi, uint32_t& lo) {
    uint32_t h;
    asm("cvt.rn.bf16x2.f32 %0, %1, %2;" : "=r"(h) : "f"(b), "f"(a));
    const float fa = __uint_as_float(h << 16);
    const float fb = __uint_as_float(h & 0xFFFF0000u);
    uint32_t l;
    asm("cvt.rn.bf16x2.f32 %0, %1, %2;" : "=r"(l) : "f"(b - fb), "f"(a - fa));
    hi = h; lo = l;
}
__device__ __forceinline__ uint32_t packh2(float a, float b) {
    uint32_t h;
    asm("cvt.rn.f16x2.f32 %0, %1, %2;" : "=r"(h) : "f"(b), "f"(a));
    return h;
}
// p = 2^(a-m), 2^(b-m) packed fp16x2 (subtract fp32, packed fp16 ex2)
__device__ __forceinline__ uint32_t ex2h2(float a, float b, float m) {
    uint32_t r;
    asm("cvt.rn.f16x2.f32 %0, %1, %2;" : "=r"(r) : "f"(b - m), "f"(a - m));
    asm("ex2.approx.f16x2 %0, %0;" : "+r"(r));
    return r;
}
__device__ __forceinline__ float ex2f(float x) {
    float y;
    asm("ex2.approx.f32 %0, %1;" : "=f"(y) : "f"(x));
    return y;
}

#define GA_BYTES   (64 * 64)                 // 4096
#define GB_BYTES   (128 * 64)                // 8192
#define STG_BYTES  (2 * GA_BYTES + 2 * GB_BYTES)  // 24576
#define GSMEM      (2 * STG_BYTES)           // 49152
#define OSTG       (GA_BYTES + 2 * GB_BYTES) // 20480
#define OSMEM      (2 * OSTG)                // 40960

__device__ __forceinline__ uint32_t swz64(uint32_t row, uint32_t seg) {
    return row * 64 + ((seg ^ (row & 3)) * 16);
}

// ============================================================================
// bf16 3-term GEMM core: tile 64x128, BK=32, 4 warps as 1M x 4N.
// ============================================================================
__device__ __forceinline__ void gemm_core(
    const __nv_bfloat16* __restrict__ Ahi, const __nv_bfloat16* __restrict__ Alo,
    const __nv_bfloat16* __restrict__ Bhi, const __nv_bfloat16* __restrict__ Blo,
    uint32_t sb, int tid, int bc, int br, float acc[4][4][4])
{
    const int lane   = tid & 31;
    const int warp_n = tid >> 5;

    auto issue = [&](int kc, int stage) {
        #pragma unroll
        for (int t = 0; t < 12; t++) {
            const int c = tid + t * 128;
            uint32_t dst;
            const __nv_bfloat16* g;
            if (c < 512) {
                const int arr = c >> 8, rem = c & 255;
                const int row = rem >> 2, seg = rem & 3;
                g = (arr ? Alo : Ahi) + (long)(br * 64 + row) * DMODEL
                  + kc * 32 + seg * 8;
                dst = sb + stage * STG_BYTES + arr * GA_BYTES + swz64(row, seg);
            } else {
                const int cb = c - 512;
                const int arr = cb >> 9, rem = cb & 511;
                const int row = rem >> 2, seg = rem & 3;
                g = (arr ? Blo : Bhi) + (long)(bc * 128 + row) * DMODEL
                  + kc * 32 + seg * 8;
                dst = sb + stage * STG_BYTES + 2 * GA_BYTES + arr * GB_BYTES
                    + swz64(row, seg);
            }
            cp_async16(dst, g);
        }
        cp_commit();
    };

    issue(0, 0);

    const int NKC = DMODEL / 32;
    for (int kc = 0; kc < NKC; kc++) {
        cp_wait<0>();
        __syncthreads();
        if (kc + 1 < NKC) issue(kc + 1, (kc + 1) & 1);

        const uint32_t base = sb + (kc & 1) * STG_BYTES;

        #pragma unroll
        for (int kk = 0; kk < 2; kk++) {
            uint32_t ahi[4][4], alo[4][4];
            {
                const uint32_t ar0  = lane & 15;
                const uint32_t aseg = kk * 2 + (lane >> 4);
                #pragma unroll
                for (int mt = 0; mt < 4; mt++) {
                    ldsm_x4(ahi[mt], base + swz64(mt * 16 + ar0, aseg));
                    ldsm_x4(alo[mt], base + GA_BYTES + swz64(mt * 16 + ar0, aseg));
                }
            }
            const uint32_t br0  = warp_n * 32 + (lane & 7) + ((lane & 16) >> 1);
            const uint32_t bseg = kk * 2 + ((lane >> 3) & 1);
            #pragma unroll
            for (int q = 0; q < 2; q++) {
                uint32_t bhi[4], blo[4];
                const uint32_t brow = br0 + q * 16;
                ldsm_x4(bhi, base + 2 * GA_BYTES + swz64(brow, bseg));
                ldsm_x4(blo, base + 2 * GA_BYTES + GB_BYTES + swz64(brow, bseg));
                #pragma unroll
                for (int mt = 0; mt < 4; mt++)
                    #pragma unroll
                    for (int n2 = 0; n2 < 2; n2++)
                        mma16816(acc[mt][2 * q + n2], ahi[mt], &bhi[n2 * 2]);
                #pragma unroll
                for (int mt = 0; mt < 4; mt++)
                    #pragma unroll
                    for (int n2 = 0; n2 < 2; n2++)
                        mma16816(acc[mt][2 * q + n2], ahi[mt], &blo[n2 * 2]);
                #pragma unroll
                for (int mt = 0; mt < 4; mt++)
                    #pragma unroll
                    for (int n2 = 0; n2 < 2; n2++)
                        mma16816(acc[mt][2 * q + n2], alo[mt], &bhi[n2 * 2]);
            }
        }
    }
}

// ============================================================================
// fp16 2-term GEMM core (A single fp16, W hi/lo): 1M x 4N layout.
// ============================================================================
__device__ __forceinline__ void h16_core(
    const __half* __restrict__ Ah,
    const __half* __restrict__ Whi, const __half* __restrict__ Wlo,
    uint32_t sb, int tid, int bc, int br, float acc[4][4][4])
{
    const int lane   = tid & 31;
    const int warp_n = tid >> 5;

    auto issue = [&](int kc, int stage) {
        #pragma unroll
        for (int t = 0; t < 10; t++) {
            const int c = tid + t * 128;
            uint32_t dst;
            const __half* g;
            if (c < 256) {
                const int row = c >> 2, seg = c & 3;
                g = Ah + (long)(br * 64 + row) * DMODEL + kc * 32 + seg * 8;
                dst = sb + stage * OSTG + swz64(row, seg);
            } else {
                const int cb = c - 256;
                const int arr = cb >> 9, rem = cb & 511;
                const int row = rem >> 2, seg = rem & 3;
                g = (arr ? Wlo : Whi) + (long)(bc * 128 + row) * DMODEL
                  + kc * 32 + seg * 8;
                dst = sb + stage * OSTG + GA_BYTES + arr * GB_BYTES
                    + swz64(row, seg);
            }
            cp_async16(dst, g);
        }
        cp_commit();
    };

    issue(0, 0);

    const int NKC = DMODEL / 32;
    for (int kc = 0; kc < NKC; kc++) {
        cp_wait<0>();
        __syncthreads();
        if (kc + 1 < NKC) issue(kc + 1, (kc + 1) & 1);

        const uint32_t base = sb + (kc & 1) * OSTG;

        #pragma unroll
        for (int kk = 0; kk < 2; kk++) {
            uint32_t ah[4][4];
            {
                const uint32_t ar0  = lane & 15;
                const uint32_t aseg = kk * 2 + (lane >> 4);
                #pragma unroll
                for (int mt = 0; mt < 4; mt++)
                    ldsm_x4(ah[mt], base + swz64(mt * 16 + ar0, aseg));
            }
            const uint32_t br0  = warp_n * 32 + (lane & 7) + ((lane & 16) >> 1);
            const uint32_t bseg = kk * 2 + ((lane >> 3) & 1);
            #pragma unroll
            for (int q = 0; q < 2; q++) {
                uint32_t bhi[4], blo[4];
                const uint32_t brow = br0 + q * 16;
                ldsm_x4(bhi, base + GA_BYTES + swz64(brow, bseg));
                ldsm_x4(blo, base + GA_BYTES + GB_BYTES + swz64(brow, bseg));
                #pragma unroll
                for (int mt = 0; mt < 4; mt++)
                    #pragma unroll
                    for (int n2 = 0; n2 < 2; n2++)
                        mma16816h(acc[mt][2 * q + n2], ah[mt], &bhi[n2 * 2]);
                #pragma unroll
                for (int mt = 0; mt < 4; mt++)
                    #pragma unroll
                    for (int n2 = 0; n2 < 2; n2++)
                        mma16816h(acc[mt][2 * q + n2], ah[mt], &blo[n2 * 2]);
            }
        }
    }
}

// ============================================================================
// Fused QKV projection GEMM: grid (8, 128, 3), 128 threads, 4 CTAs/SM.
// Q pre-scaled by log2(e)/8 (exp2-domain softmax downstream).
// ============================================================================
__global__ void __launch_bounds__(128, 4)
gemm_proj(__nv_bfloat16* __restrict__ Qhi, __nv_bfloat16* __restrict__ Qlo,
          __nv_bfloat16* __restrict__ Khi, __nv_bfloat16* __restrict__ Klo,
          __half* __restrict__ Vh)
{
    extern __shared__ char smem[];
    const uint32_t sb = smem_u32(smem);
    const int tid = threadIdx.x;
    const int bc = blockIdx.x, br = blockIdx.y, z = blockIdx.z;
    const int lane = tid & 31, warp_n = tid >> 5;

    float acc[4][4][4];
    #pragma unroll
    for (int mt = 0; mt < 4; mt++)
        #pragma unroll
        for (int nt = 0; nt < 4; nt++)
            #pragma unroll
            for (int i = 0; i < 4; i++) acc[mt][nt][i] = 0.0f;

    if (z == 2) {
        h16_core(g_Avh, g_Wvh, g_Wvl, sb, tid, bc, br, acc);
        uint32_t* C = (uint32_t*)Vh;
        #pragma unroll
        for (int mt = 0; mt < 4; mt++) {
            #pragma unroll
            for (int nt = 0; nt < 4; nt++) {
                const int row0 = br * 64 + mt * 16 + (lane >> 2);
                const int col  = bc * 128 + warp_n * 32 + nt * 8 + (lane & 3) * 2;
                const int h = col >> 6, dd = col & 63;
                #pragma unroll
                for (int half = 0; half < 2; half++) {
                    const int r = row0 + half * 8;
                    const int b = r >> 11, s = r & 2047;
                    const long off = (((((long)b * NHEADS + h) * S_LEN + s) * HDIM) + dd) >> 1;
                    C[off] = packh2(acc[mt][nt][half * 2], acc[mt][nt][half * 2 + 1]);
                }
            }
        }
    } else {
        uint32_t* Chi = (uint32_t*)(z == 0 ? Qhi : Khi);
        uint32_t* Clo = (uint32_t*)(z == 0 ? Qlo : Klo);
        const float scale = (z == 0) ? 0.125f * 1.44269504f : 1.0f;
        gemm_core(g_Ahi[z], g_Alo[z], g_Whi[z], g_Wlo[z], sb, tid, bc, br, acc);
        #pragma unroll
        for (int mt = 0; mt < 4; mt++) {
            #pragma unroll
            for (int nt = 0; nt < 4; nt++) {
                const int row0 = br * 64 + mt * 16 + (lane >> 2);
                const int col  = bc * 128 + warp_n * 32 + nt * 8 + (lane & 3) * 2;
                const int h = col >> 6, dd = col & 63;
                #pragma unroll
                for (int half = 0; half < 2; half++) {
                    const int r = row0 + half * 8;
                    const int b = r >> 11, s = r & 2047;
                    const long off = (((((long)b * NHEADS + h) * S_LEN + s) * HDIM) + dd) >> 1;
                    uint32_t hi, lo;
                    split2(acc[mt][nt][half * 2] * scale,
                           acc[mt][nt][half * 2 + 1] * scale, hi, lo);
                    Chi[off] = hi;
                    Clo[off] = lo;
                }
            }
        }
    }
}

// ============================================================================
// Output projection GEMM: fp16 2-term, fp32 row-major out. grid (8, 128).
// ============================================================================
__global__ void __launch_bounds__(128, 4)
gemm_out(const __half* __restrict__ Ah,
         const __half* __restrict__ Whi, const __half* __restrict__ Wlo,
         float* __restrict__ Cf)
{
    extern __shared__ char smem[];
    const uint32_t sb = smem_u32(smem);
    const int tid = threadIdx.x;
    const int bc = blockIdx.x, br = blockIdx.y;
    const int lane = tid & 31, warp_n = tid >> 5;

    float acc[4][4][4];
    #pragma unroll
    for (int mt = 0; mt < 4; mt++)
        #pragma unroll
        for (int nt = 0; nt < 4; nt++)
            #pragma unroll
            for (int i = 0; i < 4; i++) acc[mt][nt][i] = 0.0f;

    h16_core(Ah, Whi, Wlo, sb, tid, bc, br, acc);

    #pragma unroll
    for (int mt = 0; mt < 4; mt++) {
        #pragma unroll
        for (int nt = 0; nt < 4; nt++) {
            const int row0 = br * 64 + mt * 16 + (lane >> 2);
            const int col  = bc * 128 + warp_n * 32 + nt * 8 + (lane & 3) * 2;
            float2 v01; v01.x = acc[mt][nt][0]; v01.y = acc[mt][nt][1];
            float2 v23; v23.x = acc[mt][nt][2]; v23.y = acc[mt][nt][3];
            *(float2*)&Cf[(long)row0 * DMODEL + col] = v01;
            *(float2*)&Cf[(long)(row0 + 8) * DMODEL + col] = v23;
        }
    }
}

// ============================================================================
// Tensor-core causal flash attention, exp2-domain softmax.
// QK: bf16 3-term (scores in log2 domain). P via ex2.approx.f16x2.
// l accumulated by ones-MMA (rides corr rescale with acc_o).
// ============================================================================
#define AROWB    144
#define ARR      (64 * AROWB)            // 9216
#define KVSTG    (3 * ARR)               // 27648: Khi, Klo, V
#define ASMEM    (2 * KVSTG)             // 55296

__global__ void __launch_bounds__(128, 4)
attn_mma(const __nv_bfloat16* __restrict__ Qhi, const __nv_bfloat16* __restrict__ Qlo,
         const __nv_bfloat16* __restrict__ Khi, const __nv_bfloat16* __restrict__ Klo,
         const __half* __restrict__ Vh,
         __half* __restrict__ Oh)
{
    extern __shared__ char smem[];
    const uint32_t sb = smem_u32(smem);
    const int tid = threadIdx.x, wid = tid >> 5, lane = tid & 31;
    const int qblk = (int)gridDim.x - 1 - (int)blockIdx.x;   // longest first
    const int q0 = qblk * 64;
    const int bh = blockIdx.y;
    const long base = (long)bh * S_LEN * HDIM;
    const int ntiles = qblk + 1;

    auto ldq = [&](uint32_t smem_base) {
        #pragma unroll
        for (int t = 0; t < 8; t++) {
            const int c = tid + t * 128;
            const int arr = c >> 9, rem = c & 511;
            const int row = rem >> 3, seg = rem & 7;
            const char* src = (const char*)(arr ? Qlo : Qhi)
                            + ((base + ((long)q0 + row) * HDIM + seg * 8) << 1);
            cp_async16(smem_base + arr * ARR + row * AROWB + seg * 16, src);
        }
        cp_commit();
    };
    auto ldkv = [&](int t, int stage) {
        const long grow0 = (long)t * 64;
        #pragma unroll
        for (int i = 0; i < 12; i++) {
            const int c = tid + i * 128;
            const int arr = c >> 9, rem = c & 511;
            const int row = rem >> 3, seg = rem & 7;
            const char* p;
            if (arr == 0)      p = (const char*)Khi;
            else if (arr == 1) p = (const char*)Klo;
            else               p = (const char*)Vh;
            cp_async16(sb + stage * KVSTG + arr * ARR + row * AROWB + seg * 16,
                       p + ((base + (grow0 + row) * HDIM + seg * 8) << 1));
        }
        cp_commit();
    };

    ldq(sb + KVSTG);
    ldkv(0, 0);
    cp_wait<1>();
    __syncthreads();

    uint32_t qhF[4][4], qlF[4][4];
    {
        const uint32_t arow = wid * 16 + (lane & 15);
        #pragma unroll
        for (int kt = 0; kt < 4; kt++) {
            const uint32_t off = arow * AROWB + (kt * 16 + (lane >> 4) * 8) * 2;
            ldsm_x4(qhF[kt], sb + KVSTG + off);
            ldsm_x4(qlF[kt], sb + KVSTG + ARR + off);
        }
    }

    float m_s[2] = {-1e30f, -1e30f};
    float acc_l[4];                   // ones-MMA row-sum accumulator
    #pragma unroll
    for (int i = 0; i < 4; i++) acc_l[i] = 0.0f;
    float acc_o[8][4];
    #pragma unroll
    for (int nt = 0; nt < 8; nt++)
        #pragma unroll
        for (int i = 0; i < 4; i++) acc_o[nt][i] = 0.0f;

    const uint32_t onesF[2] = {0x3C003C00u, 0x3C003C00u};   // fp16 1.0 x2
    const int wrow_lo = q0 + wid * 16;

    for (int t = 0; t < ntiles; t++) {
        cp_wait<0>();
        __syncthreads();
        if (t + 1 < ntiles) ldkv(t + 1, (t + 1) & 1);

        const uint32_t kbase = sb + (t & 1) * KVSTG;
        const uint32_t vbase = kbase + 2 * ARR;
        const bool act = (t * 64 <= wrow_lo + 15);

        if (act) {
            float acc_s[8][4];
            #pragma unroll
            for (int nt = 0; nt < 8; nt++)
                #pragma unroll
                for (int i = 0; i < 4; i++) acc_s[nt][i] = 0.0f;

            #pragma unroll
            for (int kt = 0; kt < 4; kt++) {
                const uint32_t brow = (lane & 7) + ((lane & 16) >> 1);
                const uint32_t bcol = kt * 16 + ((lane >> 3) & 1) * 8;
                #pragma unroll
                for (int g = 0; g < 4; g++) {
                    uint32_t kh[4], kl[4];
                    const uint32_t off = (g * 16 + brow) * AROWB + bcol * 2;
                    ldsm_x4(kh, kbase + off);
                    ldsm_x4(kl, kbase + ARR + off);
                    mma16816(acc_s[2 * g],     qhF[kt], &kh[0]);
                    mma16816(acc_s[2 * g + 1], qhF[kt], &kh[2]);
                    mma16816(acc_s[2 * g],     qhF[kt], &kl[0]);
                    mma16816(acc_s[2 * g + 1], qhF[kt], &kl[2]);
                    mma16816(acc_s[2 * g],     qlF[kt], &kh[0]);
                    mma16816(acc_s[2 * g + 1], qlF[kt], &kh[2]);
                }
            }

            const int r0 = q0 + wid * 16 + (lane >> 2);
            if (t * 64 + 63 > wrow_lo) {
                #pragma unroll
                for (int nt = 0; nt < 8; nt++)
                    #pragma unroll
                    for (int i = 0; i < 4; i++) {
                        const int row = r0 + (i >> 1) * 8;
                        const int col = t * 64 + nt * 8 + 2 * (lane & 3) + (i & 1);
                        if (col > row) acc_s[nt][i] = -1e30f;
                    }
            }

            // ---- row max ----
            float tmax[2] = {-1e30f, -1e30f};
            #pragma unroll
            for (int nt = 0; nt < 8; nt++)
                #pragma unroll
                for (int i = 0; i < 4; i++)
                    tmax[i >> 1] = fmaxf(tmax[i >> 1], acc_s[nt][i]);
            #pragma unroll
            for (int h = 0; h < 2; h++) {
                tmax[h] = fmaxf(tmax[h], __shfl_xor_sync(0xffffffffu, tmax[h], 1));
                tmax[h] = fmaxf(tmax[h], __shfl_xor_sync(0xffffffffu, tmax[h], 2));
            }

            float nm[2], corr[2];
            #pragma unroll
            for (int h = 0; h < 2; h++) {
                nm[h]   = fmaxf(m_s[h], tmax[h]);
                corr[h] = ex2f(m_s[h] - nm[h]);
                m_s[h]  = nm[h];
            }
            #pragma unroll
            for (int nt = 0; nt < 8; nt++)
                #pragma unroll
                for (int i = 0; i < 4; i++) acc_o[nt][i] *= corr[i >> 1];
            #pragma unroll
            for (int i = 0; i < 4; i++) acc_l[i] *= corr[i >> 1];

            // ---- P fragments directly via packed fp16 ex2 ----
            uint32_t ph[4][4];
            #pragma unroll
            for (int kt = 0; kt < 4; kt++) {
                ph[kt][0] = ex2h2(acc_s[2 * kt][0],     acc_s[2 * kt][1],     nm[0]);
                ph[kt][1] = ex2h2(acc_s[2 * kt][2],     acc_s[2 * kt][3],     nm[1]);
                ph[kt][2] = ex2h2(acc_s[2 * kt + 1][0], acc_s[2 * kt + 1][1], nm[0]);
                ph[kt][3] = ex2h2(acc_s[2 * kt + 1][2], acc_s[2 * kt + 1][3], nm[1]);
            }

            // ---- O += P @ V ; l += P @ ones ----
            #pragma unroll
            for (int kt = 0; kt < 4; kt++) {
                const uint32_t vrow = kt * 16 + (lane & 15);
                const uint32_t vcol = (lane >> 4) * 8;
                #pragma unroll
                for (int g = 0; g < 4; g++) {
                    uint32_t vh[4];
                    const uint32_t off = vrow * AROWB + (g * 16 + vcol) * 2;
                    ldsm_x4t(vh, vbase + off);
                    mma16816h(acc_o[2 * g],     ph[kt], &vh[0]);
                    mma16816h(acc_o[2 * g + 1], ph[kt], &vh[2]);
                }
                mma16816h(acc_l, ph[kt], onesF);
            }
        }
    }

    // ---- epilogue: l already reduced by ones-MMA; no shfl needed ----
    const float inv0 = 1.0f / acc_l[0];
    const float inv1 = 1.0f / acc_l[2];
    const int b  = bh >> 4;
    const int hh = bh & 15;
    const int r0 = q0 + wid * 16 + (lane >> 2);
    #pragma unroll
    for (int nt = 0; nt < 8; nt++) {
        const int col = hh * 64 + nt * 8 + 2 * (lane & 3);
        {
            const long idx = ((long)(b * S_LEN + r0)) * DMODEL + col;
            *(uint32_t*)(Oh + idx) = packh2(acc_o[nt][0] * inv0,
                                            acc_o[nt][1] * inv0);
        }
        {
            const long idx = ((long)(b * S_LEN + r0 + 8)) * DMODEL + col;
            *(uint32_t*)(Oh + idx) = packh2(acc_o[nt][2] * inv1,
                                            acc_o[nt][3] * inv1);
        }
    }
}

// ============================================================================
// conversion kernels (float4-vectorized)
// ============================================================================
__global__ void __launch_bounds__(256)
conv_qkv(const float* __restrict__ q, const float* __restrict__ k,
         const float* __restrict__ v)
{
    const int z = blockIdx.y;
    const float* X = (z == 0) ? q : (z == 1) ? k : v;
    const int i = blockIdx.x * 256 + threadIdx.x;   // over float4
    const float4 x = ((const float4*)X)[i];
    if (z == 2) {
        uint2 o;
        o.x = packh2(x.x, x.y);
        o.y = packh2(x.z, x.w);
        ((uint2*)g_Avh)[i] = o;
    } else {
        uint32_t h0, l0, h1, l1;
        split2(x.x, x.y, h0, l0);
        split2(x.z, x.w, h1, l1);
        uint2 hv; hv.x = h0; hv.y = h1;
        uint2 lv; lv.x = l0; lv.y = l1;
        ((uint2*)g_Ahi[z])[i] = hv;
        ((uint2*)g_Alo[z])[i] = lv;
    }
}

__global__ void __launch_bounds__(256)
conv_w(const float* __restrict__ W0, const float* __restrict__ W1,
       const float* __restrict__ W2, const float* __restrict__ W3)
{
    __shared__ float t[32][33];
    const int z = blockIdx.z;
    const float* W = (z == 0) ? W0 : (z == 1) ? W1 : (z == 2) ? W2 : W3;
    const int tx = threadIdx.x, ty = threadIdx.y;
    const int n0 = blockIdx.x * 32, k0 = blockIdx.y * 32;
    #pragma unroll
    for (int r = 0; r < 4; r++) {
        const int k = ty + r * 8;
        t[k][tx] = W[(long)(k0 + k) * DMODEL + n0 + tx];
    }
    __syncthreads();
    #pragma unroll
    for (int r = 0; r < 4; r++) {
        const int nl = ty + r * 8;
        const float x = t[tx][nl];
        const long o = (long)(n0 + nl) * DMODEL + k0 + tx;
        if (z < 2) {
            const __nv_bfloat16 h = __float2bfloat16(x);
            g_Whi[z][o] = h;
            g_Wlo[z][o] = __float2bfloat16(x - __bfloat162float(h));
        } else {
            const __half h = __float2half_rn(x);
            const __half l = __float2half_rn(x - __half2float(h));
            if (z == 2) { g_Wvh[o] = h; g_Wvl[o] = l; }
            else        { g_W4h[o] = h; g_W4l[o] = l; }
        }
    }
}

// ============================================================================
extern "C" void kernel_launch(void* const* d_in, const int* in_sizes, int n_in,
                              void* d_out, int out_size)
{
    const float* q = (const float*)d_in[0];
    const float* k = (const float*)d_in[1];
    const float* v = (const float*)d_in[2];
    float* out = (float*)d_out;

    __nv_bfloat16 *qhi, *qlo, *khi, *klo;
    __half *vh, *oh, *w4h, *w4l;
    cudaGetSymbolAddress((void**)&qhi, g_Qhi);
    cudaGetSymbolAddress((void**)&qlo, g_Qlo);
    cudaGetSymbolAddress((void**)&khi, g_Khi);
    cudaGetSymbolAddress((void**)&klo, g_Klo);
    cudaGetSymbolAddress((void**)&vh,  g_Vh);
    cudaGetSymbolAddress((void**)&oh,  g_Oh);
    cudaGetSymbolAddress((void**)&w4h, g_W4h);
    cudaGetSymbolAddress((void**)&w4l, g_W4l);

    cudaFuncSetAttribute((const void*)gemm_proj,
                         cudaFuncAttributeMaxDynamicSharedMemorySize, GSMEM);
    cudaFuncSetAttribute((const void*)gemm_out,
                         cudaFuncAttributeMaxDynamicSharedMemorySize, OSMEM);
    cudaFuncSetAttribute((const void*)attn_mma,
                         cudaFuncAttributeMaxDynamicSharedMemorySize, ASMEM);

    conv_w<<<dim3(32, 32, 4), dim3(32, 8)>>>(
        (const float*)d_in[3], (const float*)d_in[4],
        (const float*)d_in[5], (const float*)d_in[6]);

    conv_qkv<<<dim3(AELEMS / 4 / 256, 3), 256>>>(q, k, v);

    gemm_proj<<<dim3(8, 128, 3), 128, GSMEM>>>(qhi, qlo, khi, klo, vh);

    attn_mma<<<dim3(S_LEN / 64, BHCNT), 128, ASMEM>>>(qhi, qlo, khi, klo,
                                                      vh, oh);

    gemm_out<<<dim3(8, 128), 128, OSMEM>>>(oh, w4h, w4l, out);
}